// round 2
// baseline (speedup 1.0000x reference)
#include <cuda_runtime.h>
#include <cuda_bf16.h>
#include <math.h>

#define B_ 128
#define L_ 512
#define CIN 48
#define COUT_ 12
#define D_MODEL 256
#define N_LAYER 4
#define D_STATE 64
#define D_CONV 4
#define HEADDIM 64
#define CHUNK 64
#define D_INNER 512
#define NHEADS 8
#define CONV_DIM 640
#define D_IN_PROJ 1160
#define NTOK (B_ * L_)
#define EPS 1e-5f

// ---------------- scratch (static device globals; no runtime alloc) ----------------
__device__ float g_y[NTOK * D_MODEL];        // residual stream
__device__ float g_h[NTOK * D_MODEL];        // rmsnorm output
__device__ float g_zx[NTOK * D_IN_PROJ];     // in_proj output (z | xBC | dt)
__device__ float g_conv[NTOK * CONV_DIM];    // conv+silu output
__device__ float g_ssd[NTOK * D_INNER];      // ssd output (+D term)
__device__ float g_gate[NTOK * D_INNER];     // gated rmsnorm output

// ---------------- block reduction (256 threads) ----------------
__device__ __forceinline__ float block_sum256(float v, float* sh) {
    #pragma unroll
    for (int o = 16; o; o >>= 1) v += __shfl_xor_sync(0xffffffffu, v, o);
    if ((threadIdx.x & 31) == 0) sh[threadIdx.x >> 5] = v;
    __syncthreads();
    if (threadIdx.x < 8) {
        v = sh[threadIdx.x];
        #pragma unroll
        for (int o = 4; o; o >>= 1) v += __shfl_xor_sync(0xffu, v, o);
        if (threadIdx.x == 0) sh[0] = v;
    }
    __syncthreads();
    float r = sh[0];
    __syncthreads();
    return r;
}

__device__ __forceinline__ float silu_f(float x) { return x / (1.f + expf(-x)); }

// ---------------- SGEMM: C[M,N] = A[M,K] @ W[N,K]^T (+res) ----------------
// 128x64 tile, 8x4 per thread, 256 threads. M%128==0, K%16==0, N%4==0.
#define TBM 128
#define TBN 64
#define TBK 16
__global__ __launch_bounds__(256) void gemm_bt(
        const float* __restrict__ A, const float* __restrict__ W,
        const float* __restrict__ res, float* __restrict__ C,
        int M, int N, int K) {
    __shared__ float As[TBK][TBM + 4];
    __shared__ float Ws[TBK][TBN + 4];
    int tid = threadIdx.x;
    int tx = tid & 15, ty = tid >> 4;     // tx: n (4 cols), ty: m (8 rows)
    int m0 = blockIdx.y * TBM, n0 = blockIdx.x * TBN;
    // A-load mapping: 2048 floats/iter = 8/thread (2 float4)
    int alm = tid >> 1;                   // 0..127 row
    int alk = (tid & 1) * 8;              // 0 or 8
    // W-load mapping: 1024 floats/iter = 4/thread (1 float4)
    int wlm = tid >> 2;                   // 0..63 row
    int wlk = (tid & 3) * 4;              // 0,4,8,12

    float acc[8][4];
    #pragma unroll
    for (int i = 0; i < 8; i++)
        #pragma unroll
        for (int j = 0; j < 4; j++) acc[i][j] = 0.f;

    for (int k0 = 0; k0 < K; k0 += TBK) {
        const float* arow = A + (long)(m0 + alm) * K + k0 + alk;
        float4 a0 = *(const float4*)(arow);
        float4 a1 = *(const float4*)(arow + 4);
        As[alk + 0][alm] = a0.x; As[alk + 1][alm] = a0.y;
        As[alk + 2][alm] = a0.z; As[alk + 3][alm] = a0.w;
        As[alk + 4][alm] = a1.x; As[alk + 5][alm] = a1.y;
        As[alk + 6][alm] = a1.z; As[alk + 7][alm] = a1.w;
        int wn = n0 + wlm;
        float4 wv = make_float4(0.f, 0.f, 0.f, 0.f);
        if (wn < N) wv = *(const float4*)(W + (long)wn * K + k0 + wlk);
        Ws[wlk + 0][wlm] = wv.x; Ws[wlk + 1][wlm] = wv.y;
        Ws[wlk + 2][wlm] = wv.z; Ws[wlk + 3][wlm] = wv.w;
        __syncthreads();
        #pragma unroll
        for (int k = 0; k < TBK; k++) {
            float ra[8], rb[4];
            #pragma unroll
            for (int i = 0; i < 8; i++) ra[i] = As[k][ty * 8 + i];
            #pragma unroll
            for (int j = 0; j < 4; j++) rb[j] = Ws[k][tx * 4 + j];
            #pragma unroll
            for (int i = 0; i < 8; i++)
                #pragma unroll
                for (int j = 0; j < 4; j++) acc[i][j] += ra[i] * rb[j];
        }
        __syncthreads();
    }
    int n = n0 + tx * 4;
    if (n < N) {   // N%4==0 so a float4 is either fully in or fully out
        #pragma unroll
        for (int i = 0; i < 8; i++) {
            long off = (long)(m0 + ty * 8 + i) * N + n;
            float4 v = make_float4(acc[i][0], acc[i][1], acc[i][2], acc[i][3]);
            if (res) {
                float4 r = *(const float4*)(res + off);
                v.x += r.x; v.y += r.y; v.z += r.z; v.w += r.w;
            }
            *(float4*)(C + off) = v;
        }
    }
}

// ---------------- LayerNorm (in place, 256 dims, 1 token/block) ----------------
__global__ void ln_kernel(float* __restrict__ y, const float* __restrict__ w,
                          const float* __restrict__ b) {
    __shared__ float sh[8];
    long t = blockIdx.x;
    int d = threadIdx.x;
    float v = y[t * D_MODEL + d];
    float mean = block_sum256(v, sh) * (1.f / D_MODEL);
    float dv = v - mean;
    float var = block_sum256(dv * dv, sh) * (1.f / D_MODEL);
    y[t * D_MODEL + d] = dv * rsqrtf(var + EPS) * w[d] + b[d];
}

// ---------------- RMSNorm 256 -> g_h ----------------
__global__ void rms_kernel(const float* __restrict__ y, const float* __restrict__ w,
                           float* __restrict__ out) {
    __shared__ float sh[8];
    long t = blockIdx.x;
    int d = threadIdx.x;
    float v = y[t * D_MODEL + d];
    float ms = block_sum256(v * v, sh) * (1.f / D_MODEL);
    out[t * D_MODEL + d] = v * rsqrtf(ms + EPS) * w[d];
}

// ---------------- depthwise causal conv (width 4) + bias + silu ----------------
__global__ void conv_kernel(const float* __restrict__ zx, const float* __restrict__ cw,
                            const float* __restrict__ cb, float* __restrict__ out) {
    long idx = (long)blockIdx.x * blockDim.x + threadIdx.x;
    if (idx >= (long)NTOK * CONV_DIM) return;
    int ch = (int)(idx % CONV_DIM);
    long t = idx / CONV_DIM;
    int l = (int)(t & (L_ - 1));
    long brow = t - l;  // b*L_
    float acc = cb[ch];
    #pragma unroll
    for (int k = 0; k < D_CONV; k++) {
        int ls = l + k - (D_CONV - 1);
        if (ls >= 0)
            acc += zx[(brow + ls) * D_IN_PROJ + D_INNER + ch] * cw[ch * D_CONV + k];
    }
    out[t * CONV_DIM + ch] = silu_f(acc);
}

// ---------------- SSD chunked scan: one block per (b,h), sequential over 8 chunks ----
#define SSD_ST 65
#define SSD_SMEM_FLOATS (5 * 64 * SSD_ST + 4 * 64)
__global__ void ssd_kernel(const float* __restrict__ conv, const float* __restrict__ zx,
                           const float* __restrict__ dtb, const float* __restrict__ Alog,
                           const float* __restrict__ Dp, float* __restrict__ out) {
    extern __shared__ float sm[];
    float* xs = sm;                    // [64][65]  x (unscaled)
    float* Bm = xs + 64 * SSD_ST;      // [64][65]
    float* Cm = Bm + 64 * SSD_ST;      // [64][65]
    float* Mm = Cm + 64 * SSD_ST;      // [64][65]  M(l,s)*dt(s)
    float* S  = Mm + 64 * SSD_ST;      // [64][65]  state S[n][p]
    float* acum = S + 64 * SSD_ST;     // 64
    float* dts  = acum + 64;
    float* dd   = dts + 64;            // dt(l)*exp(acum63-acum(l))
    float* eAl  = dd + 64;             // exp(acum(l))

    int tid = threadIdx.x;
    int b = blockIdx.x >> 3, h = blockIdx.x & 7;
    float Ah = -expf(Alog[h]);
    float dtbh = dtb[h];
    float Dh = Dp[h];
    int p = tid & 63, lg = tid >> 6;

    for (int i = tid; i < 64 * SSD_ST; i += 256) S[i] = 0.f;
    __syncthreads();

    for (int c = 0; c < 8; ++c) {
        long tok0 = (long)b * L_ + c * CHUNK;
        // load chunk data
        for (int i = tid; i < 4096; i += 256) {
            int l = i >> 6, q = i & 63;
            const float* row = conv + (tok0 + l) * CONV_DIM;
            xs[l * SSD_ST + q] = row[h * 64 + q];
            Bm[l * SSD_ST + q] = row[D_INNER + q];
            Cm[l * SSD_ST + q] = row[D_INNER + D_STATE + q];
        }
        if (tid < 64) {
            float x = zx[(tok0 + tid) * D_IN_PROJ + (D_IN_PROJ - NHEADS) + h] + dtbh;
            float dt = (x > 20.f) ? x : log1pf(expf(x));
            dts[tid] = dt;
            acum[tid] = Ah * dt;
        }
        __syncthreads();
        if (tid == 0) {
            float s = 0.f;
            for (int l = 0; l < 64; l++) { s += acum[l]; acum[l] = s; }
        }
        __syncthreads();
        if (tid < 64) {
            eAl[tid] = expf(acum[tid]);
            dd[tid] = dts[tid] * expf(acum[63] - acum[tid]);
        }
        __syncthreads();
        // M(l,s) = exp(acum_l - acum_s) * (C_l . B_s) * dt_s  (s<=l)
        for (int i = tid; i < 4096; i += 256) {
            int l = i >> 6, s = i & 63;
            float v = 0.f;
            if (s <= l) {
                float g = 0.f;
                #pragma unroll 8
                for (int n = 0; n < 64; n++) g += Cm[l * SSD_ST + n] * Bm[s * SSD_ST + n];
                v = g * expf(acum[l] - acum[s]) * dts[s];
            }
            Mm[l * SSD_ST + s] = v;
        }
        __syncthreads();
        // Y(l,p) = sum_s M(l,s)*x(s,p) + exp(acum_l)*sum_n C(l,n)*S(n,p) + Dh*x(l,p)
        for (int i = 0; i < 16; i++) {
            int l = lg * 16 + i;
            float a = Dh * xs[l * SSD_ST + p];
            for (int s = 0; s <= l; s++) a += Mm[l * SSD_ST + s] * xs[s * SSD_ST + p];
            float off = 0.f;
            #pragma unroll 8
            for (int n = 0; n < 64; n++) off += Cm[l * SSD_ST + n] * S[n * SSD_ST + p];
            out[(tok0 + l) * D_INNER + h * 64 + p] = a + eAl[l] * off;
        }
        __syncthreads();
        // S(n,p) <- exp(acum63)*S(n,p) + sum_l B(l,n)*dd(l)*x(l,p)
        float eTot = eAl[63];
        for (int i = 0; i < 16; i++) {
            int n = lg * 16 + i;
            float s = S[n * SSD_ST + p] * eTot;
            for (int l = 0; l < 64; l++)
                s += (Bm[l * SSD_ST + n] * dd[l]) * xs[l * SSD_ST + p];
            S[n * SSD_ST + p] = s;
        }
        __syncthreads();
    }
}

// ---------------- gated RMSNorm: rmsnorm(y*silu(z)) * gw ----------------
__global__ void gated_kernel(const float* __restrict__ yin, const float* __restrict__ zx,
                             const float* __restrict__ gw, float* __restrict__ out) {
    __shared__ float sh[8];
    long t = blockIdx.x;
    int d = threadIdx.x;
    float z0 = zx[t * D_IN_PROJ + d];
    float z1 = zx[t * D_IN_PROJ + d + 256];
    float u0 = yin[t * D_INNER + d] * silu_f(z0);
    float u1 = yin[t * D_INNER + d + 256] * silu_f(z1);
    float ms = block_sum256(u0 * u0 + u1 * u1, sh) * (1.f / D_INNER);
    float r = rsqrtf(ms + EPS);
    out[t * D_INNER + d] = u0 * r * gw[d];
    out[t * D_INNER + d + 256] = u1 * r * gw[d + 256];
}

// ---------------- final: rmsnorm(last token) -> elu -> @ out_W^T ----------------
__global__ void final_kernel(const float* __restrict__ y, const float* __restrict__ nw,
                             const float* __restrict__ ow, float* __restrict__ out) {
    __shared__ float sh[8];
    __shared__ float u[256];
    int b = blockIdx.x;
    int d = threadIdx.x;
    float v = y[((long)b * L_ + (L_ - 1)) * D_MODEL + d];
    float ms = block_sum256(v * v, sh) * (1.f / D_MODEL);
    float x = v * rsqrtf(ms + EPS) * nw[d];
    u[d] = (x > 0.f) ? x : (expf(x) - 1.f);
    __syncthreads();
    if (d < COUT_) {
        float a = 0.f;
        for (int k = 0; k < D_MODEL; k++) a += u[k] * ow[d * D_MODEL + k];
        out[b * COUT_ + d] = a;
    }
}

// ---------------- host orchestration ----------------
extern "C" void kernel_launch(void* const* d_in, const int* in_sizes, int n_in,
                              void* d_out, int out_size) {
    const float* obs     = (const float*)d_in[0];
    const float* in_W    = (const float*)d_in[1];
    const float* ln1_w   = (const float*)d_in[2];
    const float* ln1_b   = (const float*)d_in[3];
    const float* rms_w   = (const float*)d_in[4];
    const float* inproj  = (const float*)d_in[5];
    const float* conv_w  = (const float*)d_in[6];
    const float* conv_b  = (const float*)d_in[7];
    const float* dt_bias = (const float*)d_in[8];
    const float* A_log   = (const float*)d_in[9];
    const float* Dp      = (const float*)d_in[10];
    const float* gnorm   = (const float*)d_in[11];
    const float* outproj = (const float*)d_in[12];
    const float* normf   = (const float*)d_in[13];
    const float* out_W   = (const float*)d_in[14];
    float* out = (float*)d_out;

    float *y, *h, *zx, *conv, *ssd, *gate;
    cudaGetSymbolAddress((void**)&y, g_y);
    cudaGetSymbolAddress((void**)&h, g_h);
    cudaGetSymbolAddress((void**)&zx, g_zx);
    cudaGetSymbolAddress((void**)&conv, g_conv);
    cudaGetSymbolAddress((void**)&ssd, g_ssd);
    cudaGetSymbolAddress((void**)&gate, g_gate);

    size_t ssd_smem = SSD_SMEM_FLOATS * sizeof(float);
    cudaFuncSetAttribute(ssd_kernel, cudaFuncAttributeMaxDynamicSharedMemorySize,
                         (int)ssd_smem);

    // 1) y = obs @ in_W^T  (M=65536, N=256, K=48), then LayerNorm in place
    {
        dim3 grid((D_MODEL + TBN - 1) / TBN, NTOK / TBM);
        gemm_bt<<<grid, 256>>>(obs, in_W, nullptr, y, NTOK, D_MODEL, CIN);
        ln_kernel<<<NTOK, 256>>>(y, ln1_w, ln1_b);
    }

    for (int i = 0; i < N_LAYER; i++) {
        const float* Wi = inproj + (long)i * D_IN_PROJ * D_MODEL;
        const float* Wo = outproj + (long)i * D_MODEL * D_INNER;
        const float* cwi = conv_w + (long)i * CONV_DIM * D_CONV;
        const float* cbi = conv_b + (long)i * CONV_DIM;
        const float* dtbi = dt_bias + i * NHEADS;
        const float* Ali = A_log + i * NHEADS;
        const float* Dpi = Dp + i * NHEADS;
        const float* gwi = gnorm + (long)i * D_INNER;
        const float* rwi = rms_w + (long)i * D_MODEL;

        // a) h = rmsnorm(y) * rms_w
        rms_kernel<<<NTOK, 256>>>(y, rwi, h);
        // b) zx = h @ Wi^T (N=1160, K=256)
        {
            dim3 grid((D_IN_PROJ + TBN - 1) / TBN, NTOK / TBM);
            gemm_bt<<<grid, 256>>>(h, Wi, nullptr, zx, NTOK, D_IN_PROJ, D_MODEL);
        }
        // c) conv + silu
        {
            long total = (long)NTOK * CONV_DIM;
            int blocks = (int)((total + 255) / 256);
            conv_kernel<<<blocks, 256>>>(zx, cwi, cbi, conv);
        }
        // d) SSD scan
        ssd_kernel<<<B_ * NHEADS, 256, ssd_smem>>>(conv, zx, dtbi, Ali, Dpi, ssd);
        // e) gated rmsnorm
        gated_kernel<<<NTOK, 256>>>(ssd, zx, gwi, gate);
        // f) y = y + gate @ Wo^T (N=256, K=512)
        {
            dim3 grid((D_MODEL + TBN - 1) / TBN, NTOK / TBM);
            gemm_bt<<<grid, 256>>>(gate, Wo, y, y, NTOK, D_MODEL, D_INNER);
        }
    }

    // final head
    final_kernel<<<B_, 256>>>(y, normf, out_W, out);
}

// round 3
// speedup vs baseline: 1.0772x; 1.0772x over previous
#include <cuda_runtime.h>
#include <cuda_bf16.h>
#include <math.h>

#define B_ 128
#define L_ 512
#define CIN 48
#define COUT_ 12
#define D_MODEL 256
#define N_LAYER 4
#define D_STATE 64
#define D_CONV 4
#define HEADDIM 64
#define CHUNK 64
#define D_INNER 512
#define NHEADS 8
#define CONV_DIM 640
#define D_IN_PROJ 1160
#define NTOK (B_ * L_)
#define EPS 1e-5f

// ---------------- scratch (static device globals; no runtime alloc) ----------------
__device__ float g_y[NTOK * D_MODEL];        // residual stream
__device__ float g_h[NTOK * D_MODEL];        // rmsnorm output
__device__ float g_zx[NTOK * D_IN_PROJ];     // in_proj output (z | xBC | dt)
__device__ float g_conv[NTOK * CONV_DIM];    // conv+silu output
__device__ float g_ssd[NTOK * D_INNER];      // ssd output (+D term)
__device__ float g_gate[NTOK * D_INNER];     // gated rmsnorm output

// ---------------- block reduction (256 threads) ----------------
__device__ __forceinline__ float block_sum256(float v, float* sh) {
    #pragma unroll
    for (int o = 16; o; o >>= 1) v += __shfl_xor_sync(0xffffffffu, v, o);
    if ((threadIdx.x & 31) == 0) sh[threadIdx.x >> 5] = v;
    __syncthreads();
    if (threadIdx.x < 8) {
        v = sh[threadIdx.x];
        #pragma unroll
        for (int o = 4; o; o >>= 1) v += __shfl_xor_sync(0xffu, v, o);
        if (threadIdx.x == 0) sh[0] = v;
    }
    __syncthreads();
    float r = sh[0];
    __syncthreads();
    return r;
}

__device__ __forceinline__ float silu_f(float x) { return x / (1.f + expf(-x)); }

// ---------------- tf32 helpers ----------------
__device__ __forceinline__ unsigned f2tf32(float v) {
    unsigned r;
    asm("cvt.rna.tf32.f32 %0, %1;" : "=r"(r) : "f"(v));
    return r;
}
__device__ __forceinline__ void split_tf32(float v, unsigned& hi, unsigned& lo) {
    hi = f2tf32(v);
    lo = f2tf32(v - __uint_as_float(hi));
}
__device__ __forceinline__ void mma_tf32(float (&d)[4], const unsigned (&a)[4],
                                         const unsigned (&b)[2]) {
    asm volatile(
        "mma.sync.aligned.m16n8k8.row.col.f32.tf32.tf32.f32 "
        "{%0,%1,%2,%3}, {%4,%5,%6,%7}, {%8,%9}, {%0,%1,%2,%3};\n"
        : "+f"(d[0]), "+f"(d[1]), "+f"(d[2]), "+f"(d[3])
        : "r"(a[0]), "r"(a[1]), "r"(a[2]), "r"(a[3]), "r"(b[0]), "r"(b[1]));
}

// ---------------- tensor-core GEMM: C[M,N] = A[M,K] @ W[N,K]^T (+res) ----------------
// 3xTF32 (hi/lo split) for ~fp32 accuracy. Block tile 128x64x16, 8 warps (4x2),
// warp tile 32x32 -> 2x4 mma tiles of m16n8k8, two k8 steps per BK.
// Requires M%128==0, K%16==0, N%8==0 (all shapes here satisfy this).
#define TBM 128
#define TBN 64
#define TBK 16
__global__ __launch_bounds__(256) void gemm_tc(
        const float* __restrict__ A, const float* __restrict__ W,
        const float* __restrict__ res, float* __restrict__ C,
        int M, int N, int K) {
    __shared__ float As[TBK][TBM + 4];
    __shared__ float Ws[TBK][TBN + 4];
    int tid = threadIdx.x;
    int lane = tid & 31, wid = tid >> 5;
    int wm = (wid >> 1) * 32;            // warp M offset in tile
    int wn = (wid & 1) * 32;             // warp N offset in tile
    int grp = lane >> 2, qk = lane & 3;
    int m0 = blockIdx.y * TBM, n0 = blockIdx.x * TBN;

    // global load mappings
    int alm = tid >> 1;                  // 0..127 (A row)
    int alk = (tid & 1) * 8;             // 0 or 8
    int wlm = tid >> 2;                  // 0..63 (W row)
    int wlk = (tid & 3) * 4;             // 0,4,8,12

    const float* aptr = A + (long)(m0 + alm) * K + alk;
    const float* wptr = (n0 + wlm < N) ? (W + (long)(n0 + wlm) * K + wlk) : nullptr;

    float4 ar0 = *(const float4*)(aptr);
    float4 ar1 = *(const float4*)(aptr + 4);
    float4 wr = wptr ? *(const float4*)(wptr) : make_float4(0.f, 0.f, 0.f, 0.f);

    float acc[2][4][4];
    #pragma unroll
    for (int i = 0; i < 2; i++)
        #pragma unroll
        for (int j = 0; j < 4; j++)
            #pragma unroll
            for (int q = 0; q < 4; q++) acc[i][j][q] = 0.f;

    for (int k0 = 0; k0 < K; k0 += TBK) {
        // commit prefetched tile to smem
        As[alk + 0][alm] = ar0.x; As[alk + 1][alm] = ar0.y;
        As[alk + 2][alm] = ar0.z; As[alk + 3][alm] = ar0.w;
        As[alk + 4][alm] = ar1.x; As[alk + 5][alm] = ar1.y;
        As[alk + 6][alm] = ar1.z; As[alk + 7][alm] = ar1.w;
        Ws[wlk + 0][wlm] = wr.x; Ws[wlk + 1][wlm] = wr.y;
        Ws[wlk + 2][wlm] = wr.z; Ws[wlk + 3][wlm] = wr.w;
        __syncthreads();

        // prefetch next tile into registers (overlaps with mma below)
        if (k0 + TBK < K) {
            ar0 = *(const float4*)(aptr + k0 + TBK);
            ar1 = *(const float4*)(aptr + k0 + TBK + 4);
            if (wptr) wr = *(const float4*)(wptr + k0 + TBK);
        }

        #pragma unroll
        for (int kt = 0; kt < TBK; kt += 8) {
            unsigned ah[2][4], al[2][4], bh[4][2], bl[4][2];
            #pragma unroll
            for (int mt = 0; mt < 2; mt++) {
                int m = wm + mt * 16 + grp;
                split_tf32(As[kt + qk][m],         ah[mt][0], al[mt][0]);
                split_tf32(As[kt + qk][m + 8],     ah[mt][1], al[mt][1]);
                split_tf32(As[kt + qk + 4][m],     ah[mt][2], al[mt][2]);
                split_tf32(As[kt + qk + 4][m + 8], ah[mt][3], al[mt][3]);
            }
            #pragma unroll
            for (int nt = 0; nt < 4; nt++) {
                int n = wn + nt * 8 + grp;
                split_tf32(Ws[kt + qk][n],     bh[nt][0], bl[nt][0]);
                split_tf32(Ws[kt + qk + 4][n], bh[nt][1], bl[nt][1]);
            }
            #pragma unroll
            for (int mt = 0; mt < 2; mt++)
                #pragma unroll
                for (int nt = 0; nt < 4; nt++) {
                    mma_tf32(acc[mt][nt], ah[mt], bl[nt]);
                    mma_tf32(acc[mt][nt], al[mt], bh[nt]);
                    mma_tf32(acc[mt][nt], ah[mt], bh[nt]);
                }
        }
        __syncthreads();
    }

    // epilogue: c frag rows = grp / grp+8, cols = qk*2, qk*2+1
    #pragma unroll
    for (int mt = 0; mt < 2; mt++) {
        #pragma unroll
        for (int nt = 0; nt < 4; nt++) {
            int col = n0 + wn + nt * 8 + qk * 2;
            if (col >= N) continue;
            int row = m0 + wm + mt * 16 + grp;
            long off0 = (long)row * N + col;
            long off1 = (long)(row + 8) * N + col;
            float2 v0 = make_float2(acc[mt][nt][0], acc[mt][nt][1]);
            float2 v1 = make_float2(acc[mt][nt][2], acc[mt][nt][3]);
            if (res) {
                float2 r0 = *(const float2*)(res + off0);
                float2 r1 = *(const float2*)(res + off1);
                v0.x += r0.x; v0.y += r0.y;
                v1.x += r1.x; v1.y += r1.y;
            }
            *(float2*)(C + off0) = v0;
            *(float2*)(C + off1) = v1;
        }
    }
}

// ---------------- LayerNorm (in place, 256 dims, 1 token/block) ----------------
__global__ void ln_kernel(float* __restrict__ y, const float* __restrict__ w,
                          const float* __restrict__ b) {
    __shared__ float sh[8];
    long t = blockIdx.x;
    int d = threadIdx.x;
    float v = y[t * D_MODEL + d];
    float mean = block_sum256(v, sh) * (1.f / D_MODEL);
    float dv = v - mean;
    float var = block_sum256(dv * dv, sh) * (1.f / D_MODEL);
    y[t * D_MODEL + d] = dv * rsqrtf(var + EPS) * w[d] + b[d];
}

// ---------------- RMSNorm 256 -> g_h ----------------
__global__ void rms_kernel(const float* __restrict__ y, const float* __restrict__ w,
                           float* __restrict__ out) {
    __shared__ float sh[8];
    long t = blockIdx.x;
    int d = threadIdx.x;
    float v = y[t * D_MODEL + d];
    float ms = block_sum256(v * v, sh) * (1.f / D_MODEL);
    out[t * D_MODEL + d] = v * rsqrtf(ms + EPS) * w[d];
}

// ---------------- depthwise causal conv (width 4) + bias + silu ----------------
__global__ void conv_kernel(const float* __restrict__ zx, const float* __restrict__ cw,
                            const float* __restrict__ cb, float* __restrict__ out) {
    long idx = (long)blockIdx.x * blockDim.x + threadIdx.x;
    if (idx >= (long)NTOK * CONV_DIM) return;
    int ch = (int)(idx % CONV_DIM);
    long t = idx / CONV_DIM;
    int l = (int)(t & (L_ - 1));
    long brow = t - l;  // b*L_
    float acc = cb[ch];
    #pragma unroll
    for (int k = 0; k < D_CONV; k++) {
        int ls = l + k - (D_CONV - 1);
        if (ls >= 0)
            acc += zx[(brow + ls) * D_IN_PROJ + D_INNER + ch] * cw[ch * D_CONV + k];
    }
    out[t * CONV_DIM + ch] = silu_f(acc);
}

// ---------------- SSD chunked scan: one block per (b,h), sequential over 8 chunks ----
#define SSD_ST 65
#define SSD_SMEM_FLOATS (5 * 64 * SSD_ST + 4 * 64)
__global__ void ssd_kernel(const float* __restrict__ conv, const float* __restrict__ zx,
                           const float* __restrict__ dtb, const float* __restrict__ Alog,
                           const float* __restrict__ Dp, float* __restrict__ out) {
    extern __shared__ float sm[];
    float* xs = sm;                    // [64][65]  x (unscaled)
    float* Bm = xs + 64 * SSD_ST;      // [64][65]
    float* Cm = Bm + 64 * SSD_ST;      // [64][65]
    float* Mm = Cm + 64 * SSD_ST;      // [64][65]  M(l,s)*dt(s)
    float* S  = Mm + 64 * SSD_ST;      // [64][65]  state S[n][p]
    float* acum = S + 64 * SSD_ST;     // 64
    float* dts  = acum + 64;
    float* dd   = dts + 64;            // dt(l)*exp(acum63-acum(l))
    float* eAl  = dd + 64;             // exp(acum(l))

    int tid = threadIdx.x;
    int b = blockIdx.x >> 3, h = blockIdx.x & 7;
    float Ah = -expf(Alog[h]);
    float dtbh = dtb[h];
    float Dh = Dp[h];
    int p = tid & 63, lg = tid >> 6;

    for (int i = tid; i < 64 * SSD_ST; i += 256) S[i] = 0.f;
    __syncthreads();

    for (int c = 0; c < 8; ++c) {
        long tok0 = (long)b * L_ + c * CHUNK;
        // load chunk data
        for (int i = tid; i < 4096; i += 256) {
            int l = i >> 6, q = i & 63;
            const float* row = conv + (tok0 + l) * CONV_DIM;
            xs[l * SSD_ST + q] = row[h * 64 + q];
            Bm[l * SSD_ST + q] = row[D_INNER + q];
            Cm[l * SSD_ST + q] = row[D_INNER + D_STATE + q];
        }
        if (tid < 64) {
            float x = zx[(tok0 + tid) * D_IN_PROJ + (D_IN_PROJ - NHEADS) + h] + dtbh;
            float dt = (x > 20.f) ? x : log1pf(expf(x));
            dts[tid] = dt;
            acum[tid] = Ah * dt;
        }
        __syncthreads();
        if (tid == 0) {
            float s = 0.f;
            for (int l = 0; l < 64; l++) { s += acum[l]; acum[l] = s; }
        }
        __syncthreads();
        if (tid < 64) {
            eAl[tid] = expf(acum[tid]);
            dd[tid] = dts[tid] * expf(acum[63] - acum[tid]);
        }
        __syncthreads();
        // M(l,s) = exp(acum_l - acum_s) * (C_l . B_s) * dt_s  (s<=l)
        for (int i = tid; i < 4096; i += 256) {
            int l = i >> 6, s = i & 63;
            float v = 0.f;
            if (s <= l) {
                float g = 0.f;
                #pragma unroll 8
                for (int n = 0; n < 64; n++) g += Cm[l * SSD_ST + n] * Bm[s * SSD_ST + n];
                v = g * expf(acum[l] - acum[s]) * dts[s];
            }
            Mm[l * SSD_ST + s] = v;
        }
        __syncthreads();
        // Y(l,p) = sum_s M(l,s)*x(s,p) + exp(acum_l)*sum_n C(l,n)*S(n,p) + Dh*x(l,p)
        for (int i = 0; i < 16; i++) {
            int l = lg * 16 + i;
            float a = Dh * xs[l * SSD_ST + p];
            for (int s = 0; s <= l; s++) a += Mm[l * SSD_ST + s] * xs[s * SSD_ST + p];
            float off = 0.f;
            #pragma unroll 8
            for (int n = 0; n < 64; n++) off += Cm[l * SSD_ST + n] * S[n * SSD_ST + p];
            out[(tok0 + l) * D_INNER + h * 64 + p] = a + eAl[l] * off;
        }
        __syncthreads();
        // S(n,p) <- exp(acum63)*S(n,p) + sum_l B(l,n)*dd(l)*x(l,p)
        float eTot = eAl[63];
        for (int i = 0; i < 16; i++) {
            int n = lg * 16 + i;
            float s = S[n * SSD_ST + p] * eTot;
            for (int l = 0; l < 64; l++)
                s += (Bm[l * SSD_ST + n] * dd[l]) * xs[l * SSD_ST + p];
            S[n * SSD_ST + p] = s;
        }
        __syncthreads();
    }
}

// ---------------- gated RMSNorm: rmsnorm(y*silu(z)) * gw ----------------
__global__ void gated_kernel(const float* __restrict__ yin, const float* __restrict__ zx,
                             const float* __restrict__ gw, float* __restrict__ out) {
    __shared__ float sh[8];
    long t = blockIdx.x;
    int d = threadIdx.x;
    float z0 = zx[t * D_IN_PROJ + d];
    float z1 = zx[t * D_IN_PROJ + d + 256];
    float u0 = yin[t * D_INNER + d] * silu_f(z0);
    float u1 = yin[t * D_INNER + d + 256] * silu_f(z1);
    float ms = block_sum256(u0 * u0 + u1 * u1, sh) * (1.f / D_INNER);
    float r = rsqrtf(ms + EPS);
    out[t * D_INNER + d] = u0 * r * gw[d];
    out[t * D_INNER + d + 256] = u1 * r * gw[d + 256];
}

// ---------------- final: rmsnorm(last token) -> elu -> @ out_W^T ----------------
__global__ void final_kernel(const float* __restrict__ y, const float* __restrict__ nw,
                             const float* __restrict__ ow, float* __restrict__ out) {
    __shared__ float sh[8];
    __shared__ float u[256];
    int b = blockIdx.x;
    int d = threadIdx.x;
    float v = y[((long)b * L_ + (L_ - 1)) * D_MODEL + d];
    float ms = block_sum256(v * v, sh) * (1.f / D_MODEL);
    float x = v * rsqrtf(ms + EPS) * nw[d];
    u[d] = (x > 0.f) ? x : (expf(x) - 1.f);
    __syncthreads();
    if (d < COUT_) {
        float a = 0.f;
        for (int k = 0; k < D_MODEL; k++) a += u[k] * ow[d * D_MODEL + k];
        out[b * COUT_ + d] = a;
    }
}

// ---------------- host orchestration ----------------
extern "C" void kernel_launch(void* const* d_in, const int* in_sizes, int n_in,
                              void* d_out, int out_size) {
    const float* obs     = (const float*)d_in[0];
    const float* in_W    = (const float*)d_in[1];
    const float* ln1_w   = (const float*)d_in[2];
    const float* ln1_b   = (const float*)d_in[3];
    const float* rms_w   = (const float*)d_in[4];
    const float* inproj  = (const float*)d_in[5];
    const float* conv_w  = (const float*)d_in[6];
    const float* conv_b  = (const float*)d_in[7];
    const float* dt_bias = (const float*)d_in[8];
    const float* A_log   = (const float*)d_in[9];
    const float* Dp      = (const float*)d_in[10];
    const float* gnorm   = (const float*)d_in[11];
    const float* outproj = (const float*)d_in[12];
    const float* normf   = (const float*)d_in[13];
    const float* out_W   = (const float*)d_in[14];
    float* out = (float*)d_out;

    float *y, *h, *zx, *conv, *ssd, *gate;
    cudaGetSymbolAddress((void**)&y, g_y);
    cudaGetSymbolAddress((void**)&h, g_h);
    cudaGetSymbolAddress((void**)&zx, g_zx);
    cudaGetSymbolAddress((void**)&conv, g_conv);
    cudaGetSymbolAddress((void**)&ssd, g_ssd);
    cudaGetSymbolAddress((void**)&gate, g_gate);

    size_t ssd_smem = SSD_SMEM_FLOATS * sizeof(float);
    cudaFuncSetAttribute(ssd_kernel, cudaFuncAttributeMaxDynamicSharedMemorySize,
                         (int)ssd_smem);

    // 1) y = obs @ in_W^T  (M=65536, N=256, K=48), then LayerNorm in place
    {
        dim3 grid((D_MODEL + TBN - 1) / TBN, NTOK / TBM);
        gemm_tc<<<grid, 256>>>(obs, in_W, nullptr, y, NTOK, D_MODEL, CIN);
        ln_kernel<<<NTOK, 256>>>(y, ln1_w, ln1_b);
    }

    for (int i = 0; i < N_LAYER; i++) {
        const float* Wi = inproj + (long)i * D_IN_PROJ * D_MODEL;
        const float* Wo = outproj + (long)i * D_MODEL * D_INNER;
        const float* cwi = conv_w + (long)i * CONV_DIM * D_CONV;
        const float* cbi = conv_b + (long)i * CONV_DIM;
        const float* dtbi = dt_bias + i * NHEADS;
        const float* Ali = A_log + i * NHEADS;
        const float* Dpi = Dp + i * NHEADS;
        const float* gwi = gnorm + (long)i * D_INNER;
        const float* rwi = rms_w + (long)i * D_MODEL;

        // a) h = rmsnorm(y) * rms_w
        rms_kernel<<<NTOK, 256>>>(y, rwi, h);
        // b) zx = h @ Wi^T (N=1160, K=256)
        {
            dim3 grid((D_IN_PROJ + TBN - 1) / TBN, NTOK / TBM);
            gemm_tc<<<grid, 256>>>(h, Wi, nullptr, zx, NTOK, D_IN_PROJ, D_MODEL);
        }
        // c) conv + silu
        {
            long total = (long)NTOK * CONV_DIM;
            int blocks = (int)((total + 255) / 256);
            conv_kernel<<<blocks, 256>>>(zx, cwi, cbi, conv);
        }
        // d) SSD scan
        ssd_kernel<<<B_ * NHEADS, 256, ssd_smem>>>(conv, zx, dtbi, Ali, Dpi, ssd);
        // e) gated rmsnorm
        gated_kernel<<<NTOK, 256>>>(ssd, zx, gwi, gate);
        // f) y = y + gate @ Wo^T (N=256, K=512)
        {
            dim3 grid((D_MODEL + TBN - 1) / TBN, NTOK / TBM);
            gemm_tc<<<grid, 256>>>(gate, Wo, y, y, NTOK, D_MODEL, D_INNER);
        }
    }

    // final head
    final_kernel<<<B_, 256>>>(y, normf, out_W, out);
}

// round 4
// speedup vs baseline: 1.1846x; 1.0997x over previous
#include <cuda_runtime.h>
#include <cuda_bf16.h>
#include <math.h>

#define B_ 128
#define L_ 512
#define CIN 48
#define COUT_ 12
#define D_MODEL 256
#define N_LAYER 4
#define D_STATE 64
#define D_CONV 4
#define HEADDIM 64
#define CHUNK 64
#define D_INNER 512
#define NHEADS 8
#define CONV_DIM 640
#define D_IN_PROJ 1160
#define NTOK (B_ * L_)
#define EPS 1e-5f

// ---------------- scratch (static device globals; no runtime alloc) ----------------
__device__ float g_y[NTOK * D_MODEL];        // residual stream
__device__ float g_h[NTOK * D_MODEL];        // rmsnorm output
__device__ float g_zx[NTOK * D_IN_PROJ];     // in_proj output (z | xBC | dt)
__device__ float g_conv[NTOK * CONV_DIM];    // conv+silu output
__device__ float g_ssd[NTOK * D_INNER];      // ssd output (+D term)
__device__ float g_gate[NTOK * D_INNER];     // gated rmsnorm output

// ---------------- block reduction (256 threads) ----------------
__device__ __forceinline__ float block_sum256(float v, float* sh) {
    #pragma unroll
    for (int o = 16; o; o >>= 1) v += __shfl_xor_sync(0xffffffffu, v, o);
    if ((threadIdx.x & 31) == 0) sh[threadIdx.x >> 5] = v;
    __syncthreads();
    if (threadIdx.x < 8) {
        v = sh[threadIdx.x];
        #pragma unroll
        for (int o = 4; o; o >>= 1) v += __shfl_xor_sync(0xffu, v, o);
        if (threadIdx.x == 0) sh[0] = v;
    }
    __syncthreads();
    float r = sh[0];
    __syncthreads();
    return r;
}

__device__ __forceinline__ float silu_f(float x) { return x / (1.f + expf(-x)); }

// ---------------- bf16 split helpers ----------------
__device__ __forceinline__ unsigned pack_hi2(float a, float b) {
    __nv_bfloat162 h = __floats2bfloat162_rn(a, b);
    return *reinterpret_cast<unsigned*>(&h);
}
__device__ __forceinline__ void split2(float a, float b, unsigned& hi, unsigned& lo) {
    __nv_bfloat16 ha = __float2bfloat16_rn(a);
    __nv_bfloat16 hb = __float2bfloat16_rn(b);
    __nv_bfloat162 h; h.x = ha; h.y = hb;
    __nv_bfloat162 l = __floats2bfloat162_rn(a - __bfloat162float(ha),
                                             b - __bfloat162float(hb));
    hi = *reinterpret_cast<unsigned*>(&h);
    lo = *reinterpret_cast<unsigned*>(&l);
}
__device__ __forceinline__ void mma_bf16(float (&d)[4], const unsigned (&a)[4],
                                         const unsigned (&b)[2]) {
    asm volatile(
        "mma.sync.aligned.m16n8k16.row.col.f32.bf16.bf16.f32 "
        "{%0,%1,%2,%3}, {%4,%5,%6,%7}, {%8,%9}, {%0,%1,%2,%3};\n"
        : "+f"(d[0]), "+f"(d[1]), "+f"(d[2]), "+f"(d[3])
        : "r"(a[0]), "r"(a[1]), "r"(a[2]), "r"(a[3]), "r"(b[0]), "r"(b[1]));
}

// ---------------- tensor-core GEMM: C[M,N] = A[M,K] @ W[N,K]^T (+res) ----------------
// bf16 split-3 (hi/lo): D = Ah*Wh + Ah*Wl + Al*Wh, fp32 accum. ~2^-16 per-product err.
// Block tile 128x64x16, 8 warps (4x2), warp tile 32x32 = 2x4 m16n8k16 tiles.
// Requires M%128==0, K%16==0, N%8==0.
#define TBM 128
#define TBN 64
#define TBK 16
#define SA_H (TBK + 8)        // halves per smem row
#define SA_W (SA_H / 2)       // 32-bit words per smem row (=12, conflict-free)
__global__ __launch_bounds__(256) void gemm_bf3(
        const float* __restrict__ A, const float* __restrict__ W,
        const float* __restrict__ res, float* __restrict__ C,
        int M, int N, int K) {
    __shared__ unsigned Ah[TBM * SA_W], Al[TBM * SA_W];
    __shared__ unsigned Wh[TBN * SA_W], Wl[TBN * SA_W];
    int tid = threadIdx.x;
    int lane = tid & 31, wid = tid >> 5;
    int wm = (wid >> 1) * 32;            // warp M offset in tile
    int wn = (wid & 1) * 32;             // warp N offset in tile
    int grp = lane >> 2, qk = lane & 3;
    int m0 = blockIdx.y * TBM, n0 = blockIdx.x * TBN;

    // global load mappings
    int alm = tid >> 1;                  // 0..127 (A row)
    int alk = (tid & 1) * 8;             // 0 or 8
    int wlm = tid >> 2;                  // 0..63 (W row)
    int wlk = (tid & 3) * 4;             // 0,4,8,12

    const float* aptr = A + (long)(m0 + alm) * K + alk;
    const float* wptr = (n0 + wlm < N) ? (W + (long)(n0 + wlm) * K + wlk) : nullptr;

    float4 ar0 = *(const float4*)(aptr);
    float4 ar1 = *(const float4*)(aptr + 4);
    float4 wr = wptr ? *(const float4*)(wptr) : make_float4(0.f, 0.f, 0.f, 0.f);

    float acc[2][4][4];
    #pragma unroll
    for (int i = 0; i < 2; i++)
        #pragma unroll
        for (int j = 0; j < 4; j++)
            #pragma unroll
            for (int q = 0; q < 4; q++) acc[i][j][q] = 0.f;

    for (int k0 = 0; k0 < K; k0 += TBK) {
        // commit prefetched tile to smem as bf16 hi/lo planes
        {
            unsigned h, l;
            int base = alm * SA_W + (alk >> 1);
            split2(ar0.x, ar0.y, h, l); Ah[base + 0] = h; Al[base + 0] = l;
            split2(ar0.z, ar0.w, h, l); Ah[base + 1] = h; Al[base + 1] = l;
            split2(ar1.x, ar1.y, h, l); Ah[base + 2] = h; Al[base + 2] = l;
            split2(ar1.z, ar1.w, h, l); Ah[base + 3] = h; Al[base + 3] = l;
            int wbase = wlm * SA_W + (wlk >> 1);
            split2(wr.x, wr.y, h, l); Wh[wbase + 0] = h; Wl[wbase + 0] = l;
            split2(wr.z, wr.w, h, l); Wh[wbase + 1] = h; Wl[wbase + 1] = l;
        }
        __syncthreads();

        // prefetch next tile into registers (overlaps with mma below)
        if (k0 + TBK < K) {
            ar0 = *(const float4*)(aptr + k0 + TBK);
            ar1 = *(const float4*)(aptr + k0 + TBK + 4);
            if (wptr) wr = *(const float4*)(wptr + k0 + TBK);
        }

        // fragments (one k16 step per tile)
        unsigned fah[2][4], fal[2][4], fbh[4][2], fbl[4][2];
        #pragma unroll
        for (int mt = 0; mt < 2; mt++) {
            int m = wm + mt * 16 + grp;
            fah[mt][0] = Ah[m * SA_W + qk];
            fah[mt][1] = Ah[(m + 8) * SA_W + qk];
            fah[mt][2] = Ah[m * SA_W + qk + 4];
            fah[mt][3] = Ah[(m + 8) * SA_W + qk + 4];
            fal[mt][0] = Al[m * SA_W + qk];
            fal[mt][1] = Al[(m + 8) * SA_W + qk];
            fal[mt][2] = Al[m * SA_W + qk + 4];
            fal[mt][3] = Al[(m + 8) * SA_W + qk + 4];
        }
        #pragma unroll
        for (int nt = 0; nt < 4; nt++) {
            int n = wn + nt * 8 + grp;
            fbh[nt][0] = Wh[n * SA_W + qk];
            fbh[nt][1] = Wh[n * SA_W + qk + 4];
            fbl[nt][0] = Wl[n * SA_W + qk];
            fbl[nt][1] = Wl[n * SA_W + qk + 4];
        }
        #pragma unroll
        for (int mt = 0; mt < 2; mt++)
            #pragma unroll
            for (int nt = 0; nt < 4; nt++) {
                mma_bf16(acc[mt][nt], fah[mt], fbl[nt]);
                mma_bf16(acc[mt][nt], fal[mt], fbh[nt]);
                mma_bf16(acc[mt][nt], fah[mt], fbh[nt]);
            }
        __syncthreads();
    }

    // epilogue: c frag rows = grp / grp+8, cols = qk*2, qk*2+1
    #pragma unroll
    for (int mt = 0; mt < 2; mt++) {
        #pragma unroll
        for (int nt = 0; nt < 4; nt++) {
            int col = n0 + wn + nt * 8 + qk * 2;
            if (col >= N) continue;
            int row = m0 + wm + mt * 16 + grp;
            long off0 = (long)row * N + col;
            long off1 = (long)(row + 8) * N + col;
            float2 v0 = make_float2(acc[mt][nt][0], acc[mt][nt][1]);
            float2 v1 = make_float2(acc[mt][nt][2], acc[mt][nt][3]);
            if (res) {
                float2 r0 = *(const float2*)(res + off0);
                float2 r1 = *(const float2*)(res + off1);
                v0.x += r0.x; v0.y += r0.y;
                v1.x += r1.x; v1.y += r1.y;
            }
            *(float2*)(C + off0) = v0;
            *(float2*)(C + off1) = v1;
        }
    }
}

// ---------------- LayerNorm (in place, 256 dims, 1 token/block) ----------------
__global__ void ln_kernel(float* __restrict__ y, const float* __restrict__ w,
                          const float* __restrict__ b) {
    __shared__ float sh[8];
    long t = blockIdx.x;
    int d = threadIdx.x;
    float v = y[t * D_MODEL + d];
    float mean = block_sum256(v, sh) * (1.f / D_MODEL);
    float dv = v - mean;
    float var = block_sum256(dv * dv, sh) * (1.f / D_MODEL);
    y[t * D_MODEL + d] = dv * rsqrtf(var + EPS) * w[d] + b[d];
}

// ---------------- RMSNorm 256 -> g_h ----------------
__global__ void rms_kernel(const float* __restrict__ y, const float* __restrict__ w,
                           float* __restrict__ out) {
    __shared__ float sh[8];
    long t = blockIdx.x;
    int d = threadIdx.x;
    float v = y[t * D_MODEL + d];
    float ms = block_sum256(v * v, sh) * (1.f / D_MODEL);
    out[t * D_MODEL + d] = v * rsqrtf(ms + EPS) * w[d];
}

// ---------------- depthwise causal conv (width 4) + bias + silu ----------------
__global__ void conv_kernel(const float* __restrict__ zx, const float* __restrict__ cw,
                            const float* __restrict__ cb, float* __restrict__ out) {
    long idx = (long)blockIdx.x * blockDim.x + threadIdx.x;
    if (idx >= (long)NTOK * CONV_DIM) return;
    int ch = (int)(idx % CONV_DIM);
    long t = idx / CONV_DIM;
    int l = (int)(t & (L_ - 1));
    long brow = t - l;  // b*L_
    float acc = cb[ch];
    #pragma unroll
    for (int k = 0; k < D_CONV; k++) {
        int ls = l + k - (D_CONV - 1);
        if (ls >= 0)
            acc += zx[(brow + ls) * D_IN_PROJ + D_INNER + ch] * cw[ch * D_CONV + k];
    }
    out[t * CONV_DIM + ch] = silu_f(acc);
}

// ---------------- SSD chunked scan: one block per (b,h), sequential over 8 chunks ----
#define SSD_ST 65
#define SSD_SMEM_FLOATS (5 * 64 * SSD_ST + 4 * 64)
__global__ void ssd_kernel(const float* __restrict__ conv, const float* __restrict__ zx,
                           const float* __restrict__ dtb, const float* __restrict__ Alog,
                           const float* __restrict__ Dp, float* __restrict__ out) {
    extern __shared__ float sm[];
    float* xs = sm;                    // [64][65]  x (unscaled)
    float* Bm = xs + 64 * SSD_ST;      // [64][65]
    float* Cm = Bm + 64 * SSD_ST;      // [64][65]
    float* Mm = Cm + 64 * SSD_ST;      // [64][65]  M(l,s)*dt(s)
    float* S  = Mm + 64 * SSD_ST;      // [64][65]  state S[n][p]
    float* acum = S + 64 * SSD_ST;     // 64
    float* dts  = acum + 64;
    float* dd   = dts + 64;            // dt(l)*exp(acum63-acum(l))
    float* eAl  = dd + 64;             // exp(acum(l))

    int tid = threadIdx.x;
    int b = blockIdx.x >> 3, h = blockIdx.x & 7;
    float Ah = -expf(Alog[h]);
    float dtbh = dtb[h];
    float Dh = Dp[h];
    int p = tid & 63, lg = tid >> 6;

    for (int i = tid; i < 64 * SSD_ST; i += 256) S[i] = 0.f;
    __syncthreads();

    for (int c = 0; c < 8; ++c) {
        long tok0 = (long)b * L_ + c * CHUNK;
        // load chunk data
        for (int i = tid; i < 4096; i += 256) {
            int l = i >> 6, q = i & 63;
            const float* row = conv + (tok0 + l) * CONV_DIM;
            xs[l * SSD_ST + q] = row[h * 64 + q];
            Bm[l * SSD_ST + q] = row[D_INNER + q];
            Cm[l * SSD_ST + q] = row[D_INNER + D_STATE + q];
        }
        if (tid < 64) {
            float x = zx[(tok0 + tid) * D_IN_PROJ + (D_IN_PROJ - NHEADS) + h] + dtbh;
            float dt = (x > 20.f) ? x : log1pf(expf(x));
            dts[tid] = dt;
            acum[tid] = Ah * dt;
        }
        __syncthreads();
        // warp-parallel inclusive scan of acum[0..63] (warp 0, 2 elems/lane)
        if (tid < 32) {
            float v0 = acum[2 * tid], v1 = acum[2 * tid + 1];
            float s = v0 + v1;
            #pragma unroll
            for (int o = 1; o < 32; o <<= 1) {
                float t = __shfl_up_sync(0xffffffffu, s, o);
                if (tid >= o) s += t;
            }
            acum[2 * tid] = s - v1;
            acum[2 * tid + 1] = s;
        }
        __syncthreads();
        if (tid < 64) {
            eAl[tid] = expf(acum[tid]);
            dd[tid] = dts[tid] * expf(acum[63] - acum[tid]);
        }
        __syncthreads();
        // M(l,s) = exp(acum_l - acum_s) * (C_l . B_s) * dt_s  (s<=l)
        for (int i = tid; i < 4096; i += 256) {
            int l = i >> 6, s = i & 63;
            float v = 0.f;
            if (s <= l) {
                float g = 0.f;
                #pragma unroll 8
                for (int n = 0; n < 64; n++) g += Cm[l * SSD_ST + n] * Bm[s * SSD_ST + n];
                v = g * expf(acum[l] - acum[s]) * dts[s];
            }
            Mm[l * SSD_ST + s] = v;
        }
        __syncthreads();
        // Y(l,p) = sum_s M(l,s)*x(s,p) + exp(acum_l)*sum_n C(l,n)*S(n,p) + Dh*x(l,p)
        for (int i = 0; i < 16; i++) {
            int l = lg * 16 + i;
            float a = Dh * xs[l * SSD_ST + p];
            for (int s = 0; s <= l; s++) a += Mm[l * SSD_ST + s] * xs[s * SSD_ST + p];
            float off = 0.f;
            #pragma unroll 8
            for (int n = 0; n < 64; n++) off += Cm[l * SSD_ST + n] * S[n * SSD_ST + p];
            out[(tok0 + l) * D_INNER + h * 64 + p] = a + eAl[l] * off;
        }
        __syncthreads();
        // S(n,p) <- exp(acum63)*S(n,p) + sum_l B(l,n)*dd(l)*x(l,p)
        float eTot = eAl[63];
        for (int i = 0; i < 16; i++) {
            int n = lg * 16 + i;
            float s = S[n * SSD_ST + p] * eTot;
            for (int l = 0; l < 64; l++)
                s += (Bm[l * SSD_ST + n] * dd[l]) * xs[l * SSD_ST + p];
            S[n * SSD_ST + p] = s;
        }
        __syncthreads();
    }
}

// ---------------- gated RMSNorm: rmsnorm(y*silu(z)) * gw ----------------
__global__ void gated_kernel(const float* __restrict__ yin, const float* __restrict__ zx,
                             const float* __restrict__ gw, float* __restrict__ out) {
    __shared__ float sh[8];
    long t = blockIdx.x;
    int d = threadIdx.x;
    float z0 = zx[t * D_IN_PROJ + d];
    float z1 = zx[t * D_IN_PROJ + d + 256];
    float u0 = yin[t * D_INNER + d] * silu_f(z0);
    float u1 = yin[t * D_INNER + d + 256] * silu_f(z1);
    float ms = block_sum256(u0 * u0 + u1 * u1, sh) * (1.f / D_INNER);
    float r = rsqrtf(ms + EPS);
    out[t * D_INNER + d] = u0 * r * gw[d];
    out[t * D_INNER + d + 256] = u1 * r * gw[d + 256];
}

// ---------------- final: rmsnorm(last token) -> elu -> @ out_W^T ----------------
__global__ void final_kernel(const float* __restrict__ y, const float* __restrict__ nw,
                             const float* __restrict__ ow, float* __restrict__ out) {
    __shared__ float sh[8];
    __shared__ float u[256];
    int b = blockIdx.x;
    int d = threadIdx.x;
    float v = y[((long)b * L_ + (L_ - 1)) * D_MODEL + d];
    float ms = block_sum256(v * v, sh) * (1.f / D_MODEL);
    float x = v * rsqrtf(ms + EPS) * nw[d];
    u[d] = (x > 0.f) ? x : (expf(x) - 1.f);
    __syncthreads();
    if (d < COUT_) {
        float a = 0.f;
        for (int k = 0; k < D_MODEL; k++) a += u[k] * ow[d * D_MODEL + k];
        out[b * COUT_ + d] = a;
    }
}

// ---------------- host orchestration ----------------
extern "C" void kernel_launch(void* const* d_in, const int* in_sizes, int n_in,
                              void* d_out, int out_size) {
    const float* obs     = (const float*)d_in[0];
    const float* in_W    = (const float*)d_in[1];
    const float* ln1_w   = (const float*)d_in[2];
    const float* ln1_b   = (const float*)d_in[3];
    const float* rms_w   = (const float*)d_in[4];
    const float* inproj  = (const float*)d_in[5];
    const float* conv_w  = (const float*)d_in[6];
    const float* conv_b  = (const float*)d_in[7];
    const float* dt_bias = (const float*)d_in[8];
    const float* A_log   = (const float*)d_in[9];
    const float* Dp      = (const float*)d_in[10];
    const float* gnorm   = (const float*)d_in[11];
    const float* outproj = (const float*)d_in[12];
    const float* normf   = (const float*)d_in[13];
    const float* out_W   = (const float*)d_in[14];
    float* out = (float*)d_out;

    float *y, *h, *zx, *conv, *ssd, *gate;
    cudaGetSymbolAddress((void**)&y, g_y);
    cudaGetSymbolAddress((void**)&h, g_h);
    cudaGetSymbolAddress((void**)&zx, g_zx);
    cudaGetSymbolAddress((void**)&conv, g_conv);
    cudaGetSymbolAddress((void**)&ssd, g_ssd);
    cudaGetSymbolAddress((void**)&gate, g_gate);

    size_t ssd_smem = SSD_SMEM_FLOATS * sizeof(float);
    cudaFuncSetAttribute(ssd_kernel, cudaFuncAttributeMaxDynamicSharedMemorySize,
                         (int)ssd_smem);

    // 1) y = obs @ in_W^T  (M=65536, N=256, K=48), then LayerNorm in place
    {
        dim3 grid((D_MODEL + TBN - 1) / TBN, NTOK / TBM);
        gemm_bf3<<<grid, 256>>>(obs, in_W, nullptr, y, NTOK, D_MODEL, CIN);
        ln_kernel<<<NTOK, 256>>>(y, ln1_w, ln1_b);
    }

    for (int i = 0; i < N_LAYER; i++) {
        const float* Wi = inproj + (long)i * D_IN_PROJ * D_MODEL;
        const float* Wo = outproj + (long)i * D_MODEL * D_INNER;
        const float* cwi = conv_w + (long)i * CONV_DIM * D_CONV;
        const float* cbi = conv_b + (long)i * CONV_DIM;
        const float* dtbi = dt_bias + i * NHEADS;
        const float* Ali = A_log + i * NHEADS;
        const float* Dpi = Dp + i * NHEADS;
        const float* gwi = gnorm + (long)i * D_INNER;
        const float* rwi = rms_w + (long)i * D_MODEL;

        // a) h = rmsnorm(y) * rms_w
        rms_kernel<<<NTOK, 256>>>(y, rwi, h);
        // b) zx = h @ Wi^T (N=1160, K=256)
        {
            dim3 grid((D_IN_PROJ + TBN - 1) / TBN, NTOK / TBM);
            gemm_bf3<<<grid, 256>>>(h, Wi, nullptr, zx, NTOK, D_IN_PROJ, D_MODEL);
        }
        // c) conv + silu
        {
            long total = (long)NTOK * CONV_DIM;
            int blocks = (int)((total + 255) / 256);
            conv_kernel<<<blocks, 256>>>(zx, cwi, cbi, conv);
        }
        // d) SSD scan
        ssd_kernel<<<B_ * NHEADS, 256, ssd_smem>>>(conv, zx, dtbi, Ali, Dpi, ssd);
        // e) gated rmsnorm
        gated_kernel<<<NTOK, 256>>>(ssd, zx, gwi, gate);
        // f) y = y + gate @ Wo^T (N=256, K=512)
        {
            dim3 grid((D_MODEL + TBN - 1) / TBN, NTOK / TBM);
            gemm_bf3<<<grid, 256>>>(gate, Wo, y, y, NTOK, D_MODEL, D_INNER);
        }
    }

    // final head
    final_kernel<<<B_, 256>>>(y, normf, out_W, out);
}

// round 5
// speedup vs baseline: 1.1939x; 1.0079x over previous
#include <cuda_runtime.h>
#include <cuda_bf16.h>
#include <math.h>

#define B_ 128
#define L_ 512
#define CIN 48
#define COUT_ 12
#define D_MODEL 256
#define N_LAYER 4
#define D_STATE 64
#define D_CONV 4
#define HEADDIM 64
#define CHUNK 64
#define D_INNER 512
#define NHEADS 8
#define CONV_DIM 640
#define D_IN_PROJ 1160
#define NTOK (B_ * L_)
#define EPS 1e-5f

// ---------------- scratch (static device globals; no runtime alloc) ----------------
__device__ float g_y[NTOK * D_MODEL];        // residual stream
__device__ float g_h[NTOK * D_MODEL];        // rmsnorm output
__device__ float g_zx[NTOK * D_IN_PROJ];     // in_proj output (z | xBC | dt)
__device__ float g_conv[NTOK * CONV_DIM];    // conv+silu output
__device__ float g_ssd[NTOK * D_INNER];      // ssd output (+D term)
__device__ float g_gate[NTOK * D_INNER];     // gated rmsnorm output

// ---------------- block reduction (256 threads) ----------------
__device__ __forceinline__ float block_sum256(float v, float* sh) {
    #pragma unroll
    for (int o = 16; o; o >>= 1) v += __shfl_xor_sync(0xffffffffu, v, o);
    if ((threadIdx.x & 31) == 0) sh[threadIdx.x >> 5] = v;
    __syncthreads();
    if (threadIdx.x < 8) {
        v = sh[threadIdx.x];
        #pragma unroll
        for (int o = 4; o; o >>= 1) v += __shfl_xor_sync(0xffu, v, o);
        if (threadIdx.x == 0) sh[0] = v;
    }
    __syncthreads();
    float r = sh[0];
    __syncthreads();
    return r;
}

__device__ __forceinline__ float silu_f(float x) { return x / (1.f + expf(-x)); }

// ---------------- bf16 split helpers ----------------
__device__ __forceinline__ void split2(float a, float b, unsigned& hi, unsigned& lo) {
    __nv_bfloat16 ha = __float2bfloat16_rn(a);
    __nv_bfloat16 hb = __float2bfloat16_rn(b);
    __nv_bfloat162 h; h.x = ha; h.y = hb;
    __nv_bfloat162 l = __floats2bfloat162_rn(a - __bfloat162float(ha),
                                             b - __bfloat162float(hb));
    hi = *reinterpret_cast<unsigned*>(&h);
    lo = *reinterpret_cast<unsigned*>(&l);
}
__device__ __forceinline__ void mma_bf16(float (&d)[4], const unsigned (&a)[4],
                                         const unsigned (&b)[2]) {
    asm volatile(
        "mma.sync.aligned.m16n8k16.row.col.f32.bf16.bf16.f32 "
        "{%0,%1,%2,%3}, {%4,%5,%6,%7}, {%8,%9}, {%0,%1,%2,%3};\n"
        : "+f"(d[0]), "+f"(d[1]), "+f"(d[2]), "+f"(d[3])
        : "r"(a[0]), "r"(a[1]), "r"(a[2]), "r"(a[3]), "r"(b[0]), "r"(b[1]));
}
__device__ __forceinline__ void ldsm_x4(unsigned (&r)[4], unsigned addr) {
    asm volatile("ldmatrix.sync.aligned.m8n8.x4.shared.b16 {%0,%1,%2,%3}, [%4];"
        : "=r"(r[0]), "=r"(r[1]), "=r"(r[2]), "=r"(r[3]) : "r"(addr));
}

// ---------------- tensor-core GEMM: C[M,N] = A[M,K] @ W[N,K]^T (+res) ----------------
// bf16 split-3 (hi/lo): D = Ah*Wh + Ah*Wl + Al*Wh, fp32 accum.
// Block tile 128x64x16, 8 warps (4x2), warp tile 32x32 = 2x4 m16n8k16 tiles.
// Fragments loaded with ldmatrix (48B row stride = conflict-free).
// Requires M%128==0, K%16==0, N%8==0.
#define TBM 128
#define TBN 64
#define TBK 16
#define SA_H (TBK + 8)        // halves per smem row
#define SA_W (SA_H / 2)       // 32-bit words per smem row (=12 -> 48B stride)
__global__ __launch_bounds__(256) void gemm_bf3(
        const float* __restrict__ A, const float* __restrict__ W,
        const float* __restrict__ res, float* __restrict__ C,
        int M, int N, int K) {
    __shared__ unsigned Ah[TBM * SA_W], Al[TBM * SA_W];
    __shared__ unsigned Wh[TBN * SA_W], Wl[TBN * SA_W];
    int tid = threadIdx.x;
    int lane = tid & 31, wid = tid >> 5;
    int wm = (wid >> 1) * 32;            // warp M offset in tile
    int wn = (wid & 1) * 32;             // warp N offset in tile
    int grp = lane >> 2, qk = lane & 3;
    int m0 = blockIdx.y * TBM, n0 = blockIdx.x * TBN;

    // global load mappings
    int alm = tid >> 1;                  // 0..127 (A row)
    int alk = (tid & 1) * 8;             // 0 or 8
    int wlm = tid >> 2;                  // 0..63 (W row)
    int wlk = (tid & 3) * 4;             // 0,4,8,12

    const float* aptr = A + (long)(m0 + alm) * K + alk;
    const float* wptr = (n0 + wlm < N) ? (W + (long)(n0 + wlm) * K + wlk) : nullptr;

    float4 ar0 = *(const float4*)(aptr);
    float4 ar1 = *(const float4*)(aptr + 4);
    float4 wr = wptr ? *(const float4*)(wptr) : make_float4(0.f, 0.f, 0.f, 0.f);

    // ldmatrix lane addressing (byte offsets), loop-invariant
    unsigned sAh = (unsigned)__cvta_generic_to_shared(Ah);
    unsigned sAl = (unsigned)__cvta_generic_to_shared(Al);
    unsigned sWh = (unsigned)__cvta_generic_to_shared(Wh);
    unsigned sWl = (unsigned)__cvta_generic_to_shared(Wl);
    // A: lanes 0-15 -> rows 0-15 col 0; lanes 16-31 -> rows 0-15 col 16B
    unsigned a_off = (unsigned)((wm + (lane & 15)) * SA_W + (lane >> 4) * 4) * 4u;
    // B: lanes 0-7 rows 0-7 c0; 8-15 rows 0-7 c16; 16-23 rows 8-15 c0; 24-31 rows 8-15 c16
    unsigned b_row = (lane & 7) + ((lane >> 4) * 8);
    unsigned b_off = (unsigned)((wn + b_row) * SA_W + ((lane >> 3) & 1) * 4) * 4u;

    float acc[2][4][4];
    #pragma unroll
    for (int i = 0; i < 2; i++)
        #pragma unroll
        for (int j = 0; j < 4; j++)
            #pragma unroll
            for (int q = 0; q < 4; q++) acc[i][j][q] = 0.f;

    for (int k0 = 0; k0 < K; k0 += TBK) {
        // commit prefetched tile to smem as bf16 hi/lo planes
        {
            unsigned h, l;
            int base = alm * SA_W + (alk >> 1);
            split2(ar0.x, ar0.y, h, l); Ah[base + 0] = h; Al[base + 0] = l;
            split2(ar0.z, ar0.w, h, l); Ah[base + 1] = h; Al[base + 1] = l;
            split2(ar1.x, ar1.y, h, l); Ah[base + 2] = h; Al[base + 2] = l;
            split2(ar1.z, ar1.w, h, l); Ah[base + 3] = h; Al[base + 3] = l;
            int wbase = wlm * SA_W + (wlk >> 1);
            split2(wr.x, wr.y, h, l); Wh[wbase + 0] = h; Wl[wbase + 0] = l;
            split2(wr.z, wr.w, h, l); Wh[wbase + 1] = h; Wl[wbase + 1] = l;
        }
        __syncthreads();

        // prefetch next tile into registers (overlaps with mma below)
        if (k0 + TBK < K) {
            ar0 = *(const float4*)(aptr + k0 + TBK);
            ar1 = *(const float4*)(aptr + k0 + TBK + 4);
            if (wptr) wr = *(const float4*)(wptr + k0 + TBK);
        }

        // fragments via ldmatrix: 8 LDSM.x4 per warp per k16
        unsigned fah[2][4], fal[2][4], fbh[4][2], fbl[4][2];
        #pragma unroll
        for (int mt = 0; mt < 2; mt++) {
            unsigned off = a_off + (unsigned)(mt * 16 * SA_W) * 4u;
            ldsm_x4(fah[mt], sAh + off);
            ldsm_x4(fal[mt], sAl + off);
        }
        #pragma unroll
        for (int nt2 = 0; nt2 < 2; nt2++) {
            unsigned off = b_off + (unsigned)(nt2 * 16 * SA_W) * 4u;
            unsigned t[4];
            ldsm_x4(t, sWh + off);
            fbh[2*nt2][0] = t[0]; fbh[2*nt2][1] = t[1];
            fbh[2*nt2+1][0] = t[2]; fbh[2*nt2+1][1] = t[3];
            ldsm_x4(t, sWl + off);
            fbl[2*nt2][0] = t[0]; fbl[2*nt2][1] = t[1];
            fbl[2*nt2+1][0] = t[2]; fbl[2*nt2+1][1] = t[3];
        }
        #pragma unroll
        for (int mt = 0; mt < 2; mt++)
            #pragma unroll
            for (int nt = 0; nt < 4; nt++) {
                mma_bf16(acc[mt][nt], fah[mt], fbl[nt]);
                mma_bf16(acc[mt][nt], fal[mt], fbh[nt]);
                mma_bf16(acc[mt][nt], fah[mt], fbh[nt]);
            }
        __syncthreads();
    }

    // epilogue: c frag rows = grp / grp+8, cols = qk*2, qk*2+1
    #pragma unroll
    for (int mt = 0; mt < 2; mt++) {
        #pragma unroll
        for (int nt = 0; nt < 4; nt++) {
            int col = n0 + wn + nt * 8 + qk * 2;
            if (col >= N) continue;
            int row = m0 + wm + mt * 16 + grp;
            long off0 = (long)row * N + col;
            long off1 = (long)(row + 8) * N + col;
            float2 v0 = make_float2(acc[mt][nt][0], acc[mt][nt][1]);
            float2 v1 = make_float2(acc[mt][nt][2], acc[mt][nt][3]);
            if (res) {
                float2 r0 = *(const float2*)(res + off0);
                float2 r1 = *(const float2*)(res + off1);
                v0.x += r0.x; v0.y += r0.y;
                v1.x += r1.x; v1.y += r1.y;
            }
            *(float2*)(C + off0) = v0;
            *(float2*)(C + off1) = v1;
        }
    }
}

// ---------------- LayerNorm (in place, 256 dims, 1 token/block) ----------------
__global__ void ln_kernel(float* __restrict__ y, const float* __restrict__ w,
                          const float* __restrict__ b) {
    __shared__ float sh[8];
    long t = blockIdx.x;
    int d = threadIdx.x;
    float v = y[t * D_MODEL + d];
    float mean = block_sum256(v, sh) * (1.f / D_MODEL);
    float dv = v - mean;
    float var = block_sum256(dv * dv, sh) * (1.f / D_MODEL);
    y[t * D_MODEL + d] = dv * rsqrtf(var + EPS) * w[d] + b[d];
}

// ---------------- RMSNorm 256 -> g_h ----------------
__global__ void rms_kernel(const float* __restrict__ y, const float* __restrict__ w,
                           float* __restrict__ out) {
    __shared__ float sh[8];
    long t = blockIdx.x;
    int d = threadIdx.x;
    float v = y[t * D_MODEL + d];
    float ms = block_sum256(v * v, sh) * (1.f / D_MODEL);
    out[t * D_MODEL + d] = v * rsqrtf(ms + EPS) * w[d];
}

// ---------------- depthwise causal conv (width 4) + bias + silu ----------------
__global__ void conv_kernel(const float* __restrict__ zx, const float* __restrict__ cw,
                            const float* __restrict__ cb, float* __restrict__ out) {
    long idx = (long)blockIdx.x * blockDim.x + threadIdx.x;
    if (idx >= (long)NTOK * CONV_DIM) return;
    int ch = (int)(idx % CONV_DIM);
    long t = idx / CONV_DIM;
    int l = (int)(t & (L_ - 1));
    long brow = t - l;  // b*L_
    float acc = cb[ch];
    #pragma unroll
    for (int k = 0; k < D_CONV; k++) {
        int ls = l + k - (D_CONV - 1);
        if (ls >= 0)
            acc += zx[(brow + ls) * D_IN_PROJ + D_INNER + ch] * cw[ch * D_CONV + k];
    }
    out[t * CONV_DIM + ch] = silu_f(acc);
}

// ---------------- SSD chunked scan: one block per (b,h), 512 threads, 8 chunks ----
#define SSD_ST 65
#define SSD_SMEM_FLOATS (5 * 64 * SSD_ST + 4 * 64)
#define SSD_THREADS 512
__global__ __launch_bounds__(SSD_THREADS)
void ssd_kernel(const float* __restrict__ conv, const float* __restrict__ zx,
                const float* __restrict__ dtb, const float* __restrict__ Alog,
                const float* __restrict__ Dp, float* __restrict__ out) {
    extern __shared__ float sm[];
    float* xs = sm;                    // [64][65]  x (unscaled)
    float* Bm = xs + 64 * SSD_ST;      // [64][65]
    float* Cm = Bm + 64 * SSD_ST;      // [64][65]
    float* Mm = Cm + 64 * SSD_ST;      // [64][65]  M(l,s)*dt(s), 0 above diag
    float* S  = Mm + 64 * SSD_ST;      // [64][65]  state S[n][p]
    float* acum = S + 64 * SSD_ST;     // 64
    float* dts  = acum + 64;
    float* dd   = dts + 64;            // dt(l)*exp(acum63-acum(l))
    float* eAl  = dd + 64;             // exp(acum(l))

    int tid = threadIdx.x;
    int b = blockIdx.x >> 3, h = blockIdx.x & 7;
    float Ah = -expf(Alog[h]);
    float dtbh = dtb[h];
    float Dh = Dp[h];
    int p = tid & 63, lg = tid >> 6;   // lg in 0..7, 8 rows per group

    for (int i = tid; i < 64 * SSD_ST; i += SSD_THREADS) S[i] = 0.f;
    __syncthreads();

    for (int c = 0; c < 8; ++c) {
        long tok0 = (long)b * L_ + c * CHUNK;
        // load chunk data
        for (int i = tid; i < 4096; i += SSD_THREADS) {
            int l = i >> 6, q = i & 63;
            const float* row = conv + (tok0 + l) * CONV_DIM;
            xs[l * SSD_ST + q] = row[h * 64 + q];
            Bm[l * SSD_ST + q] = row[D_INNER + q];
            Cm[l * SSD_ST + q] = row[D_INNER + D_STATE + q];
        }
        if (tid < 64) {
            float x = zx[(tok0 + tid) * D_IN_PROJ + (D_IN_PROJ - NHEADS) + h] + dtbh;
            float dt = (x > 20.f) ? x : log1pf(expf(x));
            dts[tid] = dt;
            acum[tid] = Ah * dt;
        }
        __syncthreads();
        // warp-parallel inclusive scan of acum[0..63] (warp 0, 2 elems/lane)
        if (tid < 32) {
            float v0 = acum[2 * tid], v1 = acum[2 * tid + 1];
            float s = v0 + v1;
            #pragma unroll
            for (int o = 1; o < 32; o <<= 1) {
                float t = __shfl_up_sync(0xffffffffu, s, o);
                if (tid >= o) s += t;
            }
            acum[2 * tid] = s - v1;
            acum[2 * tid + 1] = s;
        }
        __syncthreads();
        if (tid < 64) {
            eAl[tid] = expf(acum[tid]);
            dd[tid] = dts[tid] * expf(acum[63] - acum[tid]);
        }
        __syncthreads();
        // M(l,s) = exp(acum_l - acum_s) * (C_l . B_s) * dt_s  (s<=l), else 0
        for (int i = tid; i < 4096; i += SSD_THREADS) {
            int l = i >> 6, s = i & 63;
            float v = 0.f;
            if (s <= l) {
                float g = 0.f;
                #pragma unroll 8
                for (int n = 0; n < 64; n++) g += Cm[l * SSD_ST + n] * Bm[s * SSD_ST + n];
                v = g * expf(acum[l] - acum[s]) * dts[s];
            }
            Mm[l * SSD_ST + s] = v;
        }
        __syncthreads();
        // Y(l,p) = sum_s M(l,s)*x(s,p) + exp(acum_l)*sum_n C(l,n)*S(n,p) + Dh*x(l,p)
        #pragma unroll
        for (int i = 0; i < 8; i++) {
            int l = lg * 8 + i;
            float a = Dh * xs[l * SSD_ST + p];
            #pragma unroll 8
            for (int s = 0; s < 64; s++) a += Mm[l * SSD_ST + s] * xs[s * SSD_ST + p];
            float off = 0.f;
            #pragma unroll 8
            for (int n = 0; n < 64; n++) off += Cm[l * SSD_ST + n] * S[n * SSD_ST + p];
            out[(tok0 + l) * D_INNER + h * 64 + p] = a + eAl[l] * off;
        }
        __syncthreads();
        // S(n,p) <- exp(acum63)*S(n,p) + sum_l B(l,n)*dd(l)*x(l,p)
        float eTot = eAl[63];
        #pragma unroll
        for (int i = 0; i < 8; i++) {
            int n = lg * 8 + i;
            float s = S[n * SSD_ST + p] * eTot;
            #pragma unroll 8
            for (int l = 0; l < 64; l++)
                s += (Bm[l * SSD_ST + n] * dd[l]) * xs[l * SSD_ST + p];
            S[n * SSD_ST + p] = s;
        }
        __syncthreads();
    }
}

// ---------------- gated RMSNorm: rmsnorm(y*silu(z)) * gw ----------------
__global__ void gated_kernel(const float* __restrict__ yin, const float* __restrict__ zx,
                             const float* __restrict__ gw, float* __restrict__ out) {
    __shared__ float sh[8];
    long t = blockIdx.x;
    int d = threadIdx.x;
    float z0 = zx[t * D_IN_PROJ + d];
    float z1 = zx[t * D_IN_PROJ + d + 256];
    float u0 = yin[t * D_INNER + d] * silu_f(z0);
    float u1 = yin[t * D_INNER + d + 256] * silu_f(z1);
    float ms = block_sum256(u0 * u0 + u1 * u1, sh) * (1.f / D_INNER);
    float r = rsqrtf(ms + EPS);
    out[t * D_INNER + d] = u0 * r * gw[d];
    out[t * D_INNER + d + 256] = u1 * r * gw[d + 256];
}

// ---------------- final: rmsnorm(last token) -> elu -> @ out_W^T ----------------
__global__ void final_kernel(const float* __restrict__ y, const float* __restrict__ nw,
                             const float* __restrict__ ow, float* __restrict__ out) {
    __shared__ float sh[8];
    __shared__ float u[256];
    int b = blockIdx.x;
    int d = threadIdx.x;
    float v = y[((long)b * L_ + (L_ - 1)) * D_MODEL + d];
    float ms = block_sum256(v * v, sh) * (1.f / D_MODEL);
    float x = v * rsqrtf(ms + EPS) * nw[d];
    u[d] = (x > 0.f) ? x : (expf(x) - 1.f);
    __syncthreads();
    if (d < COUT_) {
        float a = 0.f;
        for (int k = 0; k < D_MODEL; k++) a += u[k] * ow[d * D_MODEL + k];
        out[b * COUT_ + d] = a;
    }
}

// ---------------- host orchestration ----------------
extern "C" void kernel_launch(void* const* d_in, const int* in_sizes, int n_in,
                              void* d_out, int out_size) {
    const float* obs     = (const float*)d_in[0];
    const float* in_W    = (const float*)d_in[1];
    const float* ln1_w   = (const float*)d_in[2];
    const float* ln1_b   = (const float*)d_in[3];
    const float* rms_w   = (const float*)d_in[4];
    const float* inproj  = (const float*)d_in[5];
    const float* conv_w  = (const float*)d_in[6];
    const float* conv_b  = (const float*)d_in[7];
    const float* dt_bias = (const float*)d_in[8];
    const float* A_log   = (const float*)d_in[9];
    const float* Dp      = (const float*)d_in[10];
    const float* gnorm   = (const float*)d_in[11];
    const float* outproj = (const float*)d_in[12];
    const float* normf   = (const float*)d_in[13];
    const float* out_W   = (const float*)d_in[14];
    float* out = (float*)d_out;

    float *y, *h, *zx, *conv, *ssd, *gate;
    cudaGetSymbolAddress((void**)&y, g_y);
    cudaGetSymbolAddress((void**)&h, g_h);
    cudaGetSymbolAddress((void**)&zx, g_zx);
    cudaGetSymbolAddress((void**)&conv, g_conv);
    cudaGetSymbolAddress((void**)&ssd, g_ssd);
    cudaGetSymbolAddress((void**)&gate, g_gate);

    size_t ssd_smem = SSD_SMEM_FLOATS * sizeof(float);
    cudaFuncSetAttribute(ssd_kernel, cudaFuncAttributeMaxDynamicSharedMemorySize,
                         (int)ssd_smem);

    // 1) y = obs @ in_W^T  (M=65536, N=256, K=48), then LayerNorm in place
    {
        dim3 grid((D_MODEL + TBN - 1) / TBN, NTOK / TBM);
        gemm_bf3<<<grid, 256>>>(obs, in_W, nullptr, y, NTOK, D_MODEL, CIN);
        ln_kernel<<<NTOK, 256>>>(y, ln1_w, ln1_b);
    }

    for (int i = 0; i < N_LAYER; i++) {
        const float* Wi = inproj + (long)i * D_IN_PROJ * D_MODEL;
        const float* Wo = outproj + (long)i * D_MODEL * D_INNER;
        const float* cwi = conv_w + (long)i * CONV_DIM * D_CONV;
        const float* cbi = conv_b + (long)i * CONV_DIM;
        const float* dtbi = dt_bias + i * NHEADS;
        const float* Ali = A_log + i * NHEADS;
        const float* Dpi = Dp + i * NHEADS;
        const float* gwi = gnorm + (long)i * D_INNER;
        const float* rwi = rms_w + (long)i * D_MODEL;

        // a) h = rmsnorm(y) * rms_w
        rms_kernel<<<NTOK, 256>>>(y, rwi, h);
        // b) zx = h @ Wi^T (N=1160, K=256)
        {
            dim3 grid((D_IN_PROJ + TBN - 1) / TBN, NTOK / TBM);
            gemm_bf3<<<grid, 256>>>(h, Wi, nullptr, zx, NTOK, D_IN_PROJ, D_MODEL);
        }
        // c) conv + silu
        {
            long total = (long)NTOK * CONV_DIM;
            int blocks = (int)((total + 255) / 256);
            conv_kernel<<<blocks, 256>>>(zx, cwi, cbi, conv);
        }
        // d) SSD scan
        ssd_kernel<<<B_ * NHEADS, SSD_THREADS, ssd_smem>>>(conv, zx, dtbi, Ali, Dpi, ssd);
        // e) gated rmsnorm
        gated_kernel<<<NTOK, 256>>>(ssd, zx, gwi, gate);
        // f) y = y + gate @ Wo^T (N=256, K=512)
        {
            dim3 grid((D_MODEL + TBN - 1) / TBN, NTOK / TBM);
            gemm_bf3<<<grid, 256>>>(gate, Wo, y, y, NTOK, D_MODEL, D_INNER);
        }
    }

    // final head
    final_kernel<<<B_, 256>>>(y, normf, out_W, out);
}

// round 7
// speedup vs baseline: 1.3492x; 1.1301x over previous
#include <cuda_runtime.h>
#include <cuda_bf16.h>
#include <math.h>

#define B_ 128
#define L_ 512
#define CIN 48
#define COUT_ 12
#define D_MODEL 256
#define N_LAYER 4
#define D_STATE 64
#define D_CONV 4
#define HEADDIM 64
#define CHUNK 64
#define D_INNER 512
#define NHEADS 8
#define CONV_DIM 640
#define D_IN_PROJ 1160
#define NTOK (B_ * L_)
#define EPS 1e-5f

// ---------------- scratch (static device globals; no runtime alloc) ----------------
__device__ float g_y[NTOK * D_MODEL];        // residual stream
__device__ float g_h[NTOK * D_MODEL];        // rmsnorm output
__device__ float g_zx[NTOK * D_IN_PROJ];     // in_proj output (z | xBC | dt)
__device__ float g_conv[NTOK * CONV_DIM];    // conv+silu output
__device__ float g_ssd[NTOK * D_INNER];      // ssd output (+D term)
__device__ float g_gate[NTOK * D_INNER];     // gated rmsnorm output

// ---------------- block reduction (256 threads) ----------------
__device__ __forceinline__ float block_sum256(float v, float* sh) {
    #pragma unroll
    for (int o = 16; o; o >>= 1) v += __shfl_xor_sync(0xffffffffu, v, o);
    if ((threadIdx.x & 31) == 0) sh[threadIdx.x >> 5] = v;
    __syncthreads();
    if (threadIdx.x < 8) {
        v = sh[threadIdx.x];
        #pragma unroll
        for (int o = 4; o; o >>= 1) v += __shfl_xor_sync(0xffu, v, o);
        if (threadIdx.x == 0) sh[0] = v;
    }
    __syncthreads();
    float r = sh[0];
    __syncthreads();
    return r;
}

__device__ __forceinline__ float silu_f(float x) { return x / (1.f + expf(-x)); }

// ---------------- bf16 split helpers ----------------
__device__ __forceinline__ void split2(float a, float b, unsigned& hi, unsigned& lo) {
    __nv_bfloat16 ha = __float2bfloat16_rn(a);
    __nv_bfloat16 hb = __float2bfloat16_rn(b);
    __nv_bfloat162 h; h.x = ha; h.y = hb;
    __nv_bfloat162 l = __floats2bfloat162_rn(a - __bfloat162float(ha),
                                             b - __bfloat162float(hb));
    hi = *reinterpret_cast<unsigned*>(&h);
    lo = *reinterpret_cast<unsigned*>(&l);
}
__device__ __forceinline__ void mma_bf16(float (&d)[4], const unsigned (&a)[4],
                                         const unsigned (&b)[2]) {
    asm volatile(
        "mma.sync.aligned.m16n8k16.row.col.f32.bf16.bf16.f32 "
        "{%0,%1,%2,%3}, {%4,%5,%6,%7}, {%8,%9}, {%0,%1,%2,%3};\n"
        : "+f"(d[0]), "+f"(d[1]), "+f"(d[2]), "+f"(d[3])
        : "r"(a[0]), "r"(a[1]), "r"(a[2]), "r"(a[3]), "r"(b[0]), "r"(b[1]));
}
__device__ __forceinline__ void ldsm_x4(unsigned (&r)[4], unsigned addr) {
    asm volatile("ldmatrix.sync.aligned.m8n8.x4.shared.b16 {%0,%1,%2,%3}, [%4];"
        : "=r"(r[0]), "=r"(r[1]), "=r"(r[2]), "=r"(r[3]) : "r"(addr));
}

// ---------------- tensor-core GEMM: C[M,N] = A[M,K] @ W[N,K]^T (+res) ----------------
#define TBM 128
#define TBN 64
#define TBK 16
#define SA_H (TBK + 8)
#define SA_W (SA_H / 2)
__global__ __launch_bounds__(256) void gemm_bf3(
        const float* __restrict__ A, const float* __restrict__ W,
        const float* __restrict__ res, float* __restrict__ C,
        int M, int N, int K) {
    __shared__ unsigned Ah[TBM * SA_W], Al[TBM * SA_W];
    __shared__ unsigned Wh[TBN * SA_W], Wl[TBN * SA_W];
    int tid = threadIdx.x;
    int lane = tid & 31, wid = tid >> 5;
    int wm = (wid >> 1) * 32;
    int wn = (wid & 1) * 32;
    int grp = lane >> 2, qk = lane & 3;
    int m0 = blockIdx.y * TBM, n0 = blockIdx.x * TBN;

    int alm = tid >> 1;
    int alk = (tid & 1) * 8;
    int wlm = tid >> 2;
    int wlk = (tid & 3) * 4;

    const float* aptr = A + (long)(m0 + alm) * K + alk;
    const float* wptr = (n0 + wlm < N) ? (W + (long)(n0 + wlm) * K + wlk) : nullptr;

    float4 ar0 = *(const float4*)(aptr);
    float4 ar1 = *(const float4*)(aptr + 4);
    float4 wr = wptr ? *(const float4*)(wptr) : make_float4(0.f, 0.f, 0.f, 0.f);

    unsigned sAh = (unsigned)__cvta_generic_to_shared(Ah);
    unsigned sAl = (unsigned)__cvta_generic_to_shared(Al);
    unsigned sWh = (unsigned)__cvta_generic_to_shared(Wh);
    unsigned sWl = (unsigned)__cvta_generic_to_shared(Wl);
    unsigned a_off = (unsigned)((wm + (lane & 15)) * SA_W + (lane >> 4) * 4) * 4u;
    unsigned b_row = (lane & 7) + ((lane >> 4) * 8);
    unsigned b_off = (unsigned)((wn + b_row) * SA_W + ((lane >> 3) & 1) * 4) * 4u;

    float acc[2][4][4];
    #pragma unroll
    for (int i = 0; i < 2; i++)
        #pragma unroll
        for (int j = 0; j < 4; j++)
            #pragma unroll
            for (int q = 0; q < 4; q++) acc[i][j][q] = 0.f;

    for (int k0 = 0; k0 < K; k0 += TBK) {
        {
            unsigned h, l;
            int base = alm * SA_W + (alk >> 1);
            split2(ar0.x, ar0.y, h, l); Ah[base + 0] = h; Al[base + 0] = l;
            split2(ar0.z, ar0.w, h, l); Ah[base + 1] = h; Al[base + 1] = l;
            split2(ar1.x, ar1.y, h, l); Ah[base + 2] = h; Al[base + 2] = l;
            split2(ar1.z, ar1.w, h, l); Ah[base + 3] = h; Al[base + 3] = l;
            int wbase = wlm * SA_W + (wlk >> 1);
            split2(wr.x, wr.y, h, l); Wh[wbase + 0] = h; Wl[wbase + 0] = l;
            split2(wr.z, wr.w, h, l); Wh[wbase + 1] = h; Wl[wbase + 1] = l;
        }
        __syncthreads();

        if (k0 + TBK < K) {
            ar0 = *(const float4*)(aptr + k0 + TBK);
            ar1 = *(const float4*)(aptr + k0 + TBK + 4);
            if (wptr) wr = *(const float4*)(wptr + k0 + TBK);
        }

        unsigned fah[2][4], fal[2][4], fbh[4][2], fbl[4][2];
        #pragma unroll
        for (int mt = 0; mt < 2; mt++) {
            unsigned off = a_off + (unsigned)(mt * 16 * SA_W) * 4u;
            ldsm_x4(fah[mt], sAh + off);
            ldsm_x4(fal[mt], sAl + off);
        }
        #pragma unroll
        for (int nt2 = 0; nt2 < 2; nt2++) {
            unsigned off = b_off + (unsigned)(nt2 * 16 * SA_W) * 4u;
            unsigned t[4];
            ldsm_x4(t, sWh + off);
            fbh[2*nt2][0] = t[0]; fbh[2*nt2][1] = t[1];
            fbh[2*nt2+1][0] = t[2]; fbh[2*nt2+1][1] = t[3];
            ldsm_x4(t, sWl + off);
            fbl[2*nt2][0] = t[0]; fbl[2*nt2][1] = t[1];
            fbl[2*nt2+1][0] = t[2]; fbl[2*nt2+1][1] = t[3];
        }
        #pragma unroll
        for (int mt = 0; mt < 2; mt++)
            #pragma unroll
            for (int nt = 0; nt < 4; nt++) {
                mma_bf16(acc[mt][nt], fah[mt], fbl[nt]);
                mma_bf16(acc[mt][nt], fal[mt], fbh[nt]);
                mma_bf16(acc[mt][nt], fah[mt], fbh[nt]);
            }
        __syncthreads();
    }

    #pragma unroll
    for (int mt = 0; mt < 2; mt++) {
        #pragma unroll
        for (int nt = 0; nt < 4; nt++) {
            int col = n0 + wn + nt * 8 + qk * 2;
            if (col >= N) continue;
            int row = m0 + wm + mt * 16 + grp;
            long off0 = (long)row * N + col;
            long off1 = (long)(row + 8) * N + col;
            float2 v0 = make_float2(acc[mt][nt][0], acc[mt][nt][1]);
            float2 v1 = make_float2(acc[mt][nt][2], acc[mt][nt][3]);
            if (res) {
                float2 r0 = *(const float2*)(res + off0);
                float2 r1 = *(const float2*)(res + off1);
                v0.x += r0.x; v0.y += r0.y;
                v1.x += r1.x; v1.y += r1.y;
            }
            *(float2*)(C + off0) = v0;
            *(float2*)(C + off1) = v1;
        }
    }
}

// ---------------- LayerNorm (in place, 256 dims, 1 token/block) ----------------
__global__ void ln_kernel(float* __restrict__ y, const float* __restrict__ w,
                          const float* __restrict__ b) {
    __shared__ float sh[8];
    long t = blockIdx.x;
    int d = threadIdx.x;
    float v = y[t * D_MODEL + d];
    float mean = block_sum256(v, sh) * (1.f / D_MODEL);
    float dv = v - mean;
    float var = block_sum256(dv * dv, sh) * (1.f / D_MODEL);
    y[t * D_MODEL + d] = dv * rsqrtf(var + EPS) * w[d] + b[d];
}

// ---------------- RMSNorm 256 -> g_h ----------------
__global__ void rms_kernel(const float* __restrict__ y, const float* __restrict__ w,
                           float* __restrict__ out) {
    __shared__ float sh[8];
    long t = blockIdx.x;
    int d = threadIdx.x;
    float v = y[t * D_MODEL + d];
    float ms = block_sum256(v * v, sh) * (1.f / D_MODEL);
    out[t * D_MODEL + d] = v * rsqrtf(ms + EPS) * w[d];
}

// ---------------- depthwise causal conv (width 4) + bias + silu ----------------
__global__ void conv_kernel(const float* __restrict__ zx, const float* __restrict__ cw,
                            const float* __restrict__ cb, float* __restrict__ out) {
    long idx = (long)blockIdx.x * blockDim.x + threadIdx.x;
    if (idx >= (long)NTOK * CONV_DIM) return;
    int ch = (int)(idx % CONV_DIM);
    long t = idx / CONV_DIM;
    int l = (int)(t & (L_ - 1));
    long brow = t - l;  // b*L_
    float acc = cb[ch];
    #pragma unroll
    for (int k = 0; k < D_CONV; k++) {
        int ls = l + k - (D_CONV - 1);
        if (ls >= 0)
            acc += zx[(brow + ls) * D_IN_PROJ + D_INNER + ch] * cw[ch * D_CONV + k];
    }
    out[t * CONV_DIM + ch] = silu_f(acc);
}

// ---------------- SSD chunked scan: register-tiled + float4, 512 thr/block --------
// one block per (b,h); sequential over 8 chunks of 64 tokens.
#define SSD_ST 68                     // padded stride (mult of 4 for float4)
#define SSD_SMEM_FLOATS (6 * 64 * SSD_ST + 4 * 64)
#define SSD_THREADS 512
__global__ __launch_bounds__(SSD_THREADS)
void ssd_kernel(const float* __restrict__ conv, const float* __restrict__ zx,
                const float* __restrict__ dtb, const float* __restrict__ Alog,
                const float* __restrict__ Dp, float* __restrict__ out) {
    extern __shared__ float sm[];
    float* xs  = sm;                   // [64][68]  x
    float* Bm  = xs  + 64 * SSD_ST;    // [64][68]  B
    float* Cm  = Bm  + 64 * SSD_ST;    // [64][68]  C
    float* BmT = Cm  + 64 * SSD_ST;    // [64][68]  B transposed: BmT[n][s]=B[s][n]
    float* Mm  = BmT + 64 * SSD_ST;    // [64][68]  masked decay matrix
    float* S   = Mm  + 64 * SSD_ST;    // [64][68]  state S[n][p]
    float* acum = S + 64 * SSD_ST;     // 64
    float* dts  = acum + 64;
    float* dd   = dts + 64;
    float* eAl  = dd + 64;

    int tid = threadIdx.x;
    int b = blockIdx.x >> 3, h = blockIdx.x & 7;
    float Ah = -expf(Alog[h]);
    float dtbh = dtb[h];
    float Dh = Dp[h];

    // task mappings
    int pg = tid & 15;                 // p group: p = pg*4 .. pg*4+3
    int rr = tid >> 4;                 // 0..31 (row for Y / state loops)
    int msg = tid & 7;                 // M-loop: s0 = msg*8
    int ml = tid >> 3;                 // M-loop: l = 0..63

    for (int i = tid; i < 64 * SSD_ST; i += SSD_THREADS) S[i] = 0.f;
    __syncthreads();

    for (int c = 0; c < 8; ++c) {
        long tok0 = (long)b * L_ + c * CHUNK;
        // ---- load chunk ----
        for (int i = tid; i < 4096; i += SSD_THREADS) {
            int l = i >> 6, q = i & 63;
            const float* row = conv + (tok0 + l) * CONV_DIM;
            xs[l * SSD_ST + q] = row[h * 64 + q];
            float bv = row[D_INNER + q];
            Bm[l * SSD_ST + q] = bv;
            BmT[q * SSD_ST + l] = bv;
            Cm[l * SSD_ST + q] = row[D_INNER + D_STATE + q];
        }
        if (tid < 64) {
            float x = zx[(tok0 + tid) * D_IN_PROJ + (D_IN_PROJ - NHEADS) + h] + dtbh;
            float dt = (x > 20.f) ? x : log1pf(expf(x));
            dts[tid] = dt;
            acum[tid] = Ah * dt;
        }
        __syncthreads();
        // ---- inclusive scan of acum (warp 0) ----
        if (tid < 32) {
            float v0 = acum[2 * tid], v1 = acum[2 * tid + 1];
            float s = v0 + v1;
            #pragma unroll
            for (int o = 1; o < 32; o <<= 1) {
                float t = __shfl_up_sync(0xffffffffu, s, o);
                if (tid >= o) s += t;
            }
            acum[2 * tid] = s - v1;
            acum[2 * tid + 1] = s;
        }
        __syncthreads();
        if (tid < 64) {
            eAl[tid] = expf(acum[tid]);
            dd[tid] = dts[tid] * expf(acum[63] - acum[tid]);
        }
        __syncthreads();
        // ---- M(l,s): each thread does 1 l x 8 s  (dot via BmT float4) ----
        {
            float a8[8];
            #pragma unroll
            for (int j = 0; j < 8; j++) a8[j] = 0.f;
            int s0 = msg * 8;
            #pragma unroll 4
            for (int n = 0; n < 64; n++) {
                float cv = Cm[ml * SSD_ST + n];
                float4 b0 = *(const float4*)(BmT + n * SSD_ST + s0);
                float4 b1 = *(const float4*)(BmT + n * SSD_ST + s0 + 4);
                a8[0] += cv * b0.x; a8[1] += cv * b0.y;
                a8[2] += cv * b0.z; a8[3] += cv * b0.w;
                a8[4] += cv * b1.x; a8[5] += cv * b1.y;
                a8[6] += cv * b1.z; a8[7] += cv * b1.w;
            }
            float al = acum[ml];
            #pragma unroll
            for (int j = 0; j < 8; j++) {
                int s = s0 + j;
                float v = (s <= ml) ? a8[j] * expf(al - acum[s]) * dts[s] : 0.f;
                Mm[ml * SSD_ST + s] = v;
            }
        }
        __syncthreads();
        // ---- Y(l, p0..p0+3) = sum_s M*x + eAl*sum_n C*S + Dh*x ----
        #pragma unroll
        for (int it = 0; it < 2; it++) {
            int l = rr + it * 32;
            int p4 = pg * 4;
            float4 xv = *(const float4*)(xs + l * SSD_ST + p4);
            float4 a = make_float4(Dh * xv.x, Dh * xv.y, Dh * xv.z, Dh * xv.w);
            #pragma unroll 8
            for (int s = 0; s < 64; s++) {
                float m = Mm[l * SSD_ST + s];
                float4 x4 = *(const float4*)(xs + s * SSD_ST + p4);
                a.x += m * x4.x; a.y += m * x4.y;
                a.z += m * x4.z; a.w += m * x4.w;
            }
            float4 off = make_float4(0.f, 0.f, 0.f, 0.f);
            #pragma unroll 8
            for (int n = 0; n < 64; n++) {
                float cv = Cm[l * SSD_ST + n];
                float4 s4 = *(const float4*)(S + n * SSD_ST + p4);
                off.x += cv * s4.x; off.y += cv * s4.y;
                off.z += cv * s4.z; off.w += cv * s4.w;
            }
            float e = eAl[l];
            float4 r = make_float4(a.x + e * off.x, a.y + e * off.y,
                                   a.z + e * off.z, a.w + e * off.w);
            *(float4*)(out + (tok0 + l) * D_INNER + h * 64 + p4) = r;
        }
        __syncthreads();
        // ---- S(n, p0..p0+3) <- eTot*S + sum_l B(l,n)*dd(l)*x(l,p) ----
        {
            float eTot = eAl[63];
            #pragma unroll
            for (int it = 0; it < 2; it++) {
                int n = rr + it * 32;
                int p4 = pg * 4;
                float4 s4 = *(const float4*)(S + n * SSD_ST + p4);
                float4 a = make_float4(s4.x * eTot, s4.y * eTot,
                                       s4.z * eTot, s4.w * eTot);
                #pragma unroll 8
                for (int l = 0; l < 64; l++) {
                    float bd = Bm[l * SSD_ST + n] * dd[l];
                    float4 x4 = *(const float4*)(xs + l * SSD_ST + p4);
                    a.x += bd * x4.x; a.y += bd * x4.y;
                    a.z += bd * x4.z; a.w += bd * x4.w;
                }
                *(float4*)(S + n * SSD_ST + p4) = a;
            }
        }
        __syncthreads();
    }
}

// ---------------- gated RMSNorm: rmsnorm(y*silu(z)) * gw ----------------
__global__ void gated_kernel(const float* __restrict__ yin, const float* __restrict__ zx,
                             const float* __restrict__ gw, float* __restrict__ out) {
    __shared__ float sh[8];
    long t = blockIdx.x;
    int d = threadIdx.x;
    float z0 = zx[t * D_IN_PROJ + d];
    float z1 = zx[t * D_IN_PROJ + d + 256];
    float u0 = yin[t * D_INNER + d] * silu_f(z0);
    float u1 = yin[t * D_INNER + d + 256] * silu_f(z1);
    float ms = block_sum256(u0 * u0 + u1 * u1, sh) * (1.f / D_INNER);
    float r = rsqrtf(ms + EPS);
    out[t * D_INNER + d] = u0 * r * gw[d];
    out[t * D_INNER + d + 256] = u1 * r * gw[d + 256];
}

// ---------------- final: rmsnorm(last token) -> elu -> @ out_W^T ----------------
__global__ void final_kernel(const float* __restrict__ y, const float* __restrict__ nw,
                             const float* __restrict__ ow, float* __restrict__ out) {
    __shared__ float sh[8];
    __shared__ float u[256];
    int b = blockIdx.x;
    int d = threadIdx.x;
    float v = y[((long)b * L_ + (L_ - 1)) * D_MODEL + d];
    float ms = block_sum256(v * v, sh) * (1.f / D_MODEL);
    float x = v * rsqrtf(ms + EPS) * nw[d];
    u[d] = (x > 0.f) ? x : (expf(x) - 1.f);
    __syncthreads();
    if (d < COUT_) {
        float a = 0.f;
        for (int k = 0; k < D_MODEL; k++) a += u[k] * ow[d * D_MODEL + k];
        out[b * COUT_ + d] = a;
    }
}

// ---------------- host orchestration ----------------
extern "C" void kernel_launch(void* const* d_in, const int* in_sizes, int n_in,
                              void* d_out, int out_size) {
    const float* obs     = (const float*)d_in[0];
    const float* in_W    = (const float*)d_in[1];
    const float* ln1_w   = (const float*)d_in[2];
    const float* ln1_b   = (const float*)d_in[3];
    const float* rms_w   = (const float*)d_in[4];
    const float* inproj  = (const float*)d_in[5];
    const float* conv_w  = (const float*)d_in[6];
    const float* conv_b  = (const float*)d_in[7];
    const float* dt_bias = (const float*)d_in[8];
    const float* A_log   = (const float*)d_in[9];
    const float* Dp      = (const float*)d_in[10];
    const float* gnorm   = (const float*)d_in[11];
    const float* outproj = (const float*)d_in[12];
    const float* normf   = (const float*)d_in[13];
    const float* out_W   = (const float*)d_in[14];
    float* out = (float*)d_out;

    float *y, *h, *zx, *conv, *ssd, *gate;
    cudaGetSymbolAddress((void**)&y, g_y);
    cudaGetSymbolAddress((void**)&h, g_h);
    cudaGetSymbolAddress((void**)&zx, g_zx);
    cudaGetSymbolAddress((void**)&conv, g_conv);
    cudaGetSymbolAddress((void**)&ssd, g_ssd);
    cudaGetSymbolAddress((void**)&gate, g_gate);

    size_t ssd_smem = SSD_SMEM_FLOATS * sizeof(float);
    cudaFuncSetAttribute(ssd_kernel, cudaFuncAttributeMaxDynamicSharedMemorySize,
                         (int)ssd_smem);

    // 1) y = obs @ in_W^T  (M=65536, N=256, K=48), then LayerNorm in place
    {
        dim3 grid((D_MODEL + TBN - 1) / TBN, NTOK / TBM);
        gemm_bf3<<<grid, 256>>>(obs, in_W, nullptr, y, NTOK, D_MODEL, CIN);
        ln_kernel<<<NTOK, 256>>>(y, ln1_w, ln1_b);
    }

    for (int i = 0; i < N_LAYER; i++) {
        const float* Wi = inproj + (long)i * D_IN_PROJ * D_MODEL;
        const float* Wo = outproj + (long)i * D_MODEL * D_INNER;
        const float* cwi = conv_w + (long)i * CONV_DIM * D_CONV;
        const float* cbi = conv_b + (long)i * CONV_DIM;
        const float* dtbi = dt_bias + i * NHEADS;
        const float* Ali = A_log + i * NHEADS;
        const float* Dpi = Dp + i * NHEADS;
        const float* gwi = gnorm + (long)i * D_INNER;
        const float* rwi = rms_w + (long)i * D_MODEL;

        // a) h = rmsnorm(y) * rms_w
        rms_kernel<<<NTOK, 256>>>(y, rwi, h);
        // b) zx = h @ Wi^T (N=1160, K=256)
        {
            dim3 grid((D_IN_PROJ + TBN - 1) / TBN, NTOK / TBM);
            gemm_bf3<<<grid, 256>>>(h, Wi, nullptr, zx, NTOK, D_IN_PROJ, D_MODEL);
        }
        // c) conv + silu
        {
            long total = (long)NTOK * CONV_DIM;
            int blocks = (int)((total + 255) / 256);
            conv_kernel<<<blocks, 256>>>(zx, cwi, cbi, conv);
        }
        // d) SSD scan
        ssd_kernel<<<B_ * NHEADS, SSD_THREADS, ssd_smem>>>(conv, zx, dtbi, Ali, Dpi, ssd);
        // e) gated rmsnorm
        gated_kernel<<<NTOK, 256>>>(ssd, zx, gwi, gate);
        // f) y = y + gate @ Wo^T (N=256, K=512)
        {
            dim3 grid((D_MODEL + TBN - 1) / TBN, NTOK / TBM);
            gemm_bf3<<<grid, 256>>>(gate, Wo, y, y, NTOK, D_MODEL, D_INNER);
        }
    }

    // final head
    final_kernel<<<B_, 256>>>(y, normf, out_W, out);
}

// round 10
// speedup vs baseline: 1.3845x; 1.0262x over previous
#include <cuda_runtime.h>
#include <cuda_bf16.h>
#include <math.h>

#define B_ 128
#define L_ 512
#define CIN 48
#define COUT_ 12
#define D_MODEL 256
#define N_LAYER 4
#define D_STATE 64
#define D_CONV 4
#define HEADDIM 64
#define CHUNK 64
#define D_INNER 512
#define NHEADS 8
#define CONV_DIM 640
#define D_IN_PROJ 1160
#define NTOK (B_ * L_)
#define EPS 1e-5f

// ---------------- scratch (static device globals; no runtime alloc) ----------------
__device__ float g_y[NTOK * D_MODEL];
__device__ float g_h[NTOK * D_MODEL];
__device__ float g_zx[NTOK * D_IN_PROJ];
__device__ float g_conv[NTOK * CONV_DIM];
__device__ float g_ssd[NTOK * D_INNER];
__device__ float g_gate[NTOK * D_INNER];

__device__ __forceinline__ float silu_f(float x) { return x / (1.f + expf(-x)); }

__device__ __forceinline__ float warp_sum(float v) {
    #pragma unroll
    for (int o = 16; o; o >>= 1) v += __shfl_xor_sync(0xffffffffu, v, o);
    return v;
}

// ---------------- bf16 split helpers ----------------
__device__ __forceinline__ void split2(float a, float b, unsigned& hi, unsigned& lo) {
    __nv_bfloat16 ha = __float2bfloat16_rn(a);
    __nv_bfloat16 hb = __float2bfloat16_rn(b);
    __nv_bfloat162 h; h.x = ha; h.y = hb;
    __nv_bfloat162 l = __floats2bfloat162_rn(a - __bfloat162float(ha),
                                             b - __bfloat162float(hb));
    hi = *reinterpret_cast<unsigned*>(&h);
    lo = *reinterpret_cast<unsigned*>(&l);
}
__device__ __forceinline__ void mma_bf16(float (&d)[4], const unsigned (&a)[4],
                                         const unsigned (&b)[2]) {
    asm volatile(
        "mma.sync.aligned.m16n8k16.row.col.f32.bf16.bf16.f32 "
        "{%0,%1,%2,%3}, {%4,%5,%6,%7}, {%8,%9}, {%0,%1,%2,%3};\n"
        : "+f"(d[0]), "+f"(d[1]), "+f"(d[2]), "+f"(d[3])
        : "r"(a[0]), "r"(a[1]), "r"(a[2]), "r"(a[3]), "r"(b[0]), "r"(b[1]));
}
__device__ __forceinline__ void ldsm_x4(unsigned (&r)[4], unsigned addr) {
    asm volatile("ldmatrix.sync.aligned.m8n8.x4.shared.b16 {%0,%1,%2,%3}, [%4];"
        : "=r"(r[0]), "=r"(r[1]), "=r"(r[2]), "=r"(r[3]) : "r"(addr));
}

// ---------------- tensor-core GEMM: C[M,N] = A[M,K] @ W[N,K]^T (+res) ----------------
// bf16 split-3 (hi/lo), single-buffered smem (R7 known-good version).
// Block tile 128x64x16, 8 warps (4x2), warp tile 32x32.
#define TBM 128
#define TBN 64
#define TBK 16
#define SA_H (TBK + 8)
#define SA_W (SA_H / 2)
__global__ __launch_bounds__(256) void gemm_bf3(
        const float* __restrict__ A, const float* __restrict__ W,
        const float* __restrict__ res, float* __restrict__ C,
        int M, int N, int K) {
    __shared__ unsigned Ah[TBM * SA_W], Al[TBM * SA_W];
    __shared__ unsigned Wh[TBN * SA_W], Wl[TBN * SA_W];
    int tid = threadIdx.x;
    int lane = tid & 31, wid = tid >> 5;
    int wm = (wid >> 1) * 32;
    int wn = (wid & 1) * 32;
    int grp = lane >> 2, qk = lane & 3;
    int m0 = blockIdx.y * TBM, n0 = blockIdx.x * TBN;

    int alm = tid >> 1;
    int alk = (tid & 1) * 8;
    int wlm = tid >> 2;
    int wlk = (tid & 3) * 4;

    const float* aptr = A + (long)(m0 + alm) * K + alk;
    const float* wptr = (n0 + wlm < N) ? (W + (long)(n0 + wlm) * K + wlk) : nullptr;

    float4 ar0 = *(const float4*)(aptr);
    float4 ar1 = *(const float4*)(aptr + 4);
    float4 wr = wptr ? *(const float4*)(wptr) : make_float4(0.f, 0.f, 0.f, 0.f);

    unsigned sAh = (unsigned)__cvta_generic_to_shared(Ah);
    unsigned sAl = (unsigned)__cvta_generic_to_shared(Al);
    unsigned sWh = (unsigned)__cvta_generic_to_shared(Wh);
    unsigned sWl = (unsigned)__cvta_generic_to_shared(Wl);
    unsigned a_off = (unsigned)((wm + (lane & 15)) * SA_W + (lane >> 4) * 4) * 4u;
    unsigned b_row = (lane & 7) + ((lane >> 4) * 8);
    unsigned b_off = (unsigned)((wn + b_row) * SA_W + ((lane >> 3) & 1) * 4) * 4u;

    float acc[2][4][4];
    #pragma unroll
    for (int i = 0; i < 2; i++)
        #pragma unroll
        for (int j = 0; j < 4; j++)
            #pragma unroll
            for (int q = 0; q < 4; q++) acc[i][j][q] = 0.f;

    for (int k0 = 0; k0 < K; k0 += TBK) {
        {
            unsigned h, l;
            int base = alm * SA_W + (alk >> 1);
            split2(ar0.x, ar0.y, h, l); Ah[base + 0] = h; Al[base + 0] = l;
            split2(ar0.z, ar0.w, h, l); Ah[base + 1] = h; Al[base + 1] = l;
            split2(ar1.x, ar1.y, h, l); Ah[base + 2] = h; Al[base + 2] = l;
            split2(ar1.z, ar1.w, h, l); Ah[base + 3] = h; Al[base + 3] = l;
            int wbase = wlm * SA_W + (wlk >> 1);
            split2(wr.x, wr.y, h, l); Wh[wbase + 0] = h; Wl[wbase + 0] = l;
            split2(wr.z, wr.w, h, l); Wh[wbase + 1] = h; Wl[wbase + 1] = l;
        }
        __syncthreads();

        if (k0 + TBK < K) {
            ar0 = *(const float4*)(aptr + k0 + TBK);
            ar1 = *(const float4*)(aptr + k0 + TBK + 4);
            if (wptr) wr = *(const float4*)(wptr + k0 + TBK);
        }

        unsigned fah[2][4], fal[2][4], fbh[4][2], fbl[4][2];
        #pragma unroll
        for (int mt = 0; mt < 2; mt++) {
            unsigned off = a_off + (unsigned)(mt * 16 * SA_W) * 4u;
            ldsm_x4(fah[mt], sAh + off);
            ldsm_x4(fal[mt], sAl + off);
        }
        #pragma unroll
        for (int nt2 = 0; nt2 < 2; nt2++) {
            unsigned off = b_off + (unsigned)(nt2 * 16 * SA_W) * 4u;
            unsigned t[4];
            ldsm_x4(t, sWh + off);
            fbh[2*nt2][0] = t[0]; fbh[2*nt2][1] = t[1];
            fbh[2*nt2+1][0] = t[2]; fbh[2*nt2+1][1] = t[3];
            ldsm_x4(t, sWl + off);
            fbl[2*nt2][0] = t[0]; fbl[2*nt2][1] = t[1];
            fbl[2*nt2+1][0] = t[2]; fbl[2*nt2+1][1] = t[3];
        }
        #pragma unroll
        for (int mt = 0; mt < 2; mt++)
            #pragma unroll
            for (int nt = 0; nt < 4; nt++) {
                mma_bf16(acc[mt][nt], fah[mt], fbl[nt]);
                mma_bf16(acc[mt][nt], fal[mt], fbh[nt]);
                mma_bf16(acc[mt][nt], fah[mt], fbh[nt]);
            }
        __syncthreads();
    }

    #pragma unroll
    for (int mt = 0; mt < 2; mt++) {
        #pragma unroll
        for (int nt = 0; nt < 4; nt++) {
            int col = n0 + wn + nt * 8 + qk * 2;
            if (col >= N) continue;
            int row = m0 + wm + mt * 16 + grp;
            long off0 = (long)row * N + col;
            long off1 = (long)(row + 8) * N + col;
            float2 v0 = make_float2(acc[mt][nt][0], acc[mt][nt][1]);
            float2 v1 = make_float2(acc[mt][nt][2], acc[mt][nt][3]);
            if (res) {
                float2 r0 = *(const float2*)(res + off0);
                float2 r1 = *(const float2*)(res + off1);
                v0.x += r0.x; v0.y += r0.y;
                v1.x += r1.x; v1.y += r1.y;
            }
            *(float2*)(C + off0) = v0;
            *(float2*)(C + off1) = v1;
        }
    }
}

// ---------------- LayerNorm (warp per token, in place) ----------------
__global__ void ln_kernel(float* __restrict__ y, const float* __restrict__ w,
                          const float* __restrict__ b) {
    long t = (long)(blockIdx.x * (blockDim.x >> 5)) + (threadIdx.x >> 5);
    int lane = threadIdx.x & 31;
    float* row = y + t * D_MODEL;
    float4 v0 = *(const float4*)(row + lane * 8);
    float4 v1 = *(const float4*)(row + lane * 8 + 4);
    float s = v0.x + v0.y + v0.z + v0.w + v1.x + v1.y + v1.z + v1.w;
    float sq = v0.x*v0.x + v0.y*v0.y + v0.z*v0.z + v0.w*v0.w
             + v1.x*v1.x + v1.y*v1.y + v1.z*v1.z + v1.w*v1.w;
    s = warp_sum(s) * (1.f / D_MODEL);
    sq = warp_sum(sq) * (1.f / D_MODEL);
    float r = rsqrtf(sq - s * s + EPS);
    float4 w0 = *(const float4*)(w + lane * 8);
    float4 w1 = *(const float4*)(w + lane * 8 + 4);
    float4 b0 = *(const float4*)(b + lane * 8);
    float4 b1 = *(const float4*)(b + lane * 8 + 4);
    v0.x = (v0.x - s) * r * w0.x + b0.x; v0.y = (v0.y - s) * r * w0.y + b0.y;
    v0.z = (v0.z - s) * r * w0.z + b0.z; v0.w = (v0.w - s) * r * w0.w + b0.w;
    v1.x = (v1.x - s) * r * w1.x + b1.x; v1.y = (v1.y - s) * r * w1.y + b1.y;
    v1.z = (v1.z - s) * r * w1.z + b1.z; v1.w = (v1.w - s) * r * w1.w + b1.w;
    *(float4*)(row + lane * 8) = v0;
    *(float4*)(row + lane * 8 + 4) = v1;
}

// ---------------- RMSNorm (warp per token) ----------------
__global__ void rms_kernel(const float* __restrict__ y, const float* __restrict__ w,
                           float* __restrict__ out) {
    long t = (long)(blockIdx.x * (blockDim.x >> 5)) + (threadIdx.x >> 5);
    int lane = threadIdx.x & 31;
    const float* row = y + t * D_MODEL;
    float4 v0 = *(const float4*)(row + lane * 8);
    float4 v1 = *(const float4*)(row + lane * 8 + 4);
    float sq = v0.x*v0.x + v0.y*v0.y + v0.z*v0.z + v0.w*v0.w
             + v1.x*v1.x + v1.y*v1.y + v1.z*v1.z + v1.w*v1.w;
    sq = warp_sum(sq) * (1.f / D_MODEL);
    float r = rsqrtf(sq + EPS);
    float4 w0 = *(const float4*)(w + lane * 8);
    float4 w1 = *(const float4*)(w + lane * 8 + 4);
    v0.x *= r * w0.x; v0.y *= r * w0.y; v0.z *= r * w0.z; v0.w *= r * w0.w;
    v1.x *= r * w1.x; v1.y *= r * w1.y; v1.z *= r * w1.z; v1.w *= r * w1.w;
    float* orow = out + t * D_MODEL;
    *(float4*)(orow + lane * 8) = v0;
    *(float4*)(orow + lane * 8 + 4) = v1;
}

// ---------------- depthwise causal conv (width 4) + bias + silu, float4 ----------------
#define CONV_G (CONV_DIM / 4)   // 160 4-channel groups
__global__ void conv_kernel(const float* __restrict__ zx, const float* __restrict__ cw,
                            const float* __restrict__ cb, float* __restrict__ out) {
    long idx = (long)blockIdx.x * blockDim.x + threadIdx.x;
    if (idx >= (long)NTOK * CONV_G) return;
    int cg = (int)(idx % CONV_G);
    int ch = cg * 4;
    long t = idx / CONV_G;
    int l = (int)(t & (L_ - 1));
    long brow = t - l;
    float4 wr0 = *(const float4*)(cw + (ch + 0) * D_CONV);
    float4 wr1 = *(const float4*)(cw + (ch + 1) * D_CONV);
    float4 wr2 = *(const float4*)(cw + (ch + 2) * D_CONV);
    float4 wr3 = *(const float4*)(cw + (ch + 3) * D_CONV);
    float4 a = *(const float4*)(cb + ch);
    #pragma unroll
    for (int k = 0; k < D_CONV; k++) {
        int ls = l + k - (D_CONV - 1);
        if (ls >= 0) {
            float4 x = *(const float4*)(zx + (brow + ls) * D_IN_PROJ + D_INNER + ch);
            const float* w0 = &wr0.x; const float* w1 = &wr1.x;
            const float* w2 = &wr2.x; const float* w3 = &wr3.x;
            a.x += x.x * w0[k]; a.y += x.y * w1[k];
            a.z += x.z * w2[k]; a.w += x.w * w3[k];
        }
    }
    a.x = silu_f(a.x); a.y = silu_f(a.y); a.z = silu_f(a.z); a.w = silu_f(a.w);
    *(float4*)(out + t * CONV_DIM + ch) = a;
}

// ---------------- SSD chunked scan: register-tiled + float4, 512 thr/block --------
#define SSD_ST 68
#define SSD_SMEM_FLOATS (6 * 64 * SSD_ST + 4 * 64)
#define SSD_THREADS 512
__global__ __launch_bounds__(SSD_THREADS)
void ssd_kernel(const float* __restrict__ conv, const float* __restrict__ zx,
                const float* __restrict__ dtb, const float* __restrict__ Alog,
                const float* __restrict__ Dp, float* __restrict__ out) {
    extern __shared__ float sm[];
    float* xs  = sm;
    float* Bm  = xs  + 64 * SSD_ST;
    float* Cm  = Bm  + 64 * SSD_ST;
    float* BmT = Cm  + 64 * SSD_ST;
    float* Mm  = BmT + 64 * SSD_ST;
    float* S   = Mm  + 64 * SSD_ST;
    float* acum = S + 64 * SSD_ST;
    float* dts  = acum + 64;
    float* dd   = dts + 64;
    float* eAl  = dd + 64;

    int tid = threadIdx.x;
    int b = blockIdx.x >> 3, h = blockIdx.x & 7;
    float Ah = -expf(Alog[h]);
    float dtbh = dtb[h];
    float Dh = Dp[h];

    int pg = tid & 15;
    int rr = tid >> 4;
    int msg = tid & 7;
    int ml = tid >> 3;

    for (int i = tid; i < 64 * SSD_ST; i += SSD_THREADS) S[i] = 0.f;
    __syncthreads();

    for (int c = 0; c < 8; ++c) {
        long tok0 = (long)b * L_ + c * CHUNK;
        for (int i = tid; i < 4096; i += SSD_THREADS) {
            int l = i >> 6, q = i & 63;
            const float* row = conv + (tok0 + l) * CONV_DIM;
            xs[l * SSD_ST + q] = row[h * 64 + q];
            float bv = row[D_INNER + q];
            Bm[l * SSD_ST + q] = bv;
            BmT[q * SSD_ST + l] = bv;
            Cm[l * SSD_ST + q] = row[D_INNER + D_STATE + q];
        }
        if (tid < 64) {
            float x = zx[(tok0 + tid) * D_IN_PROJ + (D_IN_PROJ - NHEADS) + h] + dtbh;
            float dt = (x > 20.f) ? x : log1pf(expf(x));
            dts[tid] = dt;
            acum[tid] = Ah * dt;
        }
        __syncthreads();
        if (tid < 32) {
            float v0 = acum[2 * tid], v1 = acum[2 * tid + 1];
            float s = v0 + v1;
            #pragma unroll
            for (int o = 1; o < 32; o <<= 1) {
                float t = __shfl_up_sync(0xffffffffu, s, o);
                if (tid >= o) s += t;
            }
            acum[2 * tid] = s - v1;
            acum[2 * tid + 1] = s;
        }
        __syncthreads();
        if (tid < 64) {
            eAl[tid] = expf(acum[tid]);
            dd[tid] = dts[tid] * expf(acum[63] - acum[tid]);
        }
        __syncthreads();
        {
            float a8[8];
            #pragma unroll
            for (int j = 0; j < 8; j++) a8[j] = 0.f;
            int s0 = msg * 8;
            #pragma unroll 4
            for (int n = 0; n < 64; n++) {
                float cv = Cm[ml * SSD_ST + n];
                float4 b0 = *(const float4*)(BmT + n * SSD_ST + s0);
                float4 b1 = *(const float4*)(BmT + n * SSD_ST + s0 + 4);
                a8[0] += cv * b0.x; a8[1] += cv * b0.y;
                a8[2] += cv * b0.z; a8[3] += cv * b0.w;
                a8[4] += cv * b1.x; a8[5] += cv * b1.y;
                a8[6] += cv * b1.z; a8[7] += cv * b1.w;
            }
            float al = acum[ml];
            #pragma unroll
            for (int j = 0; j < 8; j++) {
                int s = s0 + j;
                float v = (s <= ml) ? a8[j] * expf(al - acum[s]) * dts[s] : 0.f;
                Mm[ml * SSD_ST + s] = v;
            }
        }
        __syncthreads();
        #pragma unroll
        for (int it = 0; it < 2; it++) {
            int l = rr + it * 32;
            int p4 = pg * 4;
            float4 xv = *(const float4*)(xs + l * SSD_ST + p4);
            float4 a = make_float4(Dh * xv.x, Dh * xv.y, Dh * xv.z, Dh * xv.w);
            #pragma unroll 8
            for (int s = 0; s < 64; s++) {
                float m = Mm[l * SSD_ST + s];
                float4 x4 = *(const float4*)(xs + s * SSD_ST + p4);
                a.x += m * x4.x; a.y += m * x4.y;
                a.z += m * x4.z; a.w += m * x4.w;
            }
            float4 off = make_float4(0.f, 0.f, 0.f, 0.f);
            #pragma unroll 8
            for (int n = 0; n < 64; n++) {
                float cv = Cm[l * SSD_ST + n];
                float4 s4 = *(const float4*)(S + n * SSD_ST + p4);
                off.x += cv * s4.x; off.y += cv * s4.y;
                off.z += cv * s4.z; off.w += cv * s4.w;
            }
            float e = eAl[l];
            float4 r = make_float4(a.x + e * off.x, a.y + e * off.y,
                                   a.z + e * off.z, a.w + e * off.w);
            *(float4*)(out + (tok0 + l) * D_INNER + h * 64 + p4) = r;
        }
        __syncthreads();
        {
            float eTot = eAl[63];
            #pragma unroll
            for (int it = 0; it < 2; it++) {
                int n = rr + it * 32;
                int p4 = pg * 4;
                float4 s4 = *(const float4*)(S + n * SSD_ST + p4);
                float4 a = make_float4(s4.x * eTot, s4.y * eTot,
                                       s4.z * eTot, s4.w * eTot);
                #pragma unroll 8
                for (int l = 0; l < 64; l++) {
                    float bd = Bm[l * SSD_ST + n] * dd[l];
                    float4 x4 = *(const float4*)(xs + l * SSD_ST + p4);
                    a.x += bd * x4.x; a.y += bd * x4.y;
                    a.z += bd * x4.z; a.w += bd * x4.w;
                }
                *(float4*)(S + n * SSD_ST + p4) = a;
            }
        }
        __syncthreads();
    }
}

// ---------------- gated RMSNorm (warp per token): rmsnorm(y*silu(z)) * gw ----------
__global__ void gated_kernel(const float* __restrict__ yin, const float* __restrict__ zx,
                             const float* __restrict__ gw, float* __restrict__ out) {
    long t = (long)(blockIdx.x * (blockDim.x >> 5)) + (threadIdx.x >> 5);
    int lane = threadIdx.x & 31;
    const float* yrow = yin + t * D_INNER;
    const float* zrow = zx + t * D_IN_PROJ;
    float u[16];
    float sq = 0.f;
    #pragma unroll
    for (int j = 0; j < 4; j++) {
        int d = lane * 4 + j * 128;
        float4 yv = *(const float4*)(yrow + d);
        float4 zv = *(const float4*)(zrow + d);
        float a0 = yv.x * silu_f(zv.x);
        float a1 = yv.y * silu_f(zv.y);
        float a2 = yv.z * silu_f(zv.z);
        float a3 = yv.w * silu_f(zv.w);
        u[j*4+0] = a0; u[j*4+1] = a1; u[j*4+2] = a2; u[j*4+3] = a3;
        sq += a0*a0 + a1*a1 + a2*a2 + a3*a3;
    }
    sq = warp_sum(sq) * (1.f / D_INNER);
    float r = rsqrtf(sq + EPS);
    float* orow = out + t * D_INNER;
    #pragma unroll
    for (int j = 0; j < 4; j++) {
        int d = lane * 4 + j * 128;
        float4 g = *(const float4*)(gw + d);
        float4 v = make_float4(u[j*4+0]*r*g.x, u[j*4+1]*r*g.y,
                               u[j*4+2]*r*g.z, u[j*4+3]*r*g.w);
        *(float4*)(orow + d) = v;
    }
}

// ---------------- final: rmsnorm(last token) -> elu -> @ out_W^T ----------------
__global__ void final_kernel(const float* __restrict__ y, const float* __restrict__ nw,
                             const float* __restrict__ ow, float* __restrict__ out) {
    __shared__ float sh[8];
    __shared__ float u[256];
    int b = blockIdx.x;
    int d = threadIdx.x;
    float v = y[((long)b * L_ + (L_ - 1)) * D_MODEL + d];
    float sq = v * v;
    #pragma unroll
    for (int o = 16; o; o >>= 1) sq += __shfl_xor_sync(0xffffffffu, sq, o);
    if ((d & 31) == 0) sh[d >> 5] = sq;
    __syncthreads();
    float ms = 0.f;
    #pragma unroll
    for (int i = 0; i < 8; i++) ms += sh[i];
    ms *= (1.f / D_MODEL);
    float x = v * rsqrtf(ms + EPS) * nw[d];
    u[d] = (x > 0.f) ? x : (expf(x) - 1.f);
    __syncthreads();
    if (d < COUT_) {
        float a = 0.f;
        for (int k = 0; k < D_MODEL; k++) a += u[k] * ow[d * D_MODEL + k];
        out[b * COUT_ + d] = a;
    }
}

// ---------------- host orchestration ----------------
extern "C" void kernel_launch(void* const* d_in, const int* in_sizes, int n_in,
                              void* d_out, int out_size) {
    const float* obs     = (const float*)d_in[0];
    const float* in_W    = (const float*)d_in[1];
    const float* ln1_w   = (const float*)d_in[2];
    const float* ln1_b   = (const float*)d_in[3];
    const float* rms_w   = (const float*)d_in[4];
    const float* inproj  = (const float*)d_in[5];
    const float* conv_w  = (const float*)d_in[6];
    const float* conv_b  = (const float*)d_in[7];
    const float* dt_bias = (const float*)d_in[8];
    const float* A_log   = (const float*)d_in[9];
    const float* Dp      = (const float*)d_in[10];
    const float* gnorm   = (const float*)d_in[11];
    const float* outproj = (const float*)d_in[12];
    const float* normf   = (const float*)d_in[13];
    const float* out_W   = (const float*)d_in[14];
    float* out = (float*)d_out;

    float *y, *h, *zx, *conv, *ssd, *gate;
    cudaGetSymbolAddress((void**)&y, g_y);
    cudaGetSymbolAddress((void**)&h, g_h);
    cudaGetSymbolAddress((void**)&zx, g_zx);
    cudaGetSymbolAddress((void**)&conv, g_conv);
    cudaGetSymbolAddress((void**)&ssd, g_ssd);
    cudaGetSymbolAddress((void**)&gate, g_gate);

    size_t ssd_smem = SSD_SMEM_FLOATS * sizeof(float);
    cudaFuncSetAttribute(ssd_kernel, cudaFuncAttributeMaxDynamicSharedMemorySize,
                         (int)ssd_smem);

    // 1) y = obs @ in_W^T  (M=65536, N=256, K=48), then LayerNorm in place
    {
        dim3 grid((D_MODEL + TBN - 1) / TBN, NTOK / TBM);
        gemm_bf3<<<grid, 256>>>(obs, in_W, nullptr, y, NTOK, D_MODEL, CIN);
        ln_kernel<<<NTOK / 8, 256>>>(y, ln1_w, ln1_b);
    }

    for (int i = 0; i < N_LAYER; i++) {
        const float* Wi = inproj + (long)i * D_IN_PROJ * D_MODEL;
        const float* Wo = outproj + (long)i * D_MODEL * D_INNER;
        const float* cwi = conv_w + (long)i * CONV_DIM * D_CONV;
        const float* cbi = conv_b + (long)i * CONV_DIM;
        const float* dtbi = dt_bias + i * NHEADS;
        const float* Ali = A_log + i * NHEADS;
        const float* Dpi = Dp + i * NHEADS;
        const float* gwi = gnorm + (long)i * D_INNER;
        const float* rwi = rms_w + (long)i * D_MODEL;

        rms_kernel<<<NTOK / 8, 256>>>(y, rwi, h);
        {
            dim3 grid((D_IN_PROJ + TBN - 1) / TBN, NTOK / TBM);
            gemm_bf3<<<grid, 256>>>(h, Wi, nullptr, zx, NTOK, D_IN_PROJ, D_MODEL);
        }
        {
            long total = (long)NTOK * CONV_G;
            int blocks = (int)((total + 255) / 256);
            conv_kernel<<<blocks, 256>>>(zx, cwi, cbi, conv);
        }
        ssd_kernel<<<B_ * NHEADS, SSD_THREADS, ssd_smem>>>(conv, zx, dtbi, Ali, Dpi, ssd);
        gated_kernel<<<NTOK / 8, 256>>>(ssd, zx, gwi, gate);
        {
            dim3 grid((D_MODEL + TBN - 1) / TBN, NTOK / TBM);
            gemm_bf3<<<grid, 256>>>(gate, Wo, y, y, NTOK, D_MODEL, D_INNER);
        }
    }

    final_kernel<<<B_, 256>>>(y, normf, out_W, out);
}

// round 11
// speedup vs baseline: 2.4119x; 1.7420x over previous
#include <cuda_runtime.h>
#include <cuda_bf16.h>
#include <math.h>

#define B_ 128
#define L_ 512
#define CIN 48
#define COUT_ 12
#define D_MODEL 256
#define N_LAYER 4
#define D_STATE 64
#define D_CONV 4
#define HEADDIM 64
#define CHUNK 64
#define D_INNER 512
#define NHEADS 8
#define CONV_DIM 640
#define D_IN_PROJ 1160
#define NTOK (B_ * L_)
#define EPS 1e-5f

// ---------------- scratch (static device globals; no runtime alloc) ----------------
__device__ float g_y[NTOK * D_MODEL];
__device__ float g_h[NTOK * D_MODEL];
__device__ float g_zx[NTOK * D_IN_PROJ];
__device__ float g_conv[NTOK * CONV_DIM];
__device__ float g_ssd[NTOK * D_INNER];
__device__ float g_gate[NTOK * D_INNER];

__device__ __forceinline__ float silu_f(float x) { return x / (1.f + expf(-x)); }

__device__ __forceinline__ float warp_sum(float v) {
    #pragma unroll
    for (int o = 16; o; o >>= 1) v += __shfl_xor_sync(0xffffffffu, v, o);
    return v;
}

// ---------------- bf16 split helpers ----------------
__device__ __forceinline__ void split2(float a, float b, unsigned& hi, unsigned& lo) {
    __nv_bfloat16 ha = __float2bfloat16_rn(a);
    __nv_bfloat16 hb = __float2bfloat16_rn(b);
    __nv_bfloat162 h; h.x = ha; h.y = hb;
    __nv_bfloat162 l = __floats2bfloat162_rn(a - __bfloat162float(ha),
                                             b - __bfloat162float(hb));
    hi = *reinterpret_cast<unsigned*>(&h);
    lo = *reinterpret_cast<unsigned*>(&l);
}
__device__ __forceinline__ void mma_bf16(float (&d)[4], const unsigned (&a)[4],
                                         const unsigned (&b)[2]) {
    asm volatile(
        "mma.sync.aligned.m16n8k16.row.col.f32.bf16.bf16.f32 "
        "{%0,%1,%2,%3}, {%4,%5,%6,%7}, {%8,%9}, {%0,%1,%2,%3};\n"
        : "+f"(d[0]), "+f"(d[1]), "+f"(d[2]), "+f"(d[3])
        : "r"(a[0]), "r"(a[1]), "r"(a[2]), "r"(a[3]), "r"(b[0]), "r"(b[1]));
}
__device__ __forceinline__ void ldsm_x4(unsigned (&r)[4], unsigned addr) {
    asm volatile("ldmatrix.sync.aligned.m8n8.x4.shared.b16 {%0,%1,%2,%3}, [%4];"
        : "=r"(r[0]), "=r"(r[1]), "=r"(r[2]), "=r"(r[3]) : "r"(addr));
}

// ---------------- tensor-core GEMM: C[M,N] = A[M,K] @ W[N,K]^T (+res) ----------------
// bf16 split-3 (hi/lo), single-buffered smem (known-good R7 version).
#define TBM 128
#define TBN 64
#define TBK 16
#define SA_H (TBK + 8)
#define SA_W (SA_H / 2)
__global__ __launch_bounds__(256) void gemm_bf3(
        const float* __restrict__ A, const float* __restrict__ W,
        const float* __restrict__ res, float* __restrict__ C,
        int M, int N, int K) {
    __shared__ unsigned Ah[TBM * SA_W], Al[TBM * SA_W];
    __shared__ unsigned Wh[TBN * SA_W], Wl[TBN * SA_W];
    int tid = threadIdx.x;
    int lane = tid & 31, wid = tid >> 5;
    int wm = (wid >> 1) * 32;
    int wn = (wid & 1) * 32;
    int grp = lane >> 2, qk = lane & 3;
    int m0 = blockIdx.y * TBM, n0 = blockIdx.x * TBN;

    int alm = tid >> 1;
    int alk = (tid & 1) * 8;
    int wlm = tid >> 2;
    int wlk = (tid & 3) * 4;

    const float* aptr = A + (long)(m0 + alm) * K + alk;
    const float* wptr = (n0 + wlm < N) ? (W + (long)(n0 + wlm) * K + wlk) : nullptr;

    float4 ar0 = *(const float4*)(aptr);
    float4 ar1 = *(const float4*)(aptr + 4);
    float4 wr = wptr ? *(const float4*)(wptr) : make_float4(0.f, 0.f, 0.f, 0.f);

    unsigned sAh = (unsigned)__cvta_generic_to_shared(Ah);
    unsigned sAl = (unsigned)__cvta_generic_to_shared(Al);
    unsigned sWh = (unsigned)__cvta_generic_to_shared(Wh);
    unsigned sWl = (unsigned)__cvta_generic_to_shared(Wl);
    unsigned a_off = (unsigned)((wm + (lane & 15)) * SA_W + (lane >> 4) * 4) * 4u;
    unsigned b_row = (lane & 7) + ((lane >> 4) * 8);
    unsigned b_off = (unsigned)((wn + b_row) * SA_W + ((lane >> 3) & 1) * 4) * 4u;

    float acc[2][4][4];
    #pragma unroll
    for (int i = 0; i < 2; i++)
        #pragma unroll
        for (int j = 0; j < 4; j++)
            #pragma unroll
            for (int q = 0; q < 4; q++) acc[i][j][q] = 0.f;

    for (int k0 = 0; k0 < K; k0 += TBK) {
        {
            unsigned h, l;
            int base = alm * SA_W + (alk >> 1);
            split2(ar0.x, ar0.y, h, l); Ah[base + 0] = h; Al[base + 0] = l;
            split2(ar0.z, ar0.w, h, l); Ah[base + 1] = h; Al[base + 1] = l;
            split2(ar1.x, ar1.y, h, l); Ah[base + 2] = h; Al[base + 2] = l;
            split2(ar1.z, ar1.w, h, l); Ah[base + 3] = h; Al[base + 3] = l;
            int wbase = wlm * SA_W + (wlk >> 1);
            split2(wr.x, wr.y, h, l); Wh[wbase + 0] = h; Wl[wbase + 0] = l;
            split2(wr.z, wr.w, h, l); Wh[wbase + 1] = h; Wl[wbase + 1] = l;
        }
        __syncthreads();

        if (k0 + TBK < K) {
            ar0 = *(const float4*)(aptr + k0 + TBK);
            ar1 = *(const float4*)(aptr + k0 + TBK + 4);
            if (wptr) wr = *(const float4*)(wptr + k0 + TBK);
        }

        unsigned fah[2][4], fal[2][4], fbh[4][2], fbl[4][2];
        #pragma unroll
        for (int mt = 0; mt < 2; mt++) {
            unsigned off = a_off + (unsigned)(mt * 16 * SA_W) * 4u;
            ldsm_x4(fah[mt], sAh + off);
            ldsm_x4(fal[mt], sAl + off);
        }
        #pragma unroll
        for (int nt2 = 0; nt2 < 2; nt2++) {
            unsigned off = b_off + (unsigned)(nt2 * 16 * SA_W) * 4u;
            unsigned t[4];
            ldsm_x4(t, sWh + off);
            fbh[2*nt2][0] = t[0]; fbh[2*nt2][1] = t[1];
            fbh[2*nt2+1][0] = t[2]; fbh[2*nt2+1][1] = t[3];
            ldsm_x4(t, sWl + off);
            fbl[2*nt2][0] = t[0]; fbl[2*nt2][1] = t[1];
            fbl[2*nt2+1][0] = t[2]; fbl[2*nt2+1][1] = t[3];
        }
        #pragma unroll
        for (int mt = 0; mt < 2; mt++)
            #pragma unroll
            for (int nt = 0; nt < 4; nt++) {
                mma_bf16(acc[mt][nt], fah[mt], fbl[nt]);
                mma_bf16(acc[mt][nt], fal[mt], fbh[nt]);
                mma_bf16(acc[mt][nt], fah[mt], fbh[nt]);
            }
        __syncthreads();
    }

    #pragma unroll
    for (int mt = 0; mt < 2; mt++) {
        #pragma unroll
        for (int nt = 0; nt < 4; nt++) {
            int col = n0 + wn + nt * 8 + qk * 2;
            if (col >= N) continue;
            int row = m0 + wm + mt * 16 + grp;
            long off0 = (long)row * N + col;
            long off1 = (long)(row + 8) * N + col;
            float2 v0 = make_float2(acc[mt][nt][0], acc[mt][nt][1]);
            float2 v1 = make_float2(acc[mt][nt][2], acc[mt][nt][3]);
            if (res) {
                float2 r0 = *(const float2*)(res + off0);
                float2 r1 = *(const float2*)(res + off1);
                v0.x += r0.x; v0.y += r0.y;
                v1.x += r1.x; v1.y += r1.y;
            }
            *(float2*)(C + off0) = v0;
            *(float2*)(C + off1) = v1;
        }
    }
}

// ---------------- LayerNorm (warp per token, in place) ----------------
__global__ void ln_kernel(float* __restrict__ y, const float* __restrict__ w,
                          const float* __restrict__ b) {
    long t = (long)(blockIdx.x * (blockDim.x >> 5)) + (threadIdx.x >> 5);
    int lane = threadIdx.x & 31;
    float* row = y + t * D_MODEL;
    float4 v0 = *(const float4*)(row + lane * 8);
    float4 v1 = *(const float4*)(row + lane * 8 + 4);
    float s = v0.x + v0.y + v0.z + v0.w + v1.x + v1.y + v1.z + v1.w;
    float sq = v0.x*v0.x + v0.y*v0.y + v0.z*v0.z + v0.w*v0.w
             + v1.x*v1.x + v1.y*v1.y + v1.z*v1.z + v1.w*v1.w;
    s = warp_sum(s) * (1.f / D_MODEL);
    sq = warp_sum(sq) * (1.f / D_MODEL);
    float r = rsqrtf(sq - s * s + EPS);
    float4 w0 = *(const float4*)(w + lane * 8);
    float4 w1 = *(const float4*)(w + lane * 8 + 4);
    float4 b0 = *(const float4*)(b + lane * 8);
    float4 b1 = *(const float4*)(b + lane * 8 + 4);
    v0.x = (v0.x - s) * r * w0.x + b0.x; v0.y = (v0.y - s) * r * w0.y + b0.y;
    v0.z = (v0.z - s) * r * w0.z + b0.z; v0.w = (v0.w - s) * r * w0.w + b0.w;
    v1.x = (v1.x - s) * r * w1.x + b1.x; v1.y = (v1.y - s) * r * w1.y + b1.y;
    v1.z = (v1.z - s) * r * w1.z + b1.z; v1.w = (v1.w - s) * r * w1.w + b1.w;
    *(float4*)(row + lane * 8) = v0;
    *(float4*)(row + lane * 8 + 4) = v1;
}

// ---------------- RMSNorm (warp per token) ----------------
__global__ void rms_kernel(const float* __restrict__ y, const float* __restrict__ w,
                           float* __restrict__ out) {
    long t = (long)(blockIdx.x * (blockDim.x >> 5)) + (threadIdx.x >> 5);
    int lane = threadIdx.x & 31;
    const float* row = y + t * D_MODEL;
    float4 v0 = *(const float4*)(row + lane * 8);
    float4 v1 = *(const float4*)(row + lane * 8 + 4);
    float sq = v0.x*v0.x + v0.y*v0.y + v0.z*v0.z + v0.w*v0.w
             + v1.x*v1.x + v1.y*v1.y + v1.z*v1.z + v1.w*v1.w;
    sq = warp_sum(sq) * (1.f / D_MODEL);
    float r = rsqrtf(sq + EPS);
    float4 w0 = *(const float4*)(w + lane * 8);
    float4 w1 = *(const float4*)(w + lane * 8 + 4);
    v0.x *= r * w0.x; v0.y *= r * w0.y; v0.z *= r * w0.z; v0.w *= r * w0.w;
    v1.x *= r * w1.x; v1.y *= r * w1.y; v1.z *= r * w1.z; v1.w *= r * w1.w;
    float* orow = out + t * D_MODEL;
    *(float4*)(orow + lane * 8) = v0;
    *(float4*)(orow + lane * 8 + 4) = v1;
}

// ---------------- depthwise causal conv (width 4) + bias + silu, float4 ----------------
#define CONV_G (CONV_DIM / 4)
__global__ void conv_kernel(const float* __restrict__ zx, const float* __restrict__ cw,
                            const float* __restrict__ cb, float* __restrict__ out) {
    long idx = (long)blockIdx.x * blockDim.x + threadIdx.x;
    if (idx >= (long)NTOK * CONV_G) return;
    int cg = (int)(idx % CONV_G);
    int ch = cg * 4;
    long t = idx / CONV_G;
    int l = (int)(t & (L_ - 1));
    long brow = t - l;
    float4 wr0 = *(const float4*)(cw + (ch + 0) * D_CONV);
    float4 wr1 = *(const float4*)(cw + (ch + 1) * D_CONV);
    float4 wr2 = *(const float4*)(cw + (ch + 2) * D_CONV);
    float4 wr3 = *(const float4*)(cw + (ch + 3) * D_CONV);
    float4 a = *(const float4*)(cb + ch);
    #pragma unroll
    for (int k = 0; k < D_CONV; k++) {
        int ls = l + k - (D_CONV - 1);
        if (ls >= 0) {
            float4 x = *(const float4*)(zx + (brow + ls) * D_IN_PROJ + D_INNER + ch);
            const float* w0 = &wr0.x; const float* w1 = &wr1.x;
            const float* w2 = &wr2.x; const float* w3 = &wr3.x;
            a.x += x.x * w0[k]; a.y += x.y * w1[k];
            a.z += x.z * w2[k]; a.w += x.w * w3[k];
        }
    }
    a.x = silu_f(a.x); a.y = silu_f(a.y); a.z = silu_f(a.z); a.w = silu_f(a.w);
    *(float4*)(out + t * CONV_DIM + ch) = a;
}

// ---------------- SSD chunked scan: TENSOR-CORE version ----------------
// One block per (b,h), 256 threads (8 warps), 8 sequential chunks.
// All 64x64x64 matmuls on mma.bf16 with hi/lo split-3 (same scheme as gemm_bf3).
// Warp tile: 16 rows x 32 cols -> 4 n-tiles of m16n8.
// smem planes (stride 72 halves = 36 words, conflict-free for ldmatrix):
//   XT[p][s]  : x transposed            (B-op for Y_diag, A for S-update)
//   C [l][n]                            (A for G and Y_off)
//   BM[s][n]  : B tile, then M[l][s]    (B-op for G; A for Y_diag)
//   BT[n][l]  : B^T * dd                (B-op for S-update)
//   ST[p][n]  : state transposed, persistent hi/lo across chunks (B-op for Y_off)
#define SS_W 36
#define SSD_PLANE (64 * SS_W)
#define SSD_SMEM_BYTES ((10 * SSD_PLANE + 256) * 4)
__global__ __launch_bounds__(256)
void ssd_kernel(const float* __restrict__ conv, const float* __restrict__ zx,
                const float* __restrict__ dtb, const float* __restrict__ Alog,
                const float* __restrict__ Dp, float* __restrict__ out) {
    extern __shared__ unsigned smw[];
    unsigned* XTh = smw;
    unsigned* XTl = XTh + SSD_PLANE;
    unsigned* Chp = XTl + SSD_PLANE;
    unsigned* Clp = Chp + SSD_PLANE;
    unsigned* BMh = Clp + SSD_PLANE;
    unsigned* BMl = BMh + SSD_PLANE;
    unsigned* BTh = BMl + SSD_PLANE;
    unsigned* BTl = BTh + SSD_PLANE;
    unsigned* STh = BTl + SSD_PLANE;
    unsigned* STl = STh + SSD_PLANE;
    float* acum = (float*)(STl + SSD_PLANE);
    float* dts = acum + 64;
    float* dd  = dts + 64;
    float* eAl = dd + 64;

    __nv_bfloat16* eXTh = (__nv_bfloat16*)XTh;
    __nv_bfloat16* eXTl = (__nv_bfloat16*)XTl;
    __nv_bfloat16* eCh  = (__nv_bfloat16*)Chp;
    __nv_bfloat16* eCl  = (__nv_bfloat16*)Clp;
    __nv_bfloat16* eBMh = (__nv_bfloat16*)BMh;
    __nv_bfloat16* eBMl = (__nv_bfloat16*)BMl;
    __nv_bfloat16* eBTh = (__nv_bfloat16*)BTh;
    __nv_bfloat16* eBTl = (__nv_bfloat16*)BTl;
    __nv_bfloat16* eSTh = (__nv_bfloat16*)STh;
    __nv_bfloat16* eSTl = (__nv_bfloat16*)STl;

    int tid = threadIdx.x;
    int lane = tid & 31, wid = tid >> 5;
    int wr = (wid >> 1) * 16;          // row tile base (l or p)
    int wc = (wid & 1) * 32;           // col tile base (s, p, or n) — 32 cols
    int grp = lane >> 2, qk = lane & 3;
    int b = blockIdx.x >> 3, h = blockIdx.x & 7;
    float Ahc = -expf(Alog[h]);
    float dtbh = dtb[h], Dh = Dp[h];

    unsigned sXTh = (unsigned)__cvta_generic_to_shared(XTh);
    unsigned sXTl = (unsigned)__cvta_generic_to_shared(XTl);
    unsigned sCh  = (unsigned)__cvta_generic_to_shared(Chp);
    unsigned sCl  = (unsigned)__cvta_generic_to_shared(Clp);
    unsigned sBMh = (unsigned)__cvta_generic_to_shared(BMh);
    unsigned sBMl = (unsigned)__cvta_generic_to_shared(BMl);
    unsigned sBTh = (unsigned)__cvta_generic_to_shared(BTh);
    unsigned sBTl = (unsigned)__cvta_generic_to_shared(BTl);
    unsigned sSTh = (unsigned)__cvta_generic_to_shared(STh);
    unsigned sSTl = (unsigned)__cvta_generic_to_shared(STl);
    // fragment lane-address offsets (relative; add rowbase*SS_W*4 + kk*32)
    unsigned aoffA = (unsigned)((lane & 15) * SS_W + (lane >> 4) * 4) * 4u;
    unsigned aoffB = (unsigned)(((lane & 7) + ((lane >> 4) << 3)) * SS_W
                                + ((lane >> 3) & 1) * 4) * 4u;

    for (int i = tid; i < 2 * SSD_PLANE; i += 256) STh[i] = 0u;   // zero ST hi+lo
    __syncthreads();

    int r0 = wr + grp, r1 = r0 + 8;

    for (int c = 0; c < 8; ++c) {
        long tok0 = (long)b * L_ + c * CHUNK;
        // ---- dt / cumulative decay (needs only zx) ----
        if (tid < 64) {
            float x = zx[(tok0 + tid) * D_IN_PROJ + (D_IN_PROJ - NHEADS) + h] + dtbh;
            float dt = (x > 20.f) ? x : log1pf(expf(x));
            dts[tid] = dt;
            acum[tid] = Ahc * dt;
        }
        __syncthreads();
        if (tid < 32) {
            float v0 = acum[2 * tid], v1 = acum[2 * tid + 1];
            float s = v0 + v1;
            #pragma unroll
            for (int o = 1; o < 32; o <<= 1) {
                float t = __shfl_up_sync(0xffffffffu, s, o);
                if (tid >= o) s += t;
            }
            acum[2 * tid] = s - v1;
            acum[2 * tid + 1] = s;
        }
        __syncthreads();
        if (tid < 64) {
            eAl[tid] = expf(acum[tid]);
            dd[tid] = dts[tid] * expf(acum[63] - acum[tid]);
        }
        __syncthreads();
        // ---- load tiles as bf16 hi/lo (dd folded into BT) ----
        for (int i = tid; i < 4096; i += 256) {
            int l = i >> 6, q = i & 63;
            const float* row = conv + (tok0 + l) * CONV_DIM;
            float xv = row[h * 64 + q];
            float bv = row[D_INNER + q];
            float cv = row[D_INNER + D_STATE + q];
            __nv_bfloat16 t;
            t = __float2bfloat16_rn(xv);
            eXTh[q * 72 + l] = t;
            eXTl[q * 72 + l] = __float2bfloat16_rn(xv - __bfloat162float(t));
            t = __float2bfloat16_rn(bv);
            eBMh[l * 72 + q] = t;
            eBMl[l * 72 + q] = __float2bfloat16_rn(bv - __bfloat162float(t));
            float bd = bv * dd[l];
            t = __float2bfloat16_rn(bd);
            eBTh[q * 72 + l] = t;
            eBTl[q * 72 + l] = __float2bfloat16_rn(bd - __bfloat162float(t));
            t = __float2bfloat16_rn(cv);
            eCh[l * 72 + q] = t;
            eCl[l * 72 + q] = __float2bfloat16_rn(cv - __bfloat162float(t));
        }
        __syncthreads();
        // ---- matmul 1: G[l][s] = C · B^T  (A=C rows wr, B-op=BM rows wc..wc+31) ----
        float g[4][4];
        #pragma unroll
        for (int j = 0; j < 4; j++)
            #pragma unroll
            for (int q = 0; q < 4; q++) g[j][q] = 0.f;
        #pragma unroll
        for (int kk = 0; kk < 4; kk++) {
            unsigned ah[4], al4[4], t4[4];
            unsigned ab = (unsigned)(wr * SS_W * 4) + aoffA + kk * 32;
            ldsm_x4(ah, sCh + ab);
            ldsm_x4(al4, sCl + ab);
            unsigned bh[4][2], bl[4][2];
            #pragma unroll
            for (int hf = 0; hf < 2; hf++) {
                unsigned bb = (unsigned)((wc + hf * 16) * SS_W * 4) + aoffB + kk * 32;
                ldsm_x4(t4, sBMh + bb);
                bh[hf*2][0]=t4[0]; bh[hf*2][1]=t4[1]; bh[hf*2+1][0]=t4[2]; bh[hf*2+1][1]=t4[3];
                ldsm_x4(t4, sBMl + bb);
                bl[hf*2][0]=t4[0]; bl[hf*2][1]=t4[1]; bl[hf*2+1][0]=t4[2]; bl[hf*2+1][1]=t4[3];
            }
            #pragma unroll
            for (int j = 0; j < 4; j++) {
                mma_bf16(g[j], ah, bl[j]);
                mma_bf16(g[j], al4, bh[j]);
                mma_bf16(g[j], ah, bh[j]);
            }
        }
        __syncthreads();   // all warps done reading BM (B tile)
        // ---- decay + mask in registers, write M into BM planes ----
        {
            float ar0 = acum[r0], ar1 = acum[r1];
            #pragma unroll
            for (int j = 0; j < 4; j++) {
                int cc = wc + j * 8 + qk * 2;
                float as0 = acum[cc], as1 = acum[cc + 1];
                float d0 = dts[cc], d1 = dts[cc + 1];
                float v00 = (cc     <= r0) ? g[j][0] * expf(ar0 - as0) * d0 : 0.f;
                float v01 = (cc + 1 <= r0) ? g[j][1] * expf(ar0 - as1) * d1 : 0.f;
                float v10 = (cc     <= r1) ? g[j][2] * expf(ar1 - as0) * d0 : 0.f;
                float v11 = (cc + 1 <= r1) ? g[j][3] * expf(ar1 - as1) * d1 : 0.f;
                unsigned hi, lo;
                split2(v00, v01, hi, lo);
                BMh[r0 * SS_W + (cc >> 1)] = hi; BMl[r0 * SS_W + (cc >> 1)] = lo;
                split2(v10, v11, hi, lo);
                BMh[r1 * SS_W + (cc >> 1)] = hi; BMl[r1 * SS_W + (cc >> 1)] = lo;
            }
        }
        __syncthreads();
        // ---- matmul 2 (Y=M·X) + matmul 3 (O=C·S), combined epilogue ----
        float ya[4][4], oa[4][4];
        #pragma unroll
        for (int j = 0; j < 4; j++) {
            int cc = wc + j * 8 + qk * 2;
            ya[j][0] = Dh * (__bfloat162float(eXTh[cc * 72 + r0])
                           + __bfloat162float(eXTl[cc * 72 + r0]));
            ya[j][1] = Dh * (__bfloat162float(eXTh[(cc + 1) * 72 + r0])
                           + __bfloat162float(eXTl[(cc + 1) * 72 + r0]));
            ya[j][2] = Dh * (__bfloat162float(eXTh[cc * 72 + r1])
                           + __bfloat162float(eXTl[cc * 72 + r1]));
            ya[j][3] = Dh * (__bfloat162float(eXTh[(cc + 1) * 72 + r1])
                           + __bfloat162float(eXTl[(cc + 1) * 72 + r1]));
            oa[j][0] = oa[j][1] = oa[j][2] = oa[j][3] = 0.f;
        }
        #pragma unroll
        for (int kk = 0; kk < 4; kk++) {
            unsigned ab = (unsigned)(wr * SS_W * 4) + aoffA + kk * 32;
            unsigned mh[4], ml4[4], ch4[4], cl4[4], t4[4];
            ldsm_x4(mh, sBMh + ab); ldsm_x4(ml4, sBMl + ab);
            ldsm_x4(ch4, sCh + ab); ldsm_x4(cl4, sCl + ab);
            unsigned xh[4][2], xl[4][2], shh[4][2], sll[4][2];
            #pragma unroll
            for (int hf = 0; hf < 2; hf++) {
                unsigned bb = (unsigned)((wc + hf * 16) * SS_W * 4) + aoffB + kk * 32;
                ldsm_x4(t4, sXTh + bb);
                xh[hf*2][0]=t4[0]; xh[hf*2][1]=t4[1]; xh[hf*2+1][0]=t4[2]; xh[hf*2+1][1]=t4[3];
                ldsm_x4(t4, sXTl + bb);
                xl[hf*2][0]=t4[0]; xl[hf*2][1]=t4[1]; xl[hf*2+1][0]=t4[2]; xl[hf*2+1][1]=t4[3];
                ldsm_x4(t4, sSTh + bb);
                shh[hf*2][0]=t4[0]; shh[hf*2][1]=t4[1]; shh[hf*2+1][0]=t4[2]; shh[hf*2+1][1]=t4[3];
                ldsm_x4(t4, sSTl + bb);
                sll[hf*2][0]=t4[0]; sll[hf*2][1]=t4[1]; sll[hf*2+1][0]=t4[2]; sll[hf*2+1][1]=t4[3];
            }
            #pragma unroll
            for (int j = 0; j < 4; j++) {
                mma_bf16(ya[j], mh, xl[j]);
                mma_bf16(ya[j], ml4, xh[j]);
                mma_bf16(ya[j], mh, xh[j]);
                mma_bf16(oa[j], ch4, sll[j]);
                mma_bf16(oa[j], cl4, shh[j]);
                mma_bf16(oa[j], ch4, shh[j]);
            }
        }
        {
            float e0 = eAl[r0], e1 = eAl[r1];
            #pragma unroll
            for (int j = 0; j < 4; j++) {
                int cc = wc + j * 8 + qk * 2;
                float* o0 = out + (tok0 + r0) * D_INNER + h * 64 + cc;
                float* o1 = out + (tok0 + r1) * D_INNER + h * 64 + cc;
                *(float2*)o0 = make_float2(ya[j][0] + e0 * oa[j][0],
                                           ya[j][1] + e0 * oa[j][1]);
                *(float2*)o1 = make_float2(ya[j][2] + e1 * oa[j][2],
                                           ya[j][3] + e1 * oa[j][3]);
            }
        }
        __syncthreads();   // all warps done reading ST
        // ---- S-update: ST[p][n] = eTot*ST + XT·BTd (A=XT rows wr=p, B=BT rows wc=n) ----
        {
            float eT = eAl[63];
            float sa[4][4];
            #pragma unroll
            for (int j = 0; j < 4; j++) {
                int cc = wc + j * 8 + qk * 2;
                sa[j][0] = eT * (__bfloat162float(eSTh[r0 * 72 + cc])
                               + __bfloat162float(eSTl[r0 * 72 + cc]));
                sa[j][1] = eT * (__bfloat162float(eSTh[r0 * 72 + cc + 1])
                               + __bfloat162float(eSTl[r0 * 72 + cc + 1]));
                sa[j][2] = eT * (__bfloat162float(eSTh[r1 * 72 + cc])
                               + __bfloat162float(eSTl[r1 * 72 + cc]));
                sa[j][3] = eT * (__bfloat162float(eSTh[r1 * 72 + cc + 1])
                               + __bfloat162float(eSTl[r1 * 72 + cc + 1]));
            }
            #pragma unroll
            for (int kk = 0; kk < 4; kk++) {
                unsigned ab = (unsigned)(wr * SS_W * 4) + aoffA + kk * 32;
                unsigned ah[4], al4[4], t4[4];
                ldsm_x4(ah, sXTh + ab);
                ldsm_x4(al4, sXTl + ab);
                unsigned bh[4][2], bl[4][2];
                #pragma unroll
                for (int hf = 0; hf < 2; hf++) {
                    unsigned bb = (unsigned)((wc + hf * 16) * SS_W * 4) + aoffB + kk * 32;
                    ldsm_x4(t4, sBTh + bb);
                    bh[hf*2][0]=t4[0]; bh[hf*2][1]=t4[1]; bh[hf*2+1][0]=t4[2]; bh[hf*2+1][1]=t4[3];
                    ldsm_x4(t4, sBTl + bb);
                    bl[hf*2][0]=t4[0]; bl[hf*2][1]=t4[1]; bl[hf*2+1][0]=t4[2]; bl[hf*2+1][1]=t4[3];
                }
                #pragma unroll
                for (int j = 0; j < 4; j++) {
                    mma_bf16(sa[j], ah, bl[j]);
                    mma_bf16(sa[j], al4, bh[j]);
                    mma_bf16(sa[j], ah, bh[j]);
                }
            }
            #pragma unroll
            for (int j = 0; j < 4; j++) {
                int cc = wc + j * 8 + qk * 2;
                unsigned hi, lo;
                split2(sa[j][0], sa[j][1], hi, lo);
                STh[r0 * SS_W + (cc >> 1)] = hi; STl[r0 * SS_W + (cc >> 1)] = lo;
                split2(sa[j][2], sa[j][3], hi, lo);
                STh[r1 * SS_W + (cc >> 1)] = hi; STl[r1 * SS_W + (cc >> 1)] = lo;
            }
        }
        __syncthreads();   // chunk end: ST final, tiles free for reuse
    }
}

// ---------------- gated RMSNorm (warp per token): rmsnorm(y*silu(z)) * gw ----------
__global__ void gated_kernel(const float* __restrict__ yin, const float* __restrict__ zx,
                             const float* __restrict__ gw, float* __restrict__ out) {
    long t = (long)(blockIdx.x * (blockDim.x >> 5)) + (threadIdx.x >> 5);
    int lane = threadIdx.x & 31;
    const float* yrow = yin + t * D_INNER;
    const float* zrow = zx + t * D_IN_PROJ;
    float u[16];
    float sq = 0.f;
    #pragma unroll
    for (int j = 0; j < 4; j++) {
        int d = lane * 4 + j * 128;
        float4 yv = *(const float4*)(yrow + d);
        float4 zv = *(const float4*)(zrow + d);
        float a0 = yv.x * silu_f(zv.x);
        float a1 = yv.y * silu_f(zv.y);
        float a2 = yv.z * silu_f(zv.z);
        float a3 = yv.w * silu_f(zv.w);
        u[j*4+0] = a0; u[j*4+1] = a1; u[j*4+2] = a2; u[j*4+3] = a3;
        sq += a0*a0 + a1*a1 + a2*a2 + a3*a3;
    }
    sq = warp_sum(sq) * (1.f / D_INNER);
    float r = rsqrtf(sq + EPS);
    float* orow = out + t * D_INNER;
    #pragma unroll
    for (int j = 0; j < 4; j++) {
        int d = lane * 4 + j * 128;
        float4 g = *(const float4*)(gw + d);
        float4 v = make_float4(u[j*4+0]*r*g.x, u[j*4+1]*r*g.y,
                               u[j*4+2]*r*g.z, u[j*4+3]*r*g.w);
        *(float4*)(orow + d) = v;
    }
}

// ---------------- final: rmsnorm(last token) -> elu -> @ out_W^T ----------------
__global__ void final_kernel(const float* __restrict__ y, const float* __restrict__ nw,
                             const float* __restrict__ ow, float* __restrict__ out) {
    __shared__ float sh[8];
    __shared__ float u[256];
    int b = blockIdx.x;
    int d = threadIdx.x;
    float v = y[((long)b * L_ + (L_ - 1)) * D_MODEL + d];
    float sq = v * v;
    #pragma unroll
    for (int o = 16; o; o >>= 1) sq += __shfl_xor_sync(0xffffffffu, sq, o);
    if ((d & 31) == 0) sh[d >> 5] = sq;
    __syncthreads();
    float ms = 0.f;
    #pragma unroll
    for (int i = 0; i < 8; i++) ms += sh[i];
    ms *= (1.f / D_MODEL);
    float x = v * rsqrtf(ms + EPS) * nw[d];
    u[d] = (x > 0.f) ? x : (expf(x) - 1.f);
    __syncthreads();
    if (d < COUT_) {
        float a = 0.f;
        for (int k = 0; k < D_MODEL; k++) a += u[k] * ow[d * D_MODEL + k];
        out[b * COUT_ + d] = a;
    }
}

// ---------------- host orchestration ----------------
extern "C" void kernel_launch(void* const* d_in, const int* in_sizes, int n_in,
                              void* d_out, int out_size) {
    const float* obs     = (const float*)d_in[0];
    const float* in_W    = (const float*)d_in[1];
    const float* ln1_w   = (const float*)d_in[2];
    const float* ln1_b   = (const float*)d_in[3];
    const float* rms_w   = (const float*)d_in[4];
    const float* inproj  = (const float*)d_in[5];
    const float* conv_w  = (const float*)d_in[6];
    const float* conv_b  = (const float*)d_in[7];
    const float* dt_bias = (const float*)d_in[8];
    const float* A_log   = (const float*)d_in[9];
    const float* Dp      = (const float*)d_in[10];
    const float* gnorm   = (const float*)d_in[11];
    const float* outproj = (const float*)d_in[12];
    const float* normf   = (const float*)d_in[13];
    const float* out_W   = (const float*)d_in[14];
    float* out = (float*)d_out;

    float *y, *h, *zx, *conv, *ssd, *gate;
    cudaGetSymbolAddress((void**)&y, g_y);
    cudaGetSymbolAddress((void**)&h, g_h);
    cudaGetSymbolAddress((void**)&zx, g_zx);
    cudaGetSymbolAddress((void**)&conv, g_conv);
    cudaGetSymbolAddress((void**)&ssd, g_ssd);
    cudaGetSymbolAddress((void**)&gate, g_gate);

    cudaFuncSetAttribute(ssd_kernel, cudaFuncAttributeMaxDynamicSharedMemorySize,
                         SSD_SMEM_BYTES);

    // 1) y = obs @ in_W^T, then LayerNorm in place
    {
        dim3 grid((D_MODEL + TBN - 1) / TBN, NTOK / TBM);
        gemm_bf3<<<grid, 256>>>(obs, in_W, nullptr, y, NTOK, D_MODEL, CIN);
        ln_kernel<<<NTOK / 8, 256>>>(y, ln1_w, ln1_b);
    }

    for (int i = 0; i < N_LAYER; i++) {
        const float* Wi = inproj + (long)i * D_IN_PROJ * D_MODEL;
        const float* Wo = outproj + (long)i * D_MODEL * D_INNER;
        const float* cwi = conv_w + (long)i * CONV_DIM * D_CONV;
        const float* cbi = conv_b + (long)i * CONV_DIM;
        const float* dtbi = dt_bias + i * NHEADS;
        const float* Ali = A_log + i * NHEADS;
        const float* Dpi = Dp + i * NHEADS;
        const float* gwi = gnorm + (long)i * D_INNER;
        const float* rwi = rms_w + (long)i * D_MODEL;

        rms_kernel<<<NTOK / 8, 256>>>(y, rwi, h);
        {
            dim3 grid((D_IN_PROJ + TBN - 1) / TBN, NTOK / TBM);
            gemm_bf3<<<grid, 256>>>(h, Wi, nullptr, zx, NTOK, D_IN_PROJ, D_MODEL);
        }
        {
            long total = (long)NTOK * CONV_G;
            int blocks = (int)((total + 255) / 256);
            conv_kernel<<<blocks, 256>>>(zx, cwi, cbi, conv);
        }
        ssd_kernel<<<B_ * NHEADS, 256, SSD_SMEM_BYTES>>>(conv, zx, dtbi, Ali, Dpi, ssd);
        gated_kernel<<<NTOK / 8, 256>>>(ssd, zx, gwi, gate);
        {
            dim3 grid((D_MODEL + TBN - 1) / TBN, NTOK / TBM);
            gemm_bf3<<<grid, 256>>>(gate, Wo, y, y, NTOK, D_MODEL, D_INNER);
        }
    }

    final_kernel<<<B_, 256>>>(y, normf, out_W, out);
}

// round 13
// speedup vs baseline: 2.5386x; 1.0526x over previous
#include <cuda_runtime.h>
#include <cuda_bf16.h>
#include <math.h>

#define B_ 128
#define L_ 512
#define CIN 48
#define COUT_ 12
#define D_MODEL 256
#define N_LAYER 4
#define D_STATE 64
#define D_CONV 4
#define HEADDIM 64
#define CHUNK 64
#define D_INNER 512
#define NHEADS 8
#define CONV_DIM 640
#define D_IN_PROJ 1160
#define NTOK (B_ * L_)
#define EPS 1e-5f

// ---------------- scratch (static device globals; no runtime alloc) ----------------
__device__ float g_y[NTOK * D_MODEL];
__device__ float g_h[NTOK * D_MODEL];
__device__ float g_zx[NTOK * D_IN_PROJ];
__device__ float g_conv[NTOK * CONV_DIM];
__device__ float g_ssd[NTOK * D_INNER];
__device__ float g_gate[NTOK * D_INNER];

__device__ __forceinline__ float silu_f(float x) { return x / (1.f + expf(-x)); }

__device__ __forceinline__ float warp_sum(float v) {
    #pragma unroll
    for (int o = 16; o; o >>= 1) v += __shfl_xor_sync(0xffffffffu, v, o);
    return v;
}

// ---------------- bf16 split helpers ----------------
__device__ __forceinline__ void split2(float a, float b, unsigned& hi, unsigned& lo) {
    __nv_bfloat16 ha = __float2bfloat16_rn(a);
    __nv_bfloat16 hb = __float2bfloat16_rn(b);
    __nv_bfloat162 h; h.x = ha; h.y = hb;
    __nv_bfloat162 l = __floats2bfloat162_rn(a - __bfloat162float(ha),
                                             b - __bfloat162float(hb));
    hi = *reinterpret_cast<unsigned*>(&h);
    lo = *reinterpret_cast<unsigned*>(&l);
}
__device__ __forceinline__ void mma_bf16(float (&d)[4], const unsigned (&a)[4],
                                         const unsigned (&b)[2]) {
    asm volatile(
        "mma.sync.aligned.m16n8k16.row.col.f32.bf16.bf16.f32 "
        "{%0,%1,%2,%3}, {%4,%5,%6,%7}, {%8,%9}, {%0,%1,%2,%3};\n"
        : "+f"(d[0]), "+f"(d[1]), "+f"(d[2]), "+f"(d[3])
        : "r"(a[0]), "r"(a[1]), "r"(a[2]), "r"(a[3]), "r"(b[0]), "r"(b[1]));
}
__device__ __forceinline__ void ldsm_x4(unsigned (&r)[4], unsigned addr) {
    asm volatile("ldmatrix.sync.aligned.m8n8.x4.shared.b16 {%0,%1,%2,%3}, [%4];"
        : "=r"(r[0]), "=r"(r[1]), "=r"(r[2]), "=r"(r[3]) : "r"(addr));
}

// ---------------- tensor-core GEMM: C[M,N] = A[M,K] @ W[N,K]^T (+res) ----------------
// bf16 split-3, double-buffered smem (one sync per k-iter).
// Block tile 128x64x16, 8 warps (4x2), warp tile 32x32.
#define TBM 128
#define TBN 64
#define TBK 16
#define SA_H (TBK + 8)
#define SA_W (SA_H / 2)
__global__ __launch_bounds__(256) void gemm_bf3(
        const float* __restrict__ A, const float* __restrict__ W,
        const float* __restrict__ res, float* __restrict__ C,
        int M, int N, int K) {
    __shared__ unsigned Ah[2][TBM * SA_W], Al[2][TBM * SA_W];
    __shared__ unsigned Wh[2][TBN * SA_W], Wl[2][TBN * SA_W];
    int tid = threadIdx.x;
    int lane = tid & 31, wid = tid >> 5;
    int wm = (wid >> 1) * 32;
    int wn = (wid & 1) * 32;
    int grp = lane >> 2, qk = lane & 3;
    int m0 = blockIdx.y * TBM, n0 = blockIdx.x * TBN;

    int alm = tid >> 1;
    int alk = (tid & 1) * 8;
    int wlm = tid >> 2;
    int wlk = (tid & 3) * 4;

    const float* aptr = A + (long)(m0 + alm) * K + alk;
    const float* wptr = (n0 + wlm < N) ? (W + (long)(n0 + wlm) * K + wlk) : nullptr;

    float4 ar0 = *(const float4*)(aptr);
    float4 ar1 = *(const float4*)(aptr + 4);
    float4 wr = wptr ? *(const float4*)(wptr) : make_float4(0.f, 0.f, 0.f, 0.f);

    unsigned sAh0 = (unsigned)__cvta_generic_to_shared(Ah[0]);
    unsigned sAh1 = (unsigned)__cvta_generic_to_shared(Ah[1]);
    unsigned sAl0 = (unsigned)__cvta_generic_to_shared(Al[0]);
    unsigned sAl1 = (unsigned)__cvta_generic_to_shared(Al[1]);
    unsigned sWh0 = (unsigned)__cvta_generic_to_shared(Wh[0]);
    unsigned sWh1 = (unsigned)__cvta_generic_to_shared(Wh[1]);
    unsigned sWl0 = (unsigned)__cvta_generic_to_shared(Wl[0]);
    unsigned sWl1 = (unsigned)__cvta_generic_to_shared(Wl[1]);
    unsigned a_off = (unsigned)((wm + (lane & 15)) * SA_W + (lane >> 4) * 4) * 4u;
    unsigned b_row = (lane & 7) + ((lane >> 4) * 8);
    unsigned b_off = (unsigned)((wn + b_row) * SA_W + ((lane >> 3) & 1) * 4) * 4u;

    int abase = alm * SA_W + (alk >> 1);
    int wbase = wlm * SA_W + (wlk >> 1);

    float acc[2][4][4];
    #pragma unroll
    for (int i = 0; i < 2; i++)
        #pragma unroll
        for (int j = 0; j < 4; j++)
            #pragma unroll
            for (int q = 0; q < 4; q++) acc[i][j][q] = 0.f;

    // prologue: fill buffer 0
    {
        unsigned h, l;
        split2(ar0.x, ar0.y, h, l); Ah[0][abase + 0] = h; Al[0][abase + 0] = l;
        split2(ar0.z, ar0.w, h, l); Ah[0][abase + 1] = h; Al[0][abase + 1] = l;
        split2(ar1.x, ar1.y, h, l); Ah[0][abase + 2] = h; Al[0][abase + 2] = l;
        split2(ar1.z, ar1.w, h, l); Ah[0][abase + 3] = h; Al[0][abase + 3] = l;
        split2(wr.x, wr.y, h, l);   Wh[0][wbase + 0] = h; Wl[0][wbase + 0] = l;
        split2(wr.z, wr.w, h, l);   Wh[0][wbase + 1] = h; Wl[0][wbase + 1] = l;
    }
    __syncthreads();

    int nk = K / TBK;
    for (int i = 0; i < nk; i++) {
        if (i + 1 < nk) {
            int k0 = (i + 1) * TBK;
            ar0 = *(const float4*)(aptr + k0);
            ar1 = *(const float4*)(aptr + k0 + 4);
            if (wptr) wr = *(const float4*)(wptr + k0);
        }
        int buf = i & 1;
        unsigned bAh = buf ? sAh1 : sAh0;
        unsigned bAl = buf ? sAl1 : sAl0;
        unsigned bWh = buf ? sWh1 : sWh0;
        unsigned bWl = buf ? sWl1 : sWl0;

        unsigned fah[2][4], fal[2][4], fbh[4][2], fbl[4][2];
        #pragma unroll
        for (int mt = 0; mt < 2; mt++) {
            unsigned off = a_off + (unsigned)(mt * 16 * SA_W) * 4u;
            ldsm_x4(fah[mt], bAh + off);
            ldsm_x4(fal[mt], bAl + off);
        }
        #pragma unroll
        for (int nt2 = 0; nt2 < 2; nt2++) {
            unsigned off = b_off + (unsigned)(nt2 * 16 * SA_W) * 4u;
            unsigned t[4];
            ldsm_x4(t, bWh + off);
            fbh[2*nt2][0] = t[0]; fbh[2*nt2][1] = t[1];
            fbh[2*nt2+1][0] = t[2]; fbh[2*nt2+1][1] = t[3];
            ldsm_x4(t, bWl + off);
            fbl[2*nt2][0] = t[0]; fbl[2*nt2][1] = t[1];
            fbl[2*nt2+1][0] = t[2]; fbl[2*nt2+1][1] = t[3];
        }
        #pragma unroll
        for (int mt = 0; mt < 2; mt++)
            #pragma unroll
            for (int nt = 0; nt < 4; nt++) {
                mma_bf16(acc[mt][nt], fah[mt], fbl[nt]);
                mma_bf16(acc[mt][nt], fal[mt], fbh[nt]);
                mma_bf16(acc[mt][nt], fah[mt], fbh[nt]);
            }

        if (i + 1 < nk) {
            int nb = 1 - buf;
            unsigned h, l;
            split2(ar0.x, ar0.y, h, l); Ah[nb][abase + 0] = h; Al[nb][abase + 0] = l;
            split2(ar0.z, ar0.w, h, l); Ah[nb][abase + 1] = h; Al[nb][abase + 1] = l;
            split2(ar1.x, ar1.y, h, l); Ah[nb][abase + 2] = h; Al[nb][abase + 2] = l;
            split2(ar1.z, ar1.w, h, l); Ah[nb][abase + 3] = h; Al[nb][abase + 3] = l;
            split2(wr.x, wr.y, h, l);   Wh[nb][wbase + 0] = h; Wl[nb][wbase + 0] = l;
            split2(wr.z, wr.w, h, l);   Wh[nb][wbase + 1] = h; Wl[nb][wbase + 1] = l;
            __syncthreads();
        }
    }

    #pragma unroll
    for (int mt = 0; mt < 2; mt++) {
        #pragma unroll
        for (int nt = 0; nt < 4; nt++) {
            int col = n0 + wn + nt * 8 + qk * 2;
            if (col >= N) continue;
            int row = m0 + wm + mt * 16 + grp;
            long off0 = (long)row * N + col;
            long off1 = (long)(row + 8) * N + col;
            float2 v0 = make_float2(acc[mt][nt][0], acc[mt][nt][1]);
            float2 v1 = make_float2(acc[mt][nt][2], acc[mt][nt][3]);
            if (res) {
                float2 r0 = *(const float2*)(res + off0);
                float2 r1 = *(const float2*)(res + off1);
                v0.x += r0.x; v0.y += r0.y;
                v1.x += r1.x; v1.y += r1.y;
            }
            *(float2*)(C + off0) = v0;
            *(float2*)(C + off1) = v1;
        }
    }
}

// ---------------- LayerNorm (warp per token, in place) ----------------
__global__ void ln_kernel(float* __restrict__ y, const float* __restrict__ w,
                          const float* __restrict__ b) {
    long t = (long)(blockIdx.x * (blockDim.x >> 5)) + (threadIdx.x >> 5);
    int lane = threadIdx.x & 31;
    float* row = y + t * D_MODEL;
    float4 v0 = *(const float4*)(row + lane * 8);
    float4 v1 = *(const float4*)(row + lane * 8 + 4);
    float s = v0.x + v0.y + v0.z + v0.w + v1.x + v1.y + v1.z + v1.w;
    float sq = v0.x*v0.x + v0.y*v0.y + v0.z*v0.z + v0.w*v0.w
             + v1.x*v1.x + v1.y*v1.y + v1.z*v1.z + v1.w*v1.w;
    s = warp_sum(s) * (1.f / D_MODEL);
    sq = warp_sum(sq) * (1.f / D_MODEL);
    float r = rsqrtf(sq - s * s + EPS);
    float4 w0 = *(const float4*)(w + lane * 8);
    float4 w1 = *(const float4*)(w + lane * 8 + 4);
    float4 b0 = *(const float4*)(b + lane * 8);
    float4 b1 = *(const float4*)(b + lane * 8 + 4);
    v0.x = (v0.x - s) * r * w0.x + b0.x; v0.y = (v0.y - s) * r * w0.y + b0.y;
    v0.z = (v0.z - s) * r * w0.z + b0.z; v0.w = (v0.w - s) * r * w0.w + b0.w;
    v1.x = (v1.x - s) * r * w1.x + b1.x; v1.y = (v1.y - s) * r * w1.y + b1.y;
    v1.z = (v1.z - s) * r * w1.z + b1.z; v1.w = (v1.w - s) * r * w1.w + b1.w;
    *(float4*)(row + lane * 8) = v0;
    *(float4*)(row + lane * 8 + 4) = v1;
}

// ---------------- RMSNorm (warp per token) ----------------
__global__ void rms_kernel(const float* __restrict__ y, const float* __restrict__ w,
                           float* __restrict__ out) {
    long t = (long)(blockIdx.x * (blockDim.x >> 5)) + (threadIdx.x >> 5);
    int lane = threadIdx.x & 31;
    const float* row = y + t * D_MODEL;
    float4 v0 = *(const float4*)(row + lane * 8);
    float4 v1 = *(const float4*)(row + lane * 8 + 4);
    float sq = v0.x*v0.x + v0.y*v0.y + v0.z*v0.z + v0.w*v0.w
             + v1.x*v1.x + v1.y*v1.y + v1.z*v1.z + v1.w*v1.w;
    sq = warp_sum(sq) * (1.f / D_MODEL);
    float r = rsqrtf(sq + EPS);
    float4 w0 = *(const float4*)(w + lane * 8);
    float4 w1 = *(const float4*)(w + lane * 8 + 4);
    v0.x *= r * w0.x; v0.y *= r * w0.y; v0.z *= r * w0.z; v0.w *= r * w0.w;
    v1.x *= r * w1.x; v1.y *= r * w1.y; v1.z *= r * w1.z; v1.w *= r * w1.w;
    float* orow = out + t * D_MODEL;
    *(float4*)(orow + lane * 8) = v0;
    *(float4*)(orow + lane * 8 + 4) = v1;
}

// ---------------- depthwise causal conv (width 4) + bias + silu, float4 ----------------
#define CONV_G (CONV_DIM / 4)
__global__ void conv_kernel(const float* __restrict__ zx, const float* __restrict__ cw,
                            const float* __restrict__ cb, float* __restrict__ out) {
    long idx = (long)blockIdx.x * blockDim.x + threadIdx.x;
    if (idx >= (long)NTOK * CONV_G) return;
    int cg = (int)(idx % CONV_G);
    int ch = cg * 4;
    long t = idx / CONV_G;
    int l = (int)(t & (L_ - 1));
    long brow = t - l;
    float4 wr0 = *(const float4*)(cw + (ch + 0) * D_CONV);
    float4 wr1 = *(const float4*)(cw + (ch + 1) * D_CONV);
    float4 wr2 = *(const float4*)(cw + (ch + 2) * D_CONV);
    float4 wr3 = *(const float4*)(cw + (ch + 3) * D_CONV);
    float4 a = *(const float4*)(cb + ch);
    #pragma unroll
    for (int k = 0; k < D_CONV; k++) {
        int ls = l + k - (D_CONV - 1);
        if (ls >= 0) {
            float4 x = *(const float4*)(zx + (brow + ls) * D_IN_PROJ + D_INNER + ch);
            const float* w0 = &wr0.x; const float* w1 = &wr1.x;
            const float* w2 = &wr2.x; const float* w3 = &wr3.x;
            a.x += x.x * w0[k]; a.y += x.y * w1[k];
            a.z += x.z * w2[k]; a.w += x.w * w3[k];
        }
    }
    a.x = silu_f(a.x); a.y = silu_f(a.y); a.z = silu_f(a.z); a.w = silu_f(a.w);
    *(float4*)(out + t * CONV_DIM + ch) = a;
}

// ---------------- SSD chunked scan: TENSOR-CORE version (R11 known-good) ----------
#define SS_W 36
#define SSD_PLANE (64 * SS_W)
#define SSD_SMEM_BYTES ((10 * SSD_PLANE + 256) * 4)
__global__ __launch_bounds__(256)
void ssd_kernel(const float* __restrict__ conv, const float* __restrict__ zx,
                const float* __restrict__ dtb, const float* __restrict__ Alog,
                const float* __restrict__ Dp, float* __restrict__ out) {
    extern __shared__ unsigned smw[];
    unsigned* XTh = smw;
    unsigned* XTl = XTh + SSD_PLANE;
    unsigned* Chp = XTl + SSD_PLANE;
    unsigned* Clp = Chp + SSD_PLANE;
    unsigned* BMh = Clp + SSD_PLANE;
    unsigned* BMl = BMh + SSD_PLANE;
    unsigned* BTh = BMl + SSD_PLANE;
    unsigned* BTl = BTh + SSD_PLANE;
    unsigned* STh = BTl + SSD_PLANE;
    unsigned* STl = STh + SSD_PLANE;
    float* acum = (float*)(STl + SSD_PLANE);
    float* dts = acum + 64;
    float* dd  = dts + 64;
    float* eAl = dd + 64;

    __nv_bfloat16* eXTh = (__nv_bfloat16*)XTh;
    __nv_bfloat16* eXTl = (__nv_bfloat16*)XTl;
    __nv_bfloat16* eCh  = (__nv_bfloat16*)Chp;
    __nv_bfloat16* eCl  = (__nv_bfloat16*)Clp;
    __nv_bfloat16* eBMh = (__nv_bfloat16*)BMh;
    __nv_bfloat16* eBMl = (__nv_bfloat16*)BMl;
    __nv_bfloat16* eBTh = (__nv_bfloat16*)BTh;
    __nv_bfloat16* eBTl = (__nv_bfloat16*)BTl;
    __nv_bfloat16* eSTh = (__nv_bfloat16*)STh;
    __nv_bfloat16* eSTl = (__nv_bfloat16*)STl;

    int tid = threadIdx.x;
    int lane = tid & 31, wid = tid >> 5;
    int wr = (wid >> 1) * 16;
    int wc = (wid & 1) * 32;
    int grp = lane >> 2, qk = lane & 3;
    int b = blockIdx.x >> 3, h = blockIdx.x & 7;
    float Ahc = -expf(Alog[h]);
    float dtbh = dtb[h], Dh = Dp[h];

    unsigned sXTh = (unsigned)__cvta_generic_to_shared(XTh);
    unsigned sXTl = (unsigned)__cvta_generic_to_shared(XTl);
    unsigned sCh  = (unsigned)__cvta_generic_to_shared(Chp);
    unsigned sCl  = (unsigned)__cvta_generic_to_shared(Clp);
    unsigned sBMh = (unsigned)__cvta_generic_to_shared(BMh);
    unsigned sBMl = (unsigned)__cvta_generic_to_shared(BMl);
    unsigned sBTh = (unsigned)__cvta_generic_to_shared(BTh);
    unsigned sBTl = (unsigned)__cvta_generic_to_shared(BTl);
    unsigned sSTh = (unsigned)__cvta_generic_to_shared(STh);
    unsigned sSTl = (unsigned)__cvta_generic_to_shared(STl);
    unsigned aoffA = (unsigned)((lane & 15) * SS_W + (lane >> 4) * 4) * 4u;
    unsigned aoffB = (unsigned)(((lane & 7) + ((lane >> 4) << 3)) * SS_W
                                + ((lane >> 3) & 1) * 4) * 4u;

    for (int i = tid; i < 2 * SSD_PLANE; i += 256) STh[i] = 0u;
    __syncthreads();

    int r0 = wr + grp, r1 = r0 + 8;

    for (int c = 0; c < 8; ++c) {
        long tok0 = (long)b * L_ + c * CHUNK;
        if (tid < 64) {
            float x = zx[(tok0 + tid) * D_IN_PROJ + (D_IN_PROJ - NHEADS) + h] + dtbh;
            float dt = (x > 20.f) ? x : log1pf(expf(x));
            dts[tid] = dt;
            acum[tid] = Ahc * dt;
        }
        __syncthreads();
        if (tid < 32) {
            float v0 = acum[2 * tid], v1 = acum[2 * tid + 1];
            float s = v0 + v1;
            #pragma unroll
            for (int o = 1; o < 32; o <<= 1) {
                float t = __shfl_up_sync(0xffffffffu, s, o);
                if (tid >= o) s += t;
            }
            acum[2 * tid] = s - v1;
            acum[2 * tid + 1] = s;
        }
        __syncthreads();
        if (tid < 64) {
            eAl[tid] = expf(acum[tid]);
            dd[tid] = dts[tid] * expf(acum[63] - acum[tid]);
        }
        __syncthreads();
        for (int i = tid; i < 4096; i += 256) {
            int l = i >> 6, q = i & 63;
            const float* row = conv + (tok0 + l) * CONV_DIM;
            float xv = row[h * 64 + q];
            float bv = row[D_INNER + q];
            float cv = row[D_INNER + D_STATE + q];
            __nv_bfloat16 t;
            t = __float2bfloat16_rn(xv);
            eXTh[q * 72 + l] = t;
            eXTl[q * 72 + l] = __float2bfloat16_rn(xv - __bfloat162float(t));
            t = __float2bfloat16_rn(bv);
            eBMh[l * 72 + q] = t;
            eBMl[l * 72 + q] = __float2bfloat16_rn(bv - __bfloat162float(t));
            float bd = bv * dd[l];
            t = __float2bfloat16_rn(bd);
            eBTh[q * 72 + l] = t;
            eBTl[q * 72 + l] = __float2bfloat16_rn(bd - __bfloat162float(t));
            t = __float2bfloat16_rn(cv);
            eCh[l * 72 + q] = t;
            eCl[l * 72 + q] = __float2bfloat16_rn(cv - __bfloat162float(t));
        }
        __syncthreads();
        float g[4][4];
        #pragma unroll
        for (int j = 0; j < 4; j++)
            #pragma unroll
            for (int q = 0; q < 4; q++) g[j][q] = 0.f;
        #pragma unroll
        for (int kk = 0; kk < 4; kk++) {
            unsigned ah[4], al4[4], t4[4];
            unsigned ab = (unsigned)(wr * SS_W * 4) + aoffA + kk * 32;
            ldsm_x4(ah, sCh + ab);
            ldsm_x4(al4, sCl + ab);
            unsigned bh[4][2], bl[4][2];
            #pragma unroll
            for (int hf = 0; hf < 2; hf++) {
                unsigned bb = (unsigned)((wc + hf * 16) * SS_W * 4) + aoffB + kk * 32;
                ldsm_x4(t4, sBMh + bb);
                bh[hf*2][0]=t4[0]; bh[hf*2][1]=t4[1]; bh[hf*2+1][0]=t4[2]; bh[hf*2+1][1]=t4[3];
                ldsm_x4(t4, sBMl + bb);
                bl[hf*2][0]=t4[0]; bl[hf*2][1]=t4[1]; bl[hf*2+1][0]=t4[2]; bl[hf*2+1][1]=t4[3];
            }
            #pragma unroll
            for (int j = 0; j < 4; j++) {
                mma_bf16(g[j], ah, bl[j]);
                mma_bf16(g[j], al4, bh[j]);
                mma_bf16(g[j], ah, bh[j]);
            }
        }
        __syncthreads();
        {
            float ar0 = acum[r0], ar1 = acum[r1];
            #pragma unroll
            for (int j = 0; j < 4; j++) {
                int cc = wc + j * 8 + qk * 2;
                float as0 = acum[cc], as1 = acum[cc + 1];
                float d0 = dts[cc], d1 = dts[cc + 1];
                float v00 = (cc     <= r0) ? g[j][0] * expf(ar0 - as0) * d0 : 0.f;
                float v01 = (cc + 1 <= r0) ? g[j][1] * expf(ar0 - as1) * d1 : 0.f;
                float v10 = (cc     <= r1) ? g[j][2] * expf(ar1 - as0) * d0 : 0.f;
                float v11 = (cc + 1 <= r1) ? g[j][3] * expf(ar1 - as1) * d1 : 0.f;
                unsigned hi, lo;
                split2(v00, v01, hi, lo);
                BMh[r0 * SS_W + (cc >> 1)] = hi; BMl[r0 * SS_W + (cc >> 1)] = lo;
                split2(v10, v11, hi, lo);
                BMh[r1 * SS_W + (cc >> 1)] = hi; BMl[r1 * SS_W + (cc >> 1)] = lo;
            }
        }
        __syncthreads();
        float ya[4][4], oa[4][4];
        #pragma unroll
        for (int j = 0; j < 4; j++) {
            int cc = wc + j * 8 + qk * 2;
            ya[j][0] = Dh * (__bfloat162float(eXTh[cc * 72 + r0])
                           + __bfloat162float(eXTl[cc * 72 + r0]));
            ya[j][1] = Dh * (__bfloat162float(eXTh[(cc + 1) * 72 + r0])
                           + __bfloat162float(eXTl[(cc + 1) * 72 + r0]));
            ya[j][2] = Dh * (__bfloat162float(eXTh[cc * 72 + r1])
                           + __bfloat162float(eXTl[cc * 72 + r1]));
            ya[j][3] = Dh * (__bfloat162float(eXTh[(cc + 1) * 72 + r1])
                           + __bfloat162float(eXTl[(cc + 1) * 72 + r1]));
            oa[j][0] = oa[j][1] = oa[j][2] = oa[j][3] = 0.f;
        }
        #pragma unroll
        for (int kk = 0; kk < 4; kk++) {
            unsigned ab = (unsigned)(wr * SS_W * 4) + aoffA + kk * 32;
            unsigned mh[4], ml4[4], ch4[4], cl4[4], t4[4];
            ldsm_x4(mh, sBMh + ab); ldsm_x4(ml4, sBMl + ab);
            ldsm_x4(ch4, sCh + ab); ldsm_x4(cl4, sCl + ab);
            unsigned xh[4][2], xl[4][2], shh[4][2], sll[4][2];
            #pragma unroll
            for (int hf = 0; hf < 2; hf++) {
                unsigned bb = (unsigned)((wc + hf * 16) * SS_W * 4) + aoffB + kk * 32;
                ldsm_x4(t4, sXTh + bb);
                xh[hf*2][0]=t4[0]; xh[hf*2][1]=t4[1]; xh[hf*2+1][0]=t4[2]; xh[hf*2+1][1]=t4[3];
                ldsm_x4(t4, sXTl + bb);
                xl[hf*2][0]=t4[0]; xl[hf*2][1]=t4[1]; xl[hf*2+1][0]=t4[2]; xl[hf*2+1][1]=t4[3];
                ldsm_x4(t4, sSTh + bb);
                shh[hf*2][0]=t4[0]; shh[hf*2][1]=t4[1]; shh[hf*2+1][0]=t4[2]; shh[hf*2+1][1]=t4[3];
                ldsm_x4(t4, sSTl + bb);
                sll[hf*2][0]=t4[0]; sll[hf*2][1]=t4[1]; sll[hf*2+1][0]=t4[2]; sll[hf*2+1][1]=t4[3];
            }
            #pragma unroll
            for (int j = 0; j < 4; j++) {
                mma_bf16(ya[j], mh, xl[j]);
                mma_bf16(ya[j], ml4, xh[j]);
                mma_bf16(ya[j], mh, xh[j]);
                mma_bf16(oa[j], ch4, sll[j]);
                mma_bf16(oa[j], cl4, shh[j]);
                mma_bf16(oa[j], ch4, shh[j]);
            }
        }
        {
            float e0 = eAl[r0], e1 = eAl[r1];
            #pragma unroll
            for (int j = 0; j < 4; j++) {
                int cc = wc + j * 8 + qk * 2;
                float* o0 = out + (tok0 + r0) * D_INNER + h * 64 + cc;
                float* o1 = out + (tok0 + r1) * D_INNER + h * 64 + cc;
                *(float2*)o0 = make_float2(ya[j][0] + e0 * oa[j][0],
                                           ya[j][1] + e0 * oa[j][1]);
                *(float2*)o1 = make_float2(ya[j][2] + e1 * oa[j][2],
                                           ya[j][3] + e1 * oa[j][3]);
            }
        }
        __syncthreads();
        {
            float eT = eAl[63];
            float sa[4][4];
            #pragma unroll
            for (int j = 0; j < 4; j++) {
                int cc = wc + j * 8 + qk * 2;
                sa[j][0] = eT * (__bfloat162float(eSTh[r0 * 72 + cc])
                               + __bfloat162float(eSTl[r0 * 72 + cc]));
                sa[j][1] = eT * (__bfloat162float(eSTh[r0 * 72 + cc + 1])
                               + __bfloat162float(eSTl[r0 * 72 + cc + 1]));
                sa[j][2] = eT * (__bfloat162float(eSTh[r1 * 72 + cc])
                               + __bfloat162float(eSTl[r1 * 72 + cc]));
                sa[j][3] = eT * (__bfloat162float(eSTh[r1 * 72 + cc + 1])
                               + __bfloat162float(eSTl[r1 * 72 + cc + 1]));
            }
            #pragma unroll
            for (int kk = 0; kk < 4; kk++) {
                unsigned ab = (unsigned)(wr * SS_W * 4) + aoffA + kk * 32;
                unsigned ah[4], al4[4], t4[4];
                ldsm_x4(ah, sXTh + ab);
                ldsm_x4(al4, sXTl + ab);
                unsigned bh[4][2], bl[4][2];
                #pragma unroll
                for (int hf = 0; hf < 2; hf++) {
                    unsigned bb = (unsigned)((wc + hf * 16) * SS_W * 4) + aoffB + kk * 32;
                    ldsm_x4(t4, sBTh + bb);
                    bh[hf*2][0]=t4[0]; bh[hf*2][1]=t4[1]; bh[hf*2+1][0]=t4[2]; bh[hf*2+1][1]=t4[3];
                    ldsm_x4(t4, sBTl + bb);
                    bl[hf*2][0]=t4[0]; bl[hf*2][1]=t4[1]; bl[hf*2+1][0]=t4[2]; bl[hf*2+1][1]=t4[3];
                }
                #pragma unroll
                for (int j = 0; j < 4; j++) {
                    mma_bf16(sa[j], ah, bl[j]);
                    mma_bf16(sa[j], al4, bh[j]);
                    mma_bf16(sa[j], ah, bh[j]);
                }
            }
            #pragma unroll
            for (int j = 0; j < 4; j++) {
                int cc = wc + j * 8 + qk * 2;
                unsigned hi, lo;
                split2(sa[j][0], sa[j][1], hi, lo);
                STh[r0 * SS_W + (cc >> 1)] = hi; STl[r0 * SS_W + (cc >> 1)] = lo;
                split2(sa[j][2], sa[j][3], hi, lo);
                STh[r1 * SS_W + (cc >> 1)] = hi; STl[r1 * SS_W + (cc >> 1)] = lo;
            }
        }
        __syncthreads();
    }
}

// ---------------- gated RMSNorm (warp per token): rmsnorm(y*silu(z)) * gw ----------
__global__ void gated_kernel(const float* __restrict__ yin, const float* __restrict__ zx,
                             const float* __restrict__ gw, float* __restrict__ out) {
    long t = (long)(blockIdx.x * (blockDim.x >> 5)) + (threadIdx.x >> 5);
    int lane = threadIdx.x & 31;
    const float* yrow = yin + t * D_INNER;
    const float* zrow = zx + t * D_IN_PROJ;
    float u[16];
    float sq = 0.f;
    #pragma unroll
    for (int j = 0; j < 4; j++) {
        int d = lane * 4 + j * 128;
        float4 yv = *(const float4*)(yrow + d);
        float4 zv = *(const float4*)(zrow + d);
        float a0 = yv.x * silu_f(zv.x);
        float a1 = yv.y * silu_f(zv.y);
        float a2 = yv.z * silu_f(zv.z);
        float a3 = yv.w * silu_f(zv.w);
        u[j*4+0] = a0; u[j*4+1] = a1; u[j*4+2] = a2; u[j*4+3] = a3;
        sq += a0*a0 + a1*a1 + a2*a2 + a3*a3;
    }
    sq = warp_sum(sq) * (1.f / D_INNER);
    float r = rsqrtf(sq + EPS);
    float* orow = out + t * D_INNER;
    #pragma unroll
    for (int j = 0; j < 4; j++) {
        int d = lane * 4 + j * 128;
        float4 g = *(const float4*)(gw + d);
        float4 v = make_float4(u[j*4+0]*r*g.x, u[j*4+1]*r*g.y,
                               u[j*4+2]*r*g.z, u[j*4+3]*r*g.w);
        *(float4*)(orow + d) = v;
    }
}

// ---------------- final: rmsnorm(last token) -> elu -> @ out_W^T ----------------
__global__ void final_kernel(const float* __restrict__ y, const float* __restrict__ nw,
                             const float* __restrict__ ow, float* __restrict__ out) {
    __shared__ float sh[8];
    __shared__ float u[256];
    int b = blockIdx.x;
    int d = threadIdx.x;
    float v = y[((long)b * L_ + (L_ - 1)) * D_MODEL + d];
    float sq = v * v;
    #pragma unroll
    for (int o = 16; o; o >>= 1) sq += __shfl_xor_sync(0xffffffffu, sq, o);
    if ((d & 31) == 0) sh[d >> 5] = sq;
    __syncthreads();
    float ms = 0.f;
    #pragma unroll
    for (int i = 0; i < 8; i++) ms += sh[i];
    ms *= (1.f / D_MODEL);
    float x = v * rsqrtf(ms + EPS) * nw[d];
    u[d] = (x > 0.f) ? x : (expf(x) - 1.f);
    __syncthreads();
    if (d < COUT_) {
        float a = 0.f;
        for (int k = 0; k < D_MODEL; k++) a += u[k] * ow[d * D_MODEL + k];
        out[b * COUT_ + d] = a;
    }
}

// ---------------- host orchestration ----------------
extern "C" void kernel_launch(void* const* d_in, const int* in_sizes, int n_in,
                              void* d_out, int out_size) {
    const float* obs     = (const float*)d_in[0];
    const float* in_W    = (const float*)d_in[1];
    const float* ln1_w   = (const float*)d_in[2];
    const float* ln1_b   = (const float*)d_in[3];
    const float* rms_w   = (const float*)d_in[4];
    const float* inproj  = (const float*)d_in[5];
    const float* conv_w  = (const float*)d_in[6];
    const float* conv_b  = (const float*)d_in[7];
    const float* dt_bias = (const float*)d_in[8];
    const float* A_log   = (const float*)d_in[9];
    const float* Dp      = (const float*)d_in[10];
    const float* gnorm   = (const float*)d_in[11];
    const float* outproj = (const float*)d_in[12];
    const float* normf   = (const float*)d_in[13];
    const float* out_W   = (const float*)d_in[14];
    float* out = (float*)d_out;

    float *y, *h, *zx, *conv, *ssd, *gate;
    cudaGetSymbolAddress((void**)&y, g_y);
    cudaGetSymbolAddress((void**)&h, g_h);
    cudaGetSymbolAddress((void**)&zx, g_zx);
    cudaGetSymbolAddress((void**)&conv, g_conv);
    cudaGetSymbolAddress((void**)&ssd, g_ssd);
    cudaGetSymbolAddress((void**)&gate, g_gate);

    cudaFuncSetAttribute(ssd_kernel, cudaFuncAttributeMaxDynamicSharedMemorySize,
                         SSD_SMEM_BYTES);

    // 1) y = obs @ in_W^T, then LayerNorm in place
    {
        dim3 grid((D_MODEL + TBN - 1) / TBN, NTOK / TBM);
        gemm_bf3<<<grid, 256>>>(obs, in_W, nullptr, y, NTOK, D_MODEL, CIN);
        ln_kernel<<<NTOK / 8, 256>>>(y, ln1_w, ln1_b);
    }

    for (int i = 0; i < N_LAYER; i++) {
        const float* Wi = inproj + (long)i * D_IN_PROJ * D_MODEL;
        const float* Wo = outproj + (long)i * D_MODEL * D_INNER;
        const float* cwi = conv_w + (long)i * CONV_DIM * D_CONV;
        const float* cbi = conv_b + (long)i * CONV_DIM;
        const float* dtbi = dt_bias + i * NHEADS;
        const float* Ali = A_log + i * NHEADS;
        const float* Dpi = Dp + i * NHEADS;
        const float* gwi = gnorm + (long)i * D_INNER;
        const float* rwi = rms_w + (long)i * D_MODEL;

        rms_kernel<<<NTOK / 8, 256>>>(y, rwi, h);
        {
            dim3 grid((D_IN_PROJ + TBN - 1) / TBN, NTOK / TBM);
            gemm_bf3<<<grid, 256>>>(h, Wi, nullptr, zx, NTOK, D_IN_PROJ, D_MODEL);
        }
        {
            long total = (long)NTOK * CONV_G;
            int blocks = (int)((total + 255) / 256);
            conv_kernel<<<blocks, 256>>>(zx, cwi, cbi, conv);
        }
        ssd_kernel<<<B_ * NHEADS, 256, SSD_SMEM_BYTES>>>(conv, zx, dtbi, Ali, Dpi, ssd);
        gated_kernel<<<NTOK / 8, 256>>>(ssd, zx, gwi, gate);
        {
            dim3 grid((D_MODEL + TBN - 1) / TBN, NTOK / TBM);
            gemm_bf3<<<grid, 256>>>(gate, Wo, y, y, NTOK, D_MODEL, D_INNER);
        }
    }

    final_kernel<<<B_, 256>>>(y, normf, out_W, out);
}